// round 1
// baseline (speedup 1.0000x reference)
#include <cuda_runtime.h>

// Problem constants
#define LL     4096
#define DD     512
#define MODESN 64
#define JJ     128   // 2*MODES (Re rows then Im rows)
#define NB     32    // batch

// ---------------- static device scratch (no allocation allowed) ----------------
__device__ float g_BA [JJ * LL];            // forward basis  [j][l]   (2 MB)
__device__ float g_F  [LL * JJ];            // inverse basis  [l][j]   (2 MB)
__device__ float g_WTr[MODESN * DD * DD];   // weights_real transposed [m][d][e] (67 MB)
__device__ float g_WTi[MODESN * DD * DD];   // weights_imag transposed (67 MB)
__device__ float g_X  [NB * JJ * DD];       // stage A out: X[b][j][d] (8.4 MB)
__device__ float g_Y  [NB * JJ * DD];       // stage B out: Y[b][j][e] (8.4 MB)

// ---------------- basis builders ----------------
// Forward: rfft coefficients. X_m = sum_l q_l e^{-i 2pi m l / L}
//   rows 0..63   : cos(2pi m l / L)
//   rows 64..127 : -sin(2pi m l / L)
__global__ void build_basisA() {
    int idx = blockIdx.x * blockDim.x + threadIdx.x;
    if (idx >= JJ * LL) return;
    int j = idx >> 12;          // / 4096
    int l = idx & (LL - 1);
    int m = j & (MODESN - 1);
    int t = (m * l) & (LL - 1); // exact integer phase reduction
    float s, c;
    sincospif(2.0f * (float)t / (float)LL, &s, &c);
    g_BA[idx] = (j < MODESN) ? c : -s;
}

// Inverse: irfft with only modes 0..63 nonzero.
// out[l] = (1/L)[ Re(X_0) + 2 * sum_{m>=1} (Re(X_m)cos(th) - Im(X_m)sin(th)) ]
//   F[l][m]    = ((m==0)?1:2)/L * cos(th)
//   F[l][64+m] = -(2/L) * sin(th)   (zero for m==0 -> DC imag correctly ignored)
__global__ void build_basisC() {
    int idx = blockIdx.x * blockDim.x + threadIdx.x;
    if (idx >= LL * JJ) return;
    int l = idx >> 7;           // / 128
    int j = idx & (JJ - 1);
    int m = j & (MODESN - 1);
    int t = (m * l) & (LL - 1);
    float s, c;
    sincospif(2.0f * (float)t / (float)LL, &s, &c);
    float v;
    if (j < MODESN) v = ((m == 0) ? 1.0f : 2.0f) * (1.0f / (float)LL) * c;
    else            v = (-2.0f / (float)LL) * s;
    g_F[idx] = v;
}

// ---------------- weight transpose: [d*D+e][m] -> [m][d*D+e] ----------------
__global__ void transpose_w(const float* __restrict__ w, int which) {
    __shared__ float tile[32][33];
    float* __restrict__ wt = which ? g_WTi : g_WTr;
    int rb = blockIdx.x * 32;   // row = d*D+e
    int cb = blockIdx.y * 32;   // col = m
    int tx = threadIdx.x, ty = threadIdx.y;
    #pragma unroll
    for (int i = 0; i < 32; i += 8)
        tile[ty + i][tx] = w[(size_t)(rb + ty + i) * MODESN + cb + tx];
    __syncthreads();
    #pragma unroll
    for (int i = 0; i < 32; i += 8)
        wt[(size_t)(cb + ty + i) * (DD * DD) + rb + tx] = tile[tx][ty + i];
}

// ---------------- Stage A: X[b] (128 x 512) = BA (128 x 4096) @ q[b] (4096 x 512) ----------------
__global__ void __launch_bounds__(256) stageA_kernel(const float* __restrict__ q) {
    __shared__ float As[128 * 33];  // [j][kk] padded
    __shared__ float Qs[32 * 64];   // [kk][dd]
    int b  = blockIdx.y;
    int d0 = blockIdx.x * 64;
    int tid = threadIdx.x;
    int tc = tid & 15, tr = tid >> 4;   // 16x16 thread grid, micro 8x4
    float acc[8][4];
    #pragma unroll
    for (int i = 0; i < 8; i++)
        #pragma unroll
        for (int t = 0; t < 4; t++) acc[i][t] = 0.0f;

    const float* qb = q + (size_t)b * LL * DD;

    for (int k0 = 0; k0 < LL; k0 += 32) {
        #pragma unroll
        for (int i = 0; i < 16; i++) {              // 128x32 basis tile
            int e = tid + i * 256;
            int j = e >> 5, kk = e & 31;
            As[j * 33 + kk] = g_BA[j * LL + k0 + kk];
        }
        #pragma unroll
        for (int i = 0; i < 8; i++) {               // 32x64 q tile
            int e = tid + i * 256;
            int kk = e >> 6, dd = e & 63;
            Qs[kk * 64 + dd] = qb[(size_t)(k0 + kk) * DD + d0 + dd];
        }
        __syncthreads();
        #pragma unroll
        for (int kk = 0; kk < 32; kk++) {
            float a[8];
            #pragma unroll
            for (int i = 0; i < 8; i++) a[i] = As[(tr + i * 16) * 33 + kk];
            float4 bv = *(const float4*)&Qs[kk * 64 + tc * 4];
            #pragma unroll
            for (int i = 0; i < 8; i++) {
                acc[i][0] += a[i] * bv.x;
                acc[i][1] += a[i] * bv.y;
                acc[i][2] += a[i] * bv.z;
                acc[i][3] += a[i] * bv.w;
            }
        }
        __syncthreads();
    }
    #pragma unroll
    for (int i = 0; i < 8; i++) {
        int j = tr + i * 16;
        float4 v = make_float4(acc[i][0], acc[i][1], acc[i][2], acc[i][3]);
        *(float4*)&g_X[((size_t)b * JJ + j) * DD + d0 + tc * 4] = v;
    }
}

// ---------------- Stage B: per-mode complex matmul ----------------
// YR[b,e] = sum_d XR*Wr - XI*Wi ; YI[b,e] = sum_d XR*Wi + XI*Wr
__global__ void __launch_bounds__(128) stageB_kernel() {
    __shared__ float xr_s[32 * 33];  // [b][kk] padded
    __shared__ float xi_s[32 * 33];
    __shared__ float wr_s[32 * 64];  // [kk][e]
    __shared__ float wi_s[32 * 64];
    int m  = blockIdx.y;
    int e0 = blockIdx.x * 64;
    int tid = threadIdx.x;
    int ec = tid & 15, br = tid >> 4;   // 8 b-rows x 16 e-cols, micro 4x4 (x2 for R/I)
    float yr[4][4], yi[4][4];
    #pragma unroll
    for (int i = 0; i < 4; i++)
        #pragma unroll
        for (int t = 0; t < 4; t++) { yr[i][t] = 0.0f; yi[i][t] = 0.0f; }

    for (int k0 = 0; k0 < DD; k0 += 32) {
        #pragma unroll
        for (int i = 0; i < 8; i++) {               // 32b x 32k  X tiles
            int e = tid + i * 128;
            int bb = e >> 5, kk = e & 31;
            xr_s[bb * 33 + kk] = g_X[((size_t)bb * JJ + m) * DD + k0 + kk];
            xi_s[bb * 33 + kk] = g_X[((size_t)bb * JJ + MODESN + m) * DD + k0 + kk];
        }
        #pragma unroll
        for (int i = 0; i < 16; i++) {              // 32k x 64e  W tiles
            int e = tid + i * 128;
            int kk = e >> 6, ee = e & 63;
            size_t widx = ((size_t)m * DD + k0 + kk) * DD + e0 + ee;
            wr_s[kk * 64 + ee] = g_WTr[widx];
            wi_s[kk * 64 + ee] = g_WTi[widx];
        }
        __syncthreads();
        #pragma unroll
        for (int kk = 0; kk < 32; kk++) {
            float xr[4], xi[4];
            #pragma unroll
            for (int i = 0; i < 4; i++) {
                xr[i] = xr_s[(br * 4 + i) * 33 + kk];
                xi[i] = xi_s[(br * 4 + i) * 33 + kk];
            }
            float4 wr4 = *(const float4*)&wr_s[kk * 64 + ec * 4];
            float4 wi4 = *(const float4*)&wi_s[kk * 64 + ec * 4];
            float wr[4] = {wr4.x, wr4.y, wr4.z, wr4.w};
            float wim[4] = {wi4.x, wi4.y, wi4.z, wi4.w};
            #pragma unroll
            for (int i = 0; i < 4; i++)
                #pragma unroll
                for (int t = 0; t < 4; t++) {
                    yr[i][t] += xr[i] * wr[t];
                    yr[i][t] -= xi[i] * wim[t];
                    yi[i][t] += xr[i] * wim[t];
                    yi[i][t] += xi[i] * wr[t];
                }
        }
        __syncthreads();
    }
    #pragma unroll
    for (int i = 0; i < 4; i++) {
        int bb = br * 4 + i;
        float4 vr = make_float4(yr[i][0], yr[i][1], yr[i][2], yr[i][3]);
        float4 vi = make_float4(yi[i][0], yi[i][1], yi[i][2], yi[i][3]);
        *(float4*)&g_Y[((size_t)bb * JJ + m) * DD + e0 + ec * 4] = vr;
        *(float4*)&g_Y[((size_t)bb * JJ + MODESN + m) * DD + e0 + ec * 4] = vi;
    }
}

// ---------------- Stage C: out[b] (4096 x 512) = F (4096 x 128) @ Y[b] (128 x 512) ----------------
__global__ void __launch_bounds__(256) stageC_kernel(float* __restrict__ out) {
    __shared__ float As[128 * 33];  // [l][kk] padded
    __shared__ float Ys[32 * 64];   // [kk][ee]
    int b  = blockIdx.z;
    int l0 = blockIdx.y * 128;
    int e0 = blockIdx.x * 64;
    int tid = threadIdx.x;
    int tc = tid & 15, tr = tid >> 4;
    float acc[8][4];
    #pragma unroll
    for (int i = 0; i < 8; i++)
        #pragma unroll
        for (int t = 0; t < 4; t++) acc[i][t] = 0.0f;

    for (int k0 = 0; k0 < JJ; k0 += 32) {
        #pragma unroll
        for (int i = 0; i < 16; i++) {              // 128l x 32j basis tile
            int e = tid + i * 256;
            int l = e >> 5, kk = e & 31;
            As[l * 33 + kk] = g_F[(size_t)(l0 + l) * JJ + k0 + kk];
        }
        #pragma unroll
        for (int i = 0; i < 8; i++) {               // 32j x 64e Y tile
            int e = tid + i * 256;
            int kk = e >> 6, ee = e & 63;
            Ys[kk * 64 + ee] = g_Y[((size_t)b * JJ + k0 + kk) * DD + e0 + ee];
        }
        __syncthreads();
        #pragma unroll
        for (int kk = 0; kk < 32; kk++) {
            float a[8];
            #pragma unroll
            for (int i = 0; i < 8; i++) a[i] = As[(tr + i * 16) * 33 + kk];
            float4 bv = *(const float4*)&Ys[kk * 64 + tc * 4];
            #pragma unroll
            for (int i = 0; i < 8; i++) {
                acc[i][0] += a[i] * bv.x;
                acc[i][1] += a[i] * bv.y;
                acc[i][2] += a[i] * bv.z;
                acc[i][3] += a[i] * bv.w;
            }
        }
        __syncthreads();
    }
    #pragma unroll
    for (int i = 0; i < 8; i++) {
        int l = l0 + tr + i * 16;
        float4 v = make_float4(acc[i][0], acc[i][1], acc[i][2], acc[i][3]);
        *(float4*)&out[((size_t)b * LL + l) * DD + e0 + tc * 4] = v;
    }
}

// ---------------- launch ----------------
extern "C" void kernel_launch(void* const* d_in, const int* in_sizes, int n_in,
                              void* d_out, int out_size) {
    const float* q  = (const float*)d_in[0];
    const float* wr = (const float*)d_in[1];
    const float* wi = (const float*)d_in[2];
    float* out = (float*)d_out;

    build_basisA<<<(JJ * LL) / 256, 256>>>();
    build_basisC<<<(LL * JJ) / 256, 256>>>();

    dim3 tgrid((DD * DD) / 32, MODESN / 32);   // (8192, 2)
    transpose_w<<<tgrid, dim3(32, 8)>>>(wr, 0);
    transpose_w<<<tgrid, dim3(32, 8)>>>(wi, 1);

    stageA_kernel<<<dim3(DD / 64, NB), 256>>>(q);
    stageB_kernel<<<dim3(DD / 64, MODESN), 128>>>();
    stageC_kernel<<<dim3(DD / 64, LL / 128, NB), 256>>>(out);
}

// round 7
// speedup vs baseline: 1.3289x; 1.3289x over previous
#include <cuda_runtime.h>
#include <cuda_bf16.h>
#include <cstdint>

// Problem constants
#define LL     4096
#define DD     512
#define MODESN 64
#define JJ     128   // 2*MODES (Re rows then Im rows)
#define NB     32    // batch

// ---------------------------------------------------------------------------
// Static device scratch (no allocation allowed)
// ---------------------------------------------------------------------------
__device__ float g_BA [JJ * LL];            // forward basis  [j][l] fp32 (2 MB)
// Stage C basis (irfft), pre-swizzled bf16 hi/lo: [lt 32][kc 2] tiles [l 128][kk 64]
__device__ __align__(16) unsigned char g_Fh[64 * 16384];
__device__ __align__(16) unsigned char g_Fl[64 * 16384];
// Y transposed for stage C: per (b, et 0..3, kc 0..1): tile [e_local 128][kk 64]
__device__ __align__(16) unsigned char g_yth[(size_t)NB * 4 * 2 * 16384];
__device__ __align__(16) unsigned char g_ytl[(size_t)NB * 4 * 2 * 16384];
// Weights transposed fp32 [m][d][e]
__device__ float g_WTr[MODESN * DD * DD];
__device__ float g_WTi[MODESN * DD * DD];
// Stage A output fp32 [b][j][d]
__device__ float g_X[NB * JJ * DD];

// ---------------------------------------------------------------------------
// Helpers
// ---------------------------------------------------------------------------
__device__ __forceinline__ uint32_t swz(uint32_t x) { return x ^ ((x >> 3) & 0x70); }

// Swizzled byte offset of (row, byte-col cb) inside a [128 x 128B] tile.
__device__ __forceinline__ uint32_t swb(uint32_t row, uint32_t cb) {
    return row * 128u + (cb ^ ((row & 7u) << 4));
}

__device__ __forceinline__ uint32_t smem_u32(const void* p) {
    uint32_t a;
    asm("{ .reg .u64 t; cvta.to.shared.u64 t, %1; cvt.u32.u64 %0, t; }"
        : "=r"(a) : "l"(p));
    return a;
}

__device__ __forceinline__ uint32_t lds32(uint32_t a) {
    uint32_t v;
    asm volatile("ld.shared.b32 %0, [%1];" : "=r"(v) : "r"(a));
    return v;
}

__device__ __forceinline__ void split_bf16(float v, unsigned short& h, unsigned short& l) {
    __nv_bfloat16 bh = __float2bfloat16(v);
    float fh = __bfloat162float(bh);
    __nv_bfloat16 bl = __float2bfloat16(v - fh);
    h = __bfloat16_as_ushort(bh);
    l = __bfloat16_as_ushort(bl);
}

__device__ __forceinline__ void mma16816(float* c, const uint32_t* a,
                                         uint32_t b0, uint32_t b1) {
    asm volatile(
        "mma.sync.aligned.m16n8k16.row.col.f32.bf16.bf16.f32 "
        "{%0,%1,%2,%3}, {%4,%5,%6,%7}, {%8,%9}, {%0,%1,%2,%3};"
        : "+f"(c[0]), "+f"(c[1]), "+f"(c[2]), "+f"(c[3])
        : "r"(a[0]), "r"(a[1]), "r"(a[2]), "r"(a[3]), "r"(b0), "r"(b1));
}

// ---------------------------------------------------------------------------
// Core chunk compute: CTA tile 128(M) x 128(N), chunk K=64 (128 bytes bf16).
// SMEM at `base`: Ah @0, Al @+16384, Bh @+32768, Bl @+49152 (all SW128).
// Warp wm (0-3): M rows 32*wm..; wn (0-1): N cols 64*wn..
// Per-thread ld.shared.b32 fragment loads (provable addressing).
// 3-product split accumulate: Ah*Bh + Ah*Bl + Al*Bh.
// ---------------------------------------------------------------------------
__device__ __forceinline__ void gemm_chunk(uint32_t base, int lane, int wm, int wn,
                                           float acc[2][8][4]) {
    const uint32_t q4 = (uint32_t)(lane & 3) * 4u;
    const uint32_t rA = (uint32_t)(lane >> 2);   // 0..7
    #pragma unroll
    for (int ks = 0; ks < 4; ks++) {
        const uint32_t kb = (uint32_t)ks * 32u;
        uint32_t ah[2][4], al[2][4];
        #pragma unroll
        for (int mt = 0; mt < 2; mt++) {
            uint32_t r0 = (uint32_t)(wm * 32 + mt * 16) + rA;
            uint32_t a00 = base + swb(r0,     kb + q4);
            uint32_t a10 = base + swb(r0 + 8, kb + q4);
            uint32_t a01 = base + swb(r0,     kb + 16 + q4);
            uint32_t a11 = base + swb(r0 + 8, kb + 16 + q4);
            ah[mt][0] = lds32(a00);
            ah[mt][1] = lds32(a10);
            ah[mt][2] = lds32(a01);
            ah[mt][3] = lds32(a11);
            al[mt][0] = lds32(a00 + 16384);
            al[mt][1] = lds32(a10 + 16384);
            al[mt][2] = lds32(a01 + 16384);
            al[mt][3] = lds32(a11 + 16384);
        }
        #pragma unroll
        for (int np = 0; np < 4; np++) {
            uint32_t n0 = (uint32_t)(wn * 64 + np * 16) + rA;
            uint32_t bb = base + 32768;
            uint32_t b00 = bb + swb(n0,     kb + q4);
            uint32_t b01 = bb + swb(n0,     kb + 16 + q4);
            uint32_t b10 = bb + swb(n0 + 8, kb + q4);
            uint32_t b11 = bb + swb(n0 + 8, kb + 16 + q4);
            uint32_t bh0 = lds32(b00), bh1 = lds32(b01);
            uint32_t bh2 = lds32(b10), bh3 = lds32(b11);
            uint32_t bl0 = lds32(b00 + 16384), bl1 = lds32(b01 + 16384);
            uint32_t bl2 = lds32(b10 + 16384), bl3 = lds32(b11 + 16384);
            #pragma unroll
            for (int mt = 0; mt < 2; mt++) {
                float* c0 = acc[mt][np * 2 + 0];
                float* c1 = acc[mt][np * 2 + 1];
                mma16816(c0, ah[mt], bh0, bh1);
                mma16816(c0, ah[mt], bl0, bl1);
                mma16816(c0, al[mt], bh0, bh1);
                mma16816(c1, ah[mt], bh2, bh3);
                mma16816(c1, ah[mt], bl2, bl3);
                mma16816(c1, al[mt], bh2, bh3);
            }
        }
    }
}

// ---------------------------------------------------------------------------
// Forward basis (fp32, R1-proven): rows 0..63 cos, 64..127 -sin
// ---------------------------------------------------------------------------
__global__ void build_basisA() {
    int idx = blockIdx.x * blockDim.x + threadIdx.x;
    if (idx >= JJ * LL) return;
    int j = idx >> 12;          // / 4096
    int l = idx & (LL - 1);
    int m = j & (MODESN - 1);
    int t = (m * l) & (LL - 1);
    float s, c;
    sincospif(2.0f * (float)t / (float)LL, &s, &c);
    g_BA[idx] = (j < MODESN) ? c : -s;
}

// ---------------------------------------------------------------------------
// Inverse basis, pre-swizzled bf16 hi/lo tiles
// ---------------------------------------------------------------------------
__global__ void build_basisF_sw() {
    int t = blockIdx.x * blockDim.x + threadIdx.x;   // 65536 tasks
    int lt = t >> 11;
    int kc = (t >> 10) & 1;
    int lr = (t >> 3) & 127;
    int oc = t & 7;
    int l = lt * 128 + lr;
    uint32_t hw[4], lw[4];
    #pragma unroll
    for (int u = 0; u < 8; u++) {
        int kk = oc * 8 + u;
        int j = kc * 64 + kk;
        int m = j & 63;
        int phi = (m * l) & (LL - 1);
        float s, c;
        sincospif(2.0f * (float)phi / (float)LL, &s, &c);
        float v;
        if (j < MODESN) v = ((m == 0) ? 1.0f : 2.0f) * (1.0f / (float)LL) * c;
        else            v = (-2.0f / (float)LL) * s;
        unsigned short h, lo;
        split_bf16(v, h, lo);
        if (u & 1) { hw[u >> 1] |= (uint32_t)h << 16; lw[u >> 1] |= (uint32_t)lo << 16; }
        else       { hw[u >> 1] = h;                  lw[u >> 1] = lo; }
    }
    uint32_t off = (uint32_t)(lt * 2 + kc) * 16384u + swz((uint32_t)lr * 128u + (uint32_t)oc * 16u);
    *(uint4*)(g_Fh + off) = make_uint4(hw[0], hw[1], hw[2], hw[3]);
    *(uint4*)(g_Fl + off) = make_uint4(lw[0], lw[1], lw[2], lw[3]);
}

// ---------------------------------------------------------------------------
// Weight transpose: [d*D+e][m] -> [m][d*D+e]  (fp32, R1-proven)
// ---------------------------------------------------------------------------
__global__ void transpose_w(const float* __restrict__ w, int which) {
    __shared__ float tile[32][33];
    float* __restrict__ wt = which ? g_WTi : g_WTr;
    int rb = blockIdx.x * 32;
    int cb = blockIdx.y * 32;
    int tx = threadIdx.x, ty = threadIdx.y;
    #pragma unroll
    for (int i = 0; i < 32; i += 8)
        tile[ty + i][tx] = w[(size_t)(rb + ty + i) * MODESN + cb + tx];
    __syncthreads();
    #pragma unroll
    for (int i = 0; i < 32; i += 8)
        wt[(size_t)(cb + ty + i) * (DD * DD) + rb + tx] = tile[tx][ty + i];
}

// ---------------------------------------------------------------------------
// Stage A (fp32 SIMT, R1-proven): X[b] (128 x 512) = BA @ q[b] (4096 x 512)
// ---------------------------------------------------------------------------
__global__ void __launch_bounds__(256) stageA_kernel(const float* __restrict__ q) {
    __shared__ float As[128 * 33];  // [j][kk] padded
    __shared__ float Qs[32 * 64];   // [kk][dd]
    int b  = blockIdx.y;
    int d0 = blockIdx.x * 64;
    int tid = threadIdx.x;
    int tc = tid & 15, tr = tid >> 4;   // 16x16 thread grid, micro 8x4
    float acc[8][4];
    #pragma unroll
    for (int i = 0; i < 8; i++)
        #pragma unroll
        for (int t = 0; t < 4; t++) acc[i][t] = 0.0f;

    const float* qb = q + (size_t)b * LL * DD;

    for (int k0 = 0; k0 < LL; k0 += 32) {
        #pragma unroll
        for (int i = 0; i < 16; i++) {              // 128x32 basis tile
            int e = tid + i * 256;
            int j = e >> 5, kk = e & 31;
            As[j * 33 + kk] = g_BA[j * LL + k0 + kk];
        }
        #pragma unroll
        for (int i = 0; i < 8; i++) {               // 32x64 q tile
            int e = tid + i * 256;
            int kk = e >> 6, dd = e & 63;
            Qs[kk * 64 + dd] = qb[(size_t)(k0 + kk) * DD + d0 + dd];
        }
        __syncthreads();
        #pragma unroll
        for (int kk = 0; kk < 32; kk++) {
            float a[8];
            #pragma unroll
            for (int i = 0; i < 8; i++) a[i] = As[(tr + i * 16) * 33 + kk];
            float4 bv = *(const float4*)&Qs[kk * 64 + tc * 4];
            #pragma unroll
            for (int i = 0; i < 8; i++) {
                acc[i][0] += a[i] * bv.x;
                acc[i][1] += a[i] * bv.y;
                acc[i][2] += a[i] * bv.z;
                acc[i][3] += a[i] * bv.w;
            }
        }
        __syncthreads();
    }
    #pragma unroll
    for (int i = 0; i < 8; i++) {
        int j = tr + i * 16;
        float4 v = make_float4(acc[i][0], acc[i][1], acc[i][2], acc[i][3]);
        *(float4*)&g_X[((size_t)b * JJ + j) * DD + d0 + tc * 4] = v;
    }
}

// ---------------------------------------------------------------------------
// Stage B (fp32 SIMT, R1-proven mainloop): per-mode complex matmul.
// NEW epilogue: writes Y^T split-bf16 swizzled tiles for stage C.
// Y^T tiles: per (b, et 0..3, kc 0..1): [e_local 128][kk 64], kc0=Re, kc1=Im
// ---------------------------------------------------------------------------
__global__ void __launch_bounds__(128) stageB_kernel() {
    __shared__ float xr_s[32 * 33];
    __shared__ float xi_s[32 * 33];
    __shared__ float wr_s[32 * 64];
    __shared__ float wi_s[32 * 64];
    int m  = blockIdx.y;
    int e0 = blockIdx.x * 64;
    int tid = threadIdx.x;
    int ec = tid & 15, br = tid >> 4;
    float yr[4][4], yi[4][4];
    #pragma unroll
    for (int i = 0; i < 4; i++)
        #pragma unroll
        for (int t = 0; t < 4; t++) { yr[i][t] = 0.0f; yi[i][t] = 0.0f; }

    for (int k0 = 0; k0 < DD; k0 += 32) {
        #pragma unroll
        for (int i = 0; i < 8; i++) {
            int e = tid + i * 128;
            int bb = e >> 5, kk = e & 31;
            xr_s[bb * 33 + kk] = g_X[((size_t)bb * JJ + m) * DD + k0 + kk];
            xi_s[bb * 33 + kk] = g_X[((size_t)bb * JJ + MODESN + m) * DD + k0 + kk];
        }
        #pragma unroll
        for (int i = 0; i < 16; i++) {
            int e = tid + i * 128;
            int kk = e >> 6, ee = e & 63;
            size_t widx = ((size_t)m * DD + k0 + kk) * DD + e0 + ee;
            wr_s[kk * 64 + ee] = g_WTr[widx];
            wi_s[kk * 64 + ee] = g_WTi[widx];
        }
        __syncthreads();
        #pragma unroll
        for (int kk = 0; kk < 32; kk++) {
            float xr[4], xi[4];
            #pragma unroll
            for (int i = 0; i < 4; i++) {
                xr[i] = xr_s[(br * 4 + i) * 33 + kk];
                xi[i] = xi_s[(br * 4 + i) * 33 + kk];
            }
            float4 wr4 = *(const float4*)&wr_s[kk * 64 + ec * 4];
            float4 wi4 = *(const float4*)&wi_s[kk * 64 + ec * 4];
            float wr[4] = {wr4.x, wr4.y, wr4.z, wr4.w};
            float wim[4] = {wi4.x, wi4.y, wi4.z, wi4.w};
            #pragma unroll
            for (int i = 0; i < 4; i++)
                #pragma unroll
                for (int t = 0; t < 4; t++) {
                    yr[i][t] += xr[i] * wr[t];
                    yr[i][t] -= xi[i] * wim[t];
                    yi[i][t] += xr[i] * wim[t];
                    yi[i][t] += xi[i] * wr[t];
                }
        }
        __syncthreads();
    }
    // Epilogue: Y^T tiles. Row = e_local, col bytes = m*2. YR -> kc 0, YI -> kc 1.
    #pragma unroll
    for (int i = 0; i < 4; i++) {
        int bb = br * 4 + i;
        #pragma unroll
        for (int t = 0; t < 4; t++) {
            int e = e0 + ec * 4 + t;
            int et = e >> 7;
            int el = e & 127;
            size_t tbR = (((size_t)bb * 4 + et) * 2 + 0) * 16384;
            size_t tbI = tbR + 16384;
            uint32_t off = swz((uint32_t)el * 128u + (uint32_t)m * 2u);
            unsigned short h, l;
            split_bf16(yr[i][t], h, l);
            *(unsigned short*)(g_yth + tbR + off) = h;
            *(unsigned short*)(g_ytl + tbR + off) = l;
            split_bf16(yi[i][t], h, l);
            *(unsigned short*)(g_yth + tbI + off) = h;
            *(unsigned short*)(g_ytl + tbI + off) = l;
        }
    }
}

// ---------------------------------------------------------------------------
// Stage C (mma.sync bf16): out[b][l-tile 128][e-tile 128] = F @ Y_b, K=128
// grid (et=4, lt=32, b=32), 256 threads, 64 KB smem reused over 2 K-chunks
// ---------------------------------------------------------------------------
__global__ void __launch_bounds__(256, 2) stageC_mma(float* __restrict__ out) {
    extern __shared__ __align__(16) unsigned char smem[];
    uint32_t sb = smem_u32(smem);
    int tid = threadIdx.x;
    int lane = tid & 31, warp = tid >> 5;
    int wm = warp & 3, wn = warp >> 2;
    int et = blockIdx.x, lt = blockIdx.y, b = blockIdx.z;

    float acc[2][8][4];
    #pragma unroll
    for (int mt = 0; mt < 2; mt++)
        #pragma unroll
        for (int sg = 0; sg < 8; sg++)
            #pragma unroll
            for (int i = 0; i < 4; i++) acc[mt][sg][i] = 0.0f;

    uint4* dAh = (uint4*)(smem);
    uint4* dAl = (uint4*)(smem + 16384);
    uint4* dBh = (uint4*)(smem + 32768);
    uint4* dBl = (uint4*)(smem + 49152);

    #pragma unroll
    for (int kc = 0; kc < 2; kc++) {
        const uint4* sAh = (const uint4*)(g_Fh + (size_t)(lt * 2 + kc) * 16384);
        const uint4* sAl = (const uint4*)(g_Fl + (size_t)(lt * 2 + kc) * 16384);
        size_t ytb = (((size_t)b * 4 + et) * 2 + kc) * 16384;
        const uint4* sBh = (const uint4*)(g_yth + ytb);
        const uint4* sBl = (const uint4*)(g_ytl + ytb);
        #pragma unroll
        for (int i = 0; i < 4; i++) {
            int t2 = tid + i * 256;
            dAh[t2] = sAh[t2];
            dAl[t2] = sAl[t2];
            dBh[t2] = sBh[t2];
            dBl[t2] = sBl[t2];
        }
        __syncthreads();
        gemm_chunk(sb, lane, wm, wn, acc);
        __syncthreads();
    }

    // Epilogue: out [b][l][e]
    int tg = lane >> 2, tig = lane & 3;
    #pragma unroll
    for (int mt = 0; mt < 2; mt++) {
        int l0 = lt * 128 + wm * 32 + mt * 16;
        #pragma unroll
        for (int sg = 0; sg < 8; sg++) {
            int ecol = et * 128 + wn * 64 + sg * 8 + tig * 2;
            float* p0 = out + ((size_t)b * LL + l0 + tg) * DD + ecol;
            float* p1 = out + ((size_t)b * LL + l0 + tg + 8) * DD + ecol;
            *(float2*)p0 = make_float2(acc[mt][sg][0], acc[mt][sg][1]);
            *(float2*)p1 = make_float2(acc[mt][sg][2], acc[mt][sg][3]);
        }
    }
}

// ---------------------------------------------------------------------------
// launch
// ---------------------------------------------------------------------------
extern "C" void kernel_launch(void* const* d_in, const int* in_sizes, int n_in,
                              void* d_out, int out_size) {
    const float* q  = (const float*)d_in[0];
    const float* wr = (const float*)d_in[1];
    const float* wi = (const float*)d_in[2];
    float* out = (float*)d_out;

    // Idempotent, every invocation (no static guards — harness rule)
    cudaFuncSetAttribute(stageC_mma, cudaFuncAttributeMaxDynamicSharedMemorySize, 65536);

    build_basisA<<<(JJ * LL) / 256, 256>>>();
    build_basisF_sw<<<256, 256>>>();

    dim3 tgrid((DD * DD) / 32, MODESN / 32);
    transpose_w<<<tgrid, dim3(32, 8)>>>(wr, 0);
    transpose_w<<<tgrid, dim3(32, 8)>>>(wi, 1);

    stageA_kernel<<<dim3(DD / 64, NB), 256>>>(q);
    stageB_kernel<<<dim3(DD / 64, MODESN), 128>>>();
    stageC_mma<<<dim3(4, 32, NB), 256, 65536>>>(out);
}

// round 8
// speedup vs baseline: 1.3333x; 1.0033x over previous
#include <cuda_runtime.h>
#include <cuda_bf16.h>
#include <cstdint>

// Problem constants
#define LL     4096
#define DD     512
#define MODESN 64
#define JJ     128   // 2*MODES (Re rows then Im rows)
#define NB     32    // batch

// ---------------------------------------------------------------------------
// Static device scratch (no allocation allowed)
// ---------------------------------------------------------------------------
// Stage A basis, pre-swizzled bf16 hi/lo: [kc 64] tiles [j 128][kk 64] (16 KB)
__device__ __align__(16) unsigned char g_Ah[64 * 16384];
__device__ __align__(16) unsigned char g_Al[64 * 16384];
// Stage C basis (irfft), pre-swizzled bf16 hi/lo: [lt 32][kc 2] tiles [l 128][kk 64]
__device__ __align__(16) unsigned char g_Fh[64 * 16384];
__device__ __align__(16) unsigned char g_Fl[64 * 16384];
// Y transposed for stage C: per (b, et 0..3, kc 0..1): tile [e_local 128][kk 64]
__device__ __align__(16) unsigned char g_yth[(size_t)NB * 4 * 2 * 16384];
__device__ __align__(16) unsigned char g_ytl[(size_t)NB * 4 * 2 * 16384];
// Weights transposed fp32 [m][d][e]
__device__ float g_WTr[MODESN * DD * DD];
__device__ float g_WTi[MODESN * DD * DD];
// Stage A output fp32 [b][j][d]
__device__ float g_X[NB * JJ * DD];

// ---------------------------------------------------------------------------
// Helpers
// ---------------------------------------------------------------------------
__device__ __forceinline__ uint32_t swz(uint32_t x) { return x ^ ((x >> 3) & 0x70); }

// Swizzled byte offset of (row, byte-col cb) inside a [128 x 128B] tile.
__device__ __forceinline__ uint32_t swb(uint32_t row, uint32_t cb) {
    return row * 128u + (cb ^ ((row & 7u) << 4));
}

__device__ __forceinline__ uint32_t smem_u32(const void* p) {
    uint32_t a;
    asm("{ .reg .u64 t; cvta.to.shared.u64 t, %1; cvt.u32.u64 %0, t; }"
        : "=r"(a) : "l"(p));
    return a;
}

__device__ __forceinline__ uint32_t lds32(uint32_t a) {
    uint32_t v;
    asm volatile("ld.shared.b32 %0, [%1];" : "=r"(v) : "r"(a));
    return v;
}

__device__ __forceinline__ void split_bf16(float v, unsigned short& h, unsigned short& l) {
    __nv_bfloat16 bh = __float2bfloat16(v);
    float fh = __bfloat162float(bh);
    __nv_bfloat16 bl = __float2bfloat16(v - fh);
    h = __bfloat16_as_ushort(bh);
    l = __bfloat16_as_ushort(bl);
}

__device__ __forceinline__ void mma16816(float* c, const uint32_t* a,
                                         uint32_t b0, uint32_t b1) {
    asm volatile(
        "mma.sync.aligned.m16n8k16.row.col.f32.bf16.bf16.f32 "
        "{%0,%1,%2,%3}, {%4,%5,%6,%7}, {%8,%9}, {%0,%1,%2,%3};"
        : "+f"(c[0]), "+f"(c[1]), "+f"(c[2]), "+f"(c[3])
        : "r"(a[0]), "r"(a[1]), "r"(a[2]), "r"(a[3]), "r"(b0), "r"(b1));
}

// ---------------------------------------------------------------------------
// Core chunk compute (R7-PROVEN): CTA tile 128(M) x 128(N), chunk K=64.
// SMEM at `base`: Ah @0, Al @+16384, Bh @+32768, Bl @+49152 (all SW128).
// Warp wm (0-3): M rows 32*wm..; wn (0-1): N cols 64*wn..
// 3-product split accumulate: Ah*Bh + Ah*Bl + Al*Bh.
// ---------------------------------------------------------------------------
__device__ __forceinline__ void gemm_chunk(uint32_t base, int lane, int wm, int wn,
                                           float acc[2][8][4]) {
    const uint32_t q4 = (uint32_t)(lane & 3) * 4u;
    const uint32_t rA = (uint32_t)(lane >> 2);   // 0..7
    #pragma unroll
    for (int ks = 0; ks < 4; ks++) {
        const uint32_t kb = (uint32_t)ks * 32u;
        uint32_t ah[2][4], al[2][4];
        #pragma unroll
        for (int mt = 0; mt < 2; mt++) {
            uint32_t r0 = (uint32_t)(wm * 32 + mt * 16) + rA;
            uint32_t a00 = base + swb(r0,     kb + q4);
            uint32_t a10 = base + swb(r0 + 8, kb + q4);
            uint32_t a01 = base + swb(r0,     kb + 16 + q4);
            uint32_t a11 = base + swb(r0 + 8, kb + 16 + q4);
            ah[mt][0] = lds32(a00);
            ah[mt][1] = lds32(a10);
            ah[mt][2] = lds32(a01);
            ah[mt][3] = lds32(a11);
            al[mt][0] = lds32(a00 + 16384);
            al[mt][1] = lds32(a10 + 16384);
            al[mt][2] = lds32(a01 + 16384);
            al[mt][3] = lds32(a11 + 16384);
        }
        #pragma unroll
        for (int np = 0; np < 4; np++) {
            uint32_t n0 = (uint32_t)(wn * 64 + np * 16) + rA;
            uint32_t bb = base + 32768;
            uint32_t b00 = bb + swb(n0,     kb + q4);
            uint32_t b01 = bb + swb(n0,     kb + 16 + q4);
            uint32_t b10 = bb + swb(n0 + 8, kb + q4);
            uint32_t b11 = bb + swb(n0 + 8, kb + 16 + q4);
            uint32_t bh0 = lds32(b00), bh1 = lds32(b01);
            uint32_t bh2 = lds32(b10), bh3 = lds32(b11);
            uint32_t bl0 = lds32(b00 + 16384), bl1 = lds32(b01 + 16384);
            uint32_t bl2 = lds32(b10 + 16384), bl3 = lds32(b11 + 16384);
            #pragma unroll
            for (int mt = 0; mt < 2; mt++) {
                float* c0 = acc[mt][np * 2 + 0];
                float* c1 = acc[mt][np * 2 + 1];
                mma16816(c0, ah[mt], bh0, bh1);
                mma16816(c0, ah[mt], bl0, bl1);
                mma16816(c0, al[mt], bh0, bh1);
                mma16816(c1, ah[mt], bh2, bh3);
                mma16816(c1, ah[mt], bl2, bl3);
                mma16816(c1, al[mt], bh2, bh3);
            }
        }
    }
}

// ---------------------------------------------------------------------------
// Forward basis, pre-swizzled bf16 hi/lo tiles (clone of proven basisF pattern)
// Tiles: [kc 64][j 128][kk 64], kk = l within chunk, j = mode row.
// ---------------------------------------------------------------------------
__global__ void build_basisA_sw() {
    int t = blockIdx.x * blockDim.x + threadIdx.x;   // 65536 tasks
    int kc = t >> 10;          // 0..63
    int j  = (t >> 3) & 127;
    int oc = t & 7;
    uint32_t hw[4], lw[4];
    #pragma unroll
    for (int u = 0; u < 8; u++) {
        int kk = oc * 8 + u;
        int l = kc * 64 + kk;
        int m = j & 63;
        int phi = (m * l) & (LL - 1);
        float s, c;
        sincospif(2.0f * (float)phi / (float)LL, &s, &c);
        float v = (j < MODESN) ? c : -s;
        unsigned short h, lo;
        split_bf16(v, h, lo);
        if (u & 1) { hw[u >> 1] |= (uint32_t)h << 16; lw[u >> 1] |= (uint32_t)lo << 16; }
        else       { hw[u >> 1] = h;                  lw[u >> 1] = lo; }
    }
    uint32_t off = (uint32_t)kc * 16384u + swz((uint32_t)j * 128u + (uint32_t)oc * 16u);
    *(uint4*)(g_Ah + off) = make_uint4(hw[0], hw[1], hw[2], hw[3]);
    *(uint4*)(g_Al + off) = make_uint4(lw[0], lw[1], lw[2], lw[3]);
}

// ---------------------------------------------------------------------------
// Inverse basis, pre-swizzled bf16 hi/lo tiles (R7-PROVEN)
// ---------------------------------------------------------------------------
__global__ void build_basisF_sw() {
    int t = blockIdx.x * blockDim.x + threadIdx.x;   // 65536 tasks
    int lt = t >> 11;
    int kc = (t >> 10) & 1;
    int lr = (t >> 3) & 127;
    int oc = t & 7;
    int l = lt * 128 + lr;
    uint32_t hw[4], lw[4];
    #pragma unroll
    for (int u = 0; u < 8; u++) {
        int kk = oc * 8 + u;
        int j = kc * 64 + kk;
        int m = j & 63;
        int phi = (m * l) & (LL - 1);
        float s, c;
        sincospif(2.0f * (float)phi / (float)LL, &s, &c);
        float v;
        if (j < MODESN) v = ((m == 0) ? 1.0f : 2.0f) * (1.0f / (float)LL) * c;
        else            v = (-2.0f / (float)LL) * s;
        unsigned short h, lo;
        split_bf16(v, h, lo);
        if (u & 1) { hw[u >> 1] |= (uint32_t)h << 16; lw[u >> 1] |= (uint32_t)lo << 16; }
        else       { hw[u >> 1] = h;                  lw[u >> 1] = lo; }
    }
    uint32_t off = (uint32_t)(lt * 2 + kc) * 16384u + swz((uint32_t)lr * 128u + (uint32_t)oc * 16u);
    *(uint4*)(g_Fh + off) = make_uint4(hw[0], hw[1], hw[2], hw[3]);
    *(uint4*)(g_Fl + off) = make_uint4(lw[0], lw[1], lw[2], lw[3]);
}

// ---------------------------------------------------------------------------
// Weight transpose: [d*D+e][m] -> [m][d*D+e]  (fp32, R1-proven)
// ---------------------------------------------------------------------------
__global__ void transpose_w(const float* __restrict__ w, int which) {
    __shared__ float tile[32][33];
    float* __restrict__ wt = which ? g_WTi : g_WTr;
    int rb = blockIdx.x * 32;
    int cb = blockIdx.y * 32;
    int tx = threadIdx.x, ty = threadIdx.y;
    #pragma unroll
    for (int i = 0; i < 32; i += 8)
        tile[ty + i][tx] = w[(size_t)(rb + ty + i) * MODESN + cb + tx];
    __syncthreads();
    #pragma unroll
    for (int i = 0; i < 32; i += 8)
        wt[(size_t)(cb + ty + i) * (DD * DD) + rb + tx] = tile[tx][ty + i];
}

// ---------------------------------------------------------------------------
// Stage A (fused, mma.sync bf16): X[b][j 128][d-tile 128] = BA @ q_b, K=4096
// grid (nt=4, b=32), 256 threads, 1 CTA/SM.
// Per chunk: copy basis tiles, coalesced-load q block to fp32 staging,
// transpose+split+swizzle in-CTA, then proven gemm_chunk.
// SMEM: Ah@0 Al@16384 Bh@32768 Bl@49152, qstage fp32 @65536 (64 x 132 floats)
// ---------------------------------------------------------------------------
#define QS_STRIDE 132
__global__ void __launch_bounds__(256, 1) stageA_fused(const float* __restrict__ q) {
    extern __shared__ __align__(16) unsigned char smem[];
    uint32_t sb = smem_u32(smem);
    float* qs = (float*)(smem + 65536);
    int tid = threadIdx.x;
    int lane = tid & 31, warp = tid >> 5;
    int wm = warp & 3, wn = warp >> 2;
    int nt = blockIdx.x, b = blockIdx.y;

    float acc[2][8][4];
    #pragma unroll
    for (int mt = 0; mt < 2; mt++)
        #pragma unroll
        for (int sg = 0; sg < 8; sg++)
            #pragma unroll
            for (int i = 0; i < 4; i++) acc[mt][sg][i] = 0.0f;

    uint4* dAh = (uint4*)(smem);
    uint4* dAl = (uint4*)(smem + 16384);
    const int dl   = tid & 127;   // d_local for transpose pass
    const int half = tid >> 7;    // 0/1: kk range half*32..+31

    for (int ic = 0; ic < 64; ic++) {
        // 1) basis tiles global->smem
        const uint4* sAh = (const uint4*)(g_Ah + (size_t)ic * 16384);
        const uint4* sAl = (const uint4*)(g_Al + (size_t)ic * 16384);
        #pragma unroll
        for (int i = 0; i < 4; i++) {
            int t2 = tid + i * 256;
            dAh[t2] = sAh[t2];
            dAl[t2] = sAl[t2];
        }
        // 2) q block (64 l x 128 d) coalesced -> fp32 staging
        const float* qsrc = q + ((size_t)b * LL + (size_t)ic * 64) * DD + nt * 128;
        #pragma unroll
        for (int i = 0; i < 8; i++) {
            int idx = tid + i * 256;       // 0..2047
            int r  = idx >> 5;             // 0..63
            int c4 = idx & 31;             // 0..31 (float4 units)
            float4 v = *(const float4*)(qsrc + (size_t)r * DD + c4 * 4);
            *(float4*)&qs[r * QS_STRIDE + c4 * 4] = v;
        }
        __syncthreads();
        // 3) transpose + split + swizzled pack into B tiles
        #pragma unroll
        for (int g = 0; g < 4; g++) {
            uint32_t hw[4], lw[4];
            #pragma unroll
            for (int u = 0; u < 8; u++) {
                int kk = half * 32 + g * 8 + u;
                float v = qs[kk * QS_STRIDE + dl];
                unsigned short h, lo;
                split_bf16(v, h, lo);
                if (u & 1) { hw[u >> 1] |= (uint32_t)h << 16; lw[u >> 1] |= (uint32_t)lo << 16; }
                else       { hw[u >> 1] = h;                  lw[u >> 1] = lo; }
            }
            uint32_t off = swb((uint32_t)dl, (uint32_t)(half * 64 + g * 16));
            *(uint4*)(smem + 32768 + off) = make_uint4(hw[0], hw[1], hw[2], hw[3]);
            *(uint4*)(smem + 49152 + off) = make_uint4(lw[0], lw[1], lw[2], lw[3]);
        }
        __syncthreads();
        // 4) proven tensor-core chunk
        gemm_chunk(sb, lane, wm, wn, acc);
        __syncthreads();
    }

    // Epilogue: write fp32 X [b][j][d]
    int tg = lane >> 2, tig = lane & 3;
    #pragma unroll
    for (int mt = 0; mt < 2; mt++) {
        int j0 = wm * 32 + mt * 16;
        #pragma unroll
        for (int sg = 0; sg < 8; sg++) {
            int dcol = nt * 128 + wn * 64 + sg * 8 + tig * 2;
            float* p0 = g_X + ((size_t)b * JJ + j0 + tg) * DD + dcol;
            float* p1 = g_X + ((size_t)b * JJ + j0 + tg + 8) * DD + dcol;
            *(float2*)p0 = make_float2(acc[mt][sg][0], acc[mt][sg][1]);
            *(float2*)p1 = make_float2(acc[mt][sg][2], acc[mt][sg][3]);
        }
    }
}

// ---------------------------------------------------------------------------
// Stage B (fp32 SIMT, R7-proven): per-mode complex matmul; Y^T epilogue
// Y^T tiles: per (b, et 0..3, kc 0..1): [e_local 128][kk 64], kc0=Re, kc1=Im
// ---------------------------------------------------------------------------
__global__ void __launch_bounds__(128) stageB_kernel() {
    __shared__ float xr_s[32 * 33];
    __shared__ float xi_s[32 * 33];
    __shared__ float wr_s[32 * 64];
    __shared__ float wi_s[32 * 64];
    int m  = blockIdx.y;
    int e0 = blockIdx.x * 64;
    int tid = threadIdx.x;
    int ec = tid & 15, br = tid >> 4;
    float yr[4][4], yi[4][4];
    #pragma unroll
    for (int i = 0; i < 4; i++)
        #pragma unroll
        for (int t = 0; t < 4; t++) { yr[i][t] = 0.0f; yi[i][t] = 0.0f; }

    for (int k0 = 0; k0 < DD; k0 += 32) {
        #pragma unroll
        for (int i = 0; i < 8; i++) {
            int e = tid + i * 128;
            int bb = e >> 5, kk = e & 31;
            xr_s[bb * 33 + kk] = g_X[((size_t)bb * JJ + m) * DD + k0 + kk];
            xi_s[bb * 33 + kk] = g_X[((size_t)bb * JJ + MODESN + m) * DD + k0 + kk];
        }
        #pragma unroll
        for (int i = 0; i < 16; i++) {
            int e = tid + i * 128;
            int kk = e >> 6, ee = e & 63;
            size_t widx = ((size_t)m * DD + k0 + kk) * DD + e0 + ee;
            wr_s[kk * 64 + ee] = g_WTr[widx];
            wi_s[kk * 64 + ee] = g_WTi[widx];
        }
        __syncthreads();
        #pragma unroll
        for (int kk = 0; kk < 32; kk++) {
            float xr[4], xi[4];
            #pragma unroll
            for (int i = 0; i < 4; i++) {
                xr[i] = xr_s[(br * 4 + i) * 33 + kk];
                xi[i] = xi_s[(br * 4 + i) * 33 + kk];
            }
            float4 wr4 = *(const float4*)&wr_s[kk * 64 + ec * 4];
            float4 wi4 = *(const float4*)&wi_s[kk * 64 + ec * 4];
            float wr[4] = {wr4.x, wr4.y, wr4.z, wr4.w};
            float wim[4] = {wi4.x, wi4.y, wi4.z, wi4.w};
            #pragma unroll
            for (int i = 0; i < 4; i++)
                #pragma unroll
                for (int t = 0; t < 4; t++) {
                    yr[i][t] += xr[i] * wr[t];
                    yr[i][t] -= xi[i] * wim[t];
                    yi[i][t] += xr[i] * wim[t];
                    yi[i][t] += xi[i] * wr[t];
                }
        }
        __syncthreads();
    }
    #pragma unroll
    for (int i = 0; i < 4; i++) {
        int bb = br * 4 + i;
        #pragma unroll
        for (int t = 0; t < 4; t++) {
            int e = e0 + ec * 4 + t;
            int et = e >> 7;
            int el = e & 127;
            size_t tbR = (((size_t)bb * 4 + et) * 2 + 0) * 16384;
            size_t tbI = tbR + 16384;
            uint32_t off = swz((uint32_t)el * 128u + (uint32_t)m * 2u);
            unsigned short h, l;
            split_bf16(yr[i][t], h, l);
            *(unsigned short*)(g_yth + tbR + off) = h;
            *(unsigned short*)(g_ytl + tbR + off) = l;
            split_bf16(yi[i][t], h, l);
            *(unsigned short*)(g_yth + tbI + off) = h;
            *(unsigned short*)(g_ytl + tbI + off) = l;
        }
    }
}

// ---------------------------------------------------------------------------
// Stage C (mma.sync bf16, R7-PROVEN): out[b][l 128][e 128] = F @ Y_b, K=128
// grid (et=4, lt=32, b=32), 256 threads, 64 KB smem reused over 2 K-chunks
// ---------------------------------------------------------------------------
__global__ void __launch_bounds__(256, 2) stageC_mma(float* __restrict__ out) {
    extern __shared__ __align__(16) unsigned char smem[];
    uint32_t sb = smem_u32(smem);
    int tid = threadIdx.x;
    int lane = tid & 31, warp = tid >> 5;
    int wm = warp & 3, wn = warp >> 2;
    int et = blockIdx.x, lt = blockIdx.y, b = blockIdx.z;

    float acc[2][8][4];
    #pragma unroll
    for (int mt = 0; mt < 2; mt++)
        #pragma unroll
        for (int sg = 0; sg < 8; sg++)
            #pragma unroll
            for (int i = 0; i < 4; i++) acc[mt][sg][i] = 0.0f;

    uint4* dAh = (uint4*)(smem);
    uint4* dAl = (uint4*)(smem + 16384);
    uint4* dBh = (uint4*)(smem + 32768);
    uint4* dBl = (uint4*)(smem + 49152);

    #pragma unroll
    for (int kc = 0; kc < 2; kc++) {
        const uint4* sAh = (const uint4*)(g_Fh + (size_t)(lt * 2 + kc) * 16384);
        const uint4* sAl = (const uint4*)(g_Fl + (size_t)(lt * 2 + kc) * 16384);
        size_t ytb = (((size_t)b * 4 + et) * 2 + kc) * 16384;
        const uint4* sBh = (const uint4*)(g_yth + ytb);
        const uint4* sBl = (const uint4*)(g_ytl + ytb);
        #pragma unroll
        for (int i = 0; i < 4; i++) {
            int t2 = tid + i * 256;
            dAh[t2] = sAh[t2];
            dAl[t2] = sAl[t2];
            dBh[t2] = sBh[t2];
            dBl[t2] = sBl[t2];
        }
        __syncthreads();
        gemm_chunk(sb, lane, wm, wn, acc);
        __syncthreads();
    }

    int tg = lane >> 2, tig = lane & 3;
    #pragma unroll
    for (int mt = 0; mt < 2; mt++) {
        int l0 = lt * 128 + wm * 32 + mt * 16;
        #pragma unroll
        for (int sg = 0; sg < 8; sg++) {
            int ecol = et * 128 + wn * 64 + sg * 8 + tig * 2;
            float* p0 = out + ((size_t)b * LL + l0 + tg) * DD + ecol;
            float* p1 = out + ((size_t)b * LL + l0 + tg + 8) * DD + ecol;
            *(float2*)p0 = make_float2(acc[mt][sg][0], acc[mt][sg][1]);
            *(float2*)p1 = make_float2(acc[mt][sg][2], acc[mt][sg][3]);
        }
    }
}

// ---------------------------------------------------------------------------
// launch
// ---------------------------------------------------------------------------
extern "C" void kernel_launch(void* const* d_in, const int* in_sizes, int n_in,
                              void* d_out, int out_size) {
    const float* q  = (const float*)d_in[0];
    const float* wr = (const float*)d_in[1];
    const float* wi = (const float*)d_in[2];
    float* out = (float*)d_out;

    // Idempotent, every invocation (no static guards — harness rule)
    cudaFuncSetAttribute(stageA_fused, cudaFuncAttributeMaxDynamicSharedMemorySize, 99328);
    cudaFuncSetAttribute(stageC_mma, cudaFuncAttributeMaxDynamicSharedMemorySize, 65536);

    build_basisA_sw<<<256, 256>>>();
    build_basisF_sw<<<256, 256>>>();

    dim3 tgrid((DD * DD) / 32, MODESN / 32);
    transpose_w<<<tgrid, dim3(32, 8)>>>(wr, 0);
    transpose_w<<<tgrid, dim3(32, 8)>>>(wi, 1);

    stageA_fused<<<dim3(4, NB), 256, 99328>>>(q);
    stageB_kernel<<<dim3(DD / 64, MODESN), 128>>>();
    stageC_mma<<<dim3(4, 32, NB), 256, 65536>>>(out);
}

// round 9
// speedup vs baseline: 2.3088x; 1.7317x over previous
#include <cuda_runtime.h>
#include <cuda_bf16.h>
#include <cstdint>

// Problem constants
#define LL     4096
#define DD     512
#define MODESN 64
#define JJ     128   // 2*MODES (Re rows then Im rows)
#define NB     32    // batch

// tf32 tile geometry: [row 128][word 64 data + 4 pad] fp32 words
#define TPW     68
#define TWORDS  (128 * TPW)        // 8704 words = 34816 bytes per tile
#define TILE_BYTES (TWORDS * 4)
#define TILE_U4 (TWORDS / 4)       // 2176 uint4 per tile

// ---------------------------------------------------------------------------
// Static device scratch (no allocation allowed)
// ---------------------------------------------------------------------------
// Stage A basis tiles: [kc 64] of [j 128][kk 64(+4)] tf32 words
__device__ __align__(16) uint32_t g_A[64 * TWORDS];
// Stage C basis tiles: [lt 32][kc 2] of [l 128][j 64(+4)]
__device__ __align__(16) uint32_t g_F[64 * TWORDS];
// Y^T tiles for stage C: [b 32][et 4][kc 2] of [e_local 128][m 64(+4)]
__device__ __align__(16) uint32_t g_yt[256 * TWORDS];
// Weights transposed fp32 [m][d][e]
__device__ float g_WTr[MODESN * DD * DD];
__device__ float g_WTi[MODESN * DD * DD];
// Stage A partial outputs fp32 [b][j][d] (K-split halves)
__device__ float g_X [NB * JJ * DD];
__device__ float g_X2[NB * JJ * DD];

// ---------------------------------------------------------------------------
// Helpers
// ---------------------------------------------------------------------------
__device__ __forceinline__ uint32_t smem_u32(const void* p) {
    uint32_t a;
    asm("{ .reg .u64 t; cvta.to.shared.u64 t, %1; cvt.u32.u64 %0, t; }"
        : "=r"(a) : "l"(p));
    return a;
}

__device__ __forceinline__ uint32_t lds32(uint32_t a) {
    uint32_t v;
    asm volatile("ld.shared.b32 %0, [%1];" : "=r"(v) : "r"(a));
    return v;
}

// fp32 -> tf32 (round to nearest, result bits in a b32 register)
__device__ __forceinline__ uint32_t tf32r(float v) {
    uint32_t r;
    asm("cvt.rna.tf32.f32 %0, %1;" : "=r"(r) : "f"(v));
    return r;
}

__device__ __forceinline__ void mma_tf32(float* c, const uint32_t* a,
                                         uint32_t b0, uint32_t b1) {
    asm volatile(
        "mma.sync.aligned.m16n8k8.row.col.f32.tf32.tf32.f32 "
        "{%0,%1,%2,%3}, {%4,%5,%6,%7}, {%8,%9}, {%0,%1,%2,%3};"
        : "+f"(c[0]), "+f"(c[1]), "+f"(c[2]), "+f"(c[3])
        : "r"(a[0]), "r"(a[1]), "r"(a[2]), "r"(a[3]), "r"(b0), "r"(b1));
}

// ---------------------------------------------------------------------------
// tf32 chunk compute: CTA tile 128(M) x 128(N), chunk K=64.
// A tile at byte addr baseA: [m row 128][k word 64(+4)], row-major M x K.
// B tile at byte addr baseB: [n row 128][k word 64(+4)], col-major K x N.
// Warp wm (0-3): M rows 32*wm..; wn (0-1): N cols 64*wn.. (8 n-tiles of 8).
// Row padding to 68 words makes every fragment load bank-conflict-free:
// word addr = row*68 + k  ->  bank = (row*4 + k) mod 32, 8 rows x 4 k all distinct.
// ---------------------------------------------------------------------------
__device__ __forceinline__ void gemm_tf32(uint32_t baseA, uint32_t baseB,
                                          int lane, int wm, int wn,
                                          float acc[2][8][4]) {
    const uint32_t g  = (uint32_t)(lane >> 2);   // 0..7 (group id)
    const uint32_t t4 = (uint32_t)(lane & 3);    // 0..3
    #pragma unroll
    for (int k8 = 0; k8 < 8; k8++) {
        const uint32_t kw = (uint32_t)k8 * 8u + t4;
        uint32_t a[2][4];
        #pragma unroll
        for (int mt = 0; mt < 2; mt++) {
            uint32_t r0 = (uint32_t)(wm * 32 + mt * 16) + g;
            a[mt][0] = lds32(baseA + (r0 * TPW + kw) * 4u);
            a[mt][1] = lds32(baseA + ((r0 + 8) * TPW + kw) * 4u);
            a[mt][2] = lds32(baseA + (r0 * TPW + kw + 4) * 4u);
            a[mt][3] = lds32(baseA + ((r0 + 8) * TPW + kw + 4) * 4u);
        }
        #pragma unroll
        for (int nt = 0; nt < 8; nt++) {
            uint32_t nr = (uint32_t)(wn * 64 + nt * 8) + g;
            uint32_t b0 = lds32(baseB + (nr * TPW + kw) * 4u);
            uint32_t b1 = lds32(baseB + (nr * TPW + kw + 4) * 4u);
            mma_tf32(acc[0][nt], a[0], b0, b1);
            mma_tf32(acc[1][nt], a[1], b0, b1);
        }
    }
}

// ---------------------------------------------------------------------------
// Basis builders: write tf32-rounded padded tiles
// ---------------------------------------------------------------------------
__global__ void build_basisA_tf32() {
    int t = blockIdx.x * blockDim.x + threadIdx.x;   // 131072 tasks
    int kc = t >> 11;           // 0..63
    int j  = (t >> 4) & 127;
    int oc = t & 15;            // 4-word group
    uint32_t w[4];
    #pragma unroll
    for (int u = 0; u < 4; u++) {
        int l = kc * 64 + oc * 4 + u;
        int m = j & 63;
        int phi = (m * l) & (LL - 1);
        float s, c;
        sincospif(2.0f * (float)phi / (float)LL, &s, &c);
        w[u] = tf32r((j < MODESN) ? c : -s);
    }
    *(uint4*)&g_A[(size_t)kc * TWORDS + j * TPW + oc * 4] =
        make_uint4(w[0], w[1], w[2], w[3]);
}

__global__ void build_basisF_tf32() {
    int t = blockIdx.x * blockDim.x + threadIdx.x;   // 131072 tasks
    int tile = t >> 11;         // 0..63 = lt*2+kc
    int lt = tile >> 1;
    int kc = tile & 1;
    int lr = (t >> 4) & 127;
    int oc = t & 15;
    int l = lt * 128 + lr;
    uint32_t w[4];
    #pragma unroll
    for (int u = 0; u < 4; u++) {
        int j = kc * 64 + oc * 4 + u;
        int m = j & 63;
        int phi = (m * l) & (LL - 1);
        float s, c;
        sincospif(2.0f * (float)phi / (float)LL, &s, &c);
        float v;
        if (j < MODESN) v = ((m == 0) ? 1.0f : 2.0f) * (1.0f / (float)LL) * c;
        else            v = (-2.0f / (float)LL) * s;
        w[u] = tf32r(v);
    }
    *(uint4*)&g_F[(size_t)tile * TWORDS + lr * TPW + oc * 4] =
        make_uint4(w[0], w[1], w[2], w[3]);
}

// ---------------------------------------------------------------------------
// Weight transpose: [d*D+e][m] -> [m][d*D+e]  (fp32, R1-proven)
// ---------------------------------------------------------------------------
__global__ void transpose_w(const float* __restrict__ w, int which) {
    __shared__ float tile[32][33];
    float* __restrict__ wt = which ? g_WTi : g_WTr;
    int rb = blockIdx.x * 32;
    int cb = blockIdx.y * 32;
    int tx = threadIdx.x, ty = threadIdx.y;
    #pragma unroll
    for (int i = 0; i < 32; i += 8)
        tile[ty + i][tx] = w[(size_t)(rb + ty + i) * MODESN + cb + tx];
    __syncthreads();
    #pragma unroll
    for (int i = 0; i < 32; i += 8)
        wt[(size_t)(cb + ty + i) * (DD * DD) + rb + tx] = tile[tx][ty + i];
}

// ---------------------------------------------------------------------------
// Stage A (fused tf32 mma): X[b][j 128][d-tile 128] = BA @ q_b
// K-split: grid (dt 4, b 32, ks 2); each CTA does K chunks ks*32..+31.
// 2 CTAs/SM (103 KB smem). Per chunk: copy basis tile, coalesced q load,
// in-CTA transpose+tf32-cvt, gemm_tf32.
// SMEM: A tile @0, B tile @TILE_BYTES, q staging fp32 @2*TILE_BYTES (64x132)
// ---------------------------------------------------------------------------
#define QS_STRIDE 132
#define SMEM_A_BYTES (2 * TILE_BYTES + 64 * QS_STRIDE * 4)   // 103424
__global__ void __launch_bounds__(256, 2) stageA_tf32(const float* __restrict__ q) {
    extern __shared__ __align__(16) unsigned char smem[];
    uint32_t sb = smem_u32(smem);
    float* qs = (float*)(smem + 2 * TILE_BYTES);
    int tid = threadIdx.x;
    int lane = tid & 31, warp = tid >> 5;
    int wm = warp & 3, wn = warp >> 2;
    int dt = blockIdx.x, b = blockIdx.y, ks = blockIdx.z;

    float acc[2][8][4];
    #pragma unroll
    for (int mt = 0; mt < 2; mt++)
        #pragma unroll
        for (int nt = 0; nt < 8; nt++)
            #pragma unroll
            for (int i = 0; i < 4; i++) acc[mt][nt][i] = 0.0f;

    uint4* dA = (uint4*)smem;
    const int dl   = tid & 127;   // d_local (B-tile row) for transpose pass
    const int half = tid >> 7;    // word half 0/1

    for (int ic0 = 0; ic0 < 32; ic0++) {
        int ic = ks * 32 + ic0;
        // 1) basis tile global -> smem (2176 uint4)
        const uint4* sA = (const uint4*)&g_A[(size_t)ic * TWORDS];
        #pragma unroll
        for (int i = 0; i < 9; i++) {
            int idx = tid + i * 256;
            if (idx < TILE_U4) dA[idx] = sA[idx];
        }
        // 2) q block (64 l x 128 d) coalesced -> fp32 staging
        const float* qsrc = q + ((size_t)b * LL + (size_t)ic * 64) * DD + dt * 128;
        #pragma unroll
        for (int i = 0; i < 8; i++) {
            int idx = tid + i * 256;       // 0..2047
            int r  = idx >> 5;             // 0..63
            int c4 = idx & 31;             // float4 units
            float4 v = *(const float4*)(qsrc + (size_t)r * DD + c4 * 4);
            *(float4*)&qs[r * QS_STRIDE + c4 * 4] = v;
        }
        __syncthreads();
        // 3) transpose + tf32 cvt into B tile
        #pragma unroll
        for (int g2 = 0; g2 < 8; g2++) {
            uint32_t w[4];
            #pragma unroll
            for (int u = 0; u < 4; u++) {
                int kk = half * 32 + g2 * 4 + u;
                w[u] = tf32r(qs[kk * QS_STRIDE + dl]);
            }
            *(uint4*)(smem + TILE_BYTES + ((uint32_t)dl * TPW + half * 32 + g2 * 4) * 4) =
                make_uint4(w[0], w[1], w[2], w[3]);
        }
        __syncthreads();
        // 4) tensor chunk
        gemm_tf32(sb, sb + TILE_BYTES, lane, wm, wn, acc);
        __syncthreads();
    }

    // Epilogue: write fp32 partial X
    float* Xo = (ks == 0) ? g_X : g_X2;
    int tg = lane >> 2, tig = lane & 3;
    #pragma unroll
    for (int mt = 0; mt < 2; mt++) {
        int j0 = wm * 32 + mt * 16;
        #pragma unroll
        for (int nt = 0; nt < 8; nt++) {
            int dcol = dt * 128 + wn * 64 + nt * 8 + tig * 2;
            float* p0 = Xo + ((size_t)b * JJ + j0 + tg) * DD + dcol;
            float* p1 = Xo + ((size_t)b * JJ + j0 + tg + 8) * DD + dcol;
            *(float2*)p0 = make_float2(acc[mt][nt][0], acc[mt][nt][1]);
            *(float2*)p1 = make_float2(acc[mt][nt][2], acc[mt][nt][3]);
        }
    }
}

// ---------------------------------------------------------------------------
// Stage B (fp32 SIMT, proven mainloop): per-mode complex matmul.
// Reads X = g_X + g_X2 (K-split partials). Epilogue writes tf32 Y^T tiles.
// Y^T tiles: [b][et 0..3][kc 0..1] of [e_local 128][m word], kc0=Re, kc1=Im
// ---------------------------------------------------------------------------
__global__ void __launch_bounds__(128) stageB_kernel() {
    __shared__ float xr_s[32 * 33];
    __shared__ float xi_s[32 * 33];
    __shared__ float wr_s[32 * 64];
    __shared__ float wi_s[32 * 64];
    int m  = blockIdx.y;
    int e0 = blockIdx.x * 64;
    int tid = threadIdx.x;
    int ec = tid & 15, br = tid >> 4;
    float yr[4][4], yi[4][4];
    #pragma unroll
    for (int i = 0; i < 4; i++)
        #pragma unroll
        for (int t = 0; t < 4; t++) { yr[i][t] = 0.0f; yi[i][t] = 0.0f; }

    for (int k0 = 0; k0 < DD; k0 += 32) {
        #pragma unroll
        for (int i = 0; i < 8; i++) {
            int e = tid + i * 128;
            int bb = e >> 5, kk = e & 31;
            size_t ir = ((size_t)bb * JJ + m) * DD + k0 + kk;
            size_t ii = ((size_t)bb * JJ + MODESN + m) * DD + k0 + kk;
            xr_s[bb * 33 + kk] = g_X[ir] + g_X2[ir];
            xi_s[bb * 33 + kk] = g_X[ii] + g_X2[ii];
        }
        #pragma unroll
        for (int i = 0; i < 16; i++) {
            int e = tid + i * 128;
            int kk = e >> 6, ee = e & 63;
            size_t widx = ((size_t)m * DD + k0 + kk) * DD + e0 + ee;
            wr_s[kk * 64 + ee] = g_WTr[widx];
            wi_s[kk * 64 + ee] = g_WTi[widx];
        }
        __syncthreads();
        #pragma unroll
        for (int kk = 0; kk < 32; kk++) {
            float xr[4], xi[4];
            #pragma unroll
            for (int i = 0; i < 4; i++) {
                xr[i] = xr_s[(br * 4 + i) * 33 + kk];
                xi[i] = xi_s[(br * 4 + i) * 33 + kk];
            }
            float4 wr4 = *(const float4*)&wr_s[kk * 64 + ec * 4];
            float4 wi4 = *(const float4*)&wi_s[kk * 64 + ec * 4];
            float wr[4] = {wr4.x, wr4.y, wr4.z, wr4.w};
            float wim[4] = {wi4.x, wi4.y, wi4.z, wi4.w};
            #pragma unroll
            for (int i = 0; i < 4; i++)
                #pragma unroll
                for (int t = 0; t < 4; t++) {
                    yr[i][t] += xr[i] * wr[t];
                    yr[i][t] -= xi[i] * wim[t];
                    yi[i][t] += xr[i] * wim[t];
                    yi[i][t] += xi[i] * wr[t];
                }
        }
        __syncthreads();
    }
    // Epilogue: tf32-rounded Y^T tile words. word index = m within tile row.
    #pragma unroll
    for (int i = 0; i < 4; i++) {
        int bb = br * 4 + i;
        #pragma unroll
        for (int t = 0; t < 4; t++) {
            int e = e0 + ec * 4 + t;
            int et = e >> 7;
            int el = e & 127;
            size_t tR = (((size_t)bb * 4 + et) * 2 + 0) * TWORDS + (size_t)el * TPW + m;
            size_t tI = tR + TWORDS;
            g_yt[tR] = tf32r(yr[i][t]);
            g_yt[tI] = tf32r(yi[i][t]);
        }
    }
}

// ---------------------------------------------------------------------------
// Stage C (tf32 mma): out[b][l 128][e 128] = F @ Y_b, K=128 (2 chunks)
// grid (et 4, lt 32, b 32), 256 threads, 2 CTAs/SM (70 KB smem)
// ---------------------------------------------------------------------------
#define SMEM_C_BYTES (2 * TILE_BYTES)   // 69632
__global__ void __launch_bounds__(256, 2) stageC_tf32(float* __restrict__ out) {
    extern __shared__ __align__(16) unsigned char smem[];
    uint32_t sb = smem_u32(smem);
    int tid = threadIdx.x;
    int lane = tid & 31, warp = tid >> 5;
    int wm = warp & 3, wn = warp >> 2;
    int et = blockIdx.x, lt = blockIdx.y, b = blockIdx.z;

    float acc[2][8][4];
    #pragma unroll
    for (int mt = 0; mt < 2; mt++)
        #pragma unroll
        for (int nt = 0; nt < 8; nt++)
            #pragma unroll
            for (int i = 0; i < 4; i++) acc[mt][nt][i] = 0.0f;

    uint4* dA = (uint4*)smem;
    uint4* dB = (uint4*)(smem + TILE_BYTES);

    #pragma unroll
    for (int kc = 0; kc < 2; kc++) {
        const uint4* sA = (const uint4*)&g_F[(size_t)(lt * 2 + kc) * TWORDS];
        const uint4* sB = (const uint4*)&g_yt[(((size_t)b * 4 + et) * 2 + kc) * TWORDS];
        #pragma unroll
        for (int i = 0; i < 9; i++) {
            int idx = tid + i * 256;
            if (idx < TILE_U4) {
                dA[idx] = sA[idx];
                dB[idx] = sB[idx];
            }
        }
        __syncthreads();
        gemm_tf32(sb, sb + TILE_BYTES, lane, wm, wn, acc);
        __syncthreads();
    }

    int tg = lane >> 2, tig = lane & 3;
    #pragma unroll
    for (int mt = 0; mt < 2; mt++) {
        int l0 = lt * 128 + wm * 32 + mt * 16;
        #pragma unroll
        for (int nt = 0; nt < 8; nt++) {
            int ecol = et * 128 + wn * 64 + nt * 8 + tig * 2;
            float* p0 = out + ((size_t)b * LL + l0 + tg) * DD + ecol;
            float* p1 = out + ((size_t)b * LL + l0 + tg + 8) * DD + ecol;
            *(float2*)p0 = make_float2(acc[mt][nt][0], acc[mt][nt][1]);
            *(float2*)p1 = make_float2(acc[mt][nt][2], acc[mt][nt][3]);
        }
    }
}

// ---------------------------------------------------------------------------
// launch
// ---------------------------------------------------------------------------
extern "C" void kernel_launch(void* const* d_in, const int* in_sizes, int n_in,
                              void* d_out, int out_size) {
    const float* q  = (const float*)d_in[0];
    const float* wr = (const float*)d_in[1];
    const float* wi = (const float*)d_in[2];
    float* out = (float*)d_out;

    // Idempotent, every invocation (no static guards — harness rule)
    cudaFuncSetAttribute(stageA_tf32, cudaFuncAttributeMaxDynamicSharedMemorySize, SMEM_A_BYTES);
    cudaFuncSetAttribute(stageC_tf32, cudaFuncAttributeMaxDynamicSharedMemorySize, SMEM_C_BYTES);

    build_basisA_tf32<<<512, 256>>>();
    build_basisF_tf32<<<512, 256>>>();

    dim3 tgrid((DD * DD) / 32, MODESN / 32);
    transpose_w<<<tgrid, dim3(32, 8)>>>(wr, 0);
    transpose_w<<<tgrid, dim3(32, 8)>>>(wi, 1);

    stageA_tf32<<<dim3(4, NB, 2), 256, SMEM_A_BYTES>>>(q);
    stageB_kernel<<<dim3(DD / 64, MODESN), 128>>>();
    stageC_tf32<<<dim3(4, 32, NB), 256, SMEM_C_BYTES>>>(out);
}

// round 10
// speedup vs baseline: 2.4477x; 1.0601x over previous
#include <cuda_runtime.h>
#include <cuda_bf16.h>
#include <cstdint>

// Problem constants
#define LL     4096
#define DD     512
#define MODESN 64
#define JJ     128   // 2*MODES (Re rows then Im rows)
#define NB     32    // batch

// tf32 tile geometry: [row 128][word 64 data + 4 pad] fp32 words
#define TPW     68
#define TWORDS  (128 * TPW)        // 8704 words = 34816 bytes per tile
#define TILE_BYTES (TWORDS * 4)
#define TILE_U4 (TWORDS / 4)       // 2176 uint4 per tile

// ---------------------------------------------------------------------------
// Static device scratch (no allocation allowed)
// ---------------------------------------------------------------------------
// Stage A basis tiles: [kc 64] of [j 128][kk 64(+4)] tf32 words
__device__ __align__(16) uint32_t g_A[64 * TWORDS];
// Stage C basis tiles: [lt 32][kc 2] of [l 128][j 64(+4)]
__device__ __align__(16) uint32_t g_F[64 * TWORDS];
// Y^T tiles for stage C: [b 32][et 4][kc 2] of [e_local 128][m 64(+4)]
__device__ __align__(16) uint32_t g_yt[256 * TWORDS];
// Weights transposed fp32 [m][d][e]
__device__ float g_WTr[MODESN * DD * DD];
__device__ float g_WTi[MODESN * DD * DD];
// Stage A partial outputs fp32 [b][j][d] (K-split halves)
__device__ float g_X [NB * JJ * DD];
__device__ float g_X2[NB * JJ * DD];

// ---------------------------------------------------------------------------
// Helpers
// ---------------------------------------------------------------------------
__device__ __forceinline__ uint32_t smem_u32(const void* p) {
    uint32_t a;
    asm("{ .reg .u64 t; cvta.to.shared.u64 t, %1; cvt.u32.u64 %0, t; }"
        : "=r"(a) : "l"(p));
    return a;
}

__device__ __forceinline__ uint32_t lds32(uint32_t a) {
    uint32_t v;
    asm volatile("ld.shared.b32 %0, [%1];" : "=r"(v) : "r"(a));
    return v;
}

// fp32 -> tf32 (round to nearest, result bits in a b32 register)
__device__ __forceinline__ uint32_t tf32r(float v) {
    uint32_t r;
    asm("cvt.rna.tf32.f32 %0, %1;" : "=r"(r) : "f"(v));
    return r;
}

__device__ __forceinline__ void mma_tf32(float* c, const uint32_t* a,
                                         uint32_t b0, uint32_t b1) {
    asm volatile(
        "mma.sync.aligned.m16n8k8.row.col.f32.tf32.tf32.f32 "
        "{%0,%1,%2,%3}, {%4,%5,%6,%7}, {%8,%9}, {%0,%1,%2,%3};"
        : "+f"(c[0]), "+f"(c[1]), "+f"(c[2]), "+f"(c[3])
        : "r"(a[0]), "r"(a[1]), "r"(a[2]), "r"(a[3]), "r"(b0), "r"(b1));
}

// ---------------------------------------------------------------------------
// tf32 chunk compute (R9-PROVEN): CTA tile 128(M) x 128(N), chunk K=64.
// A tile [m row 128][k word 64(+4)]; B tile [n row 128][k word 64(+4)].
// ---------------------------------------------------------------------------
__device__ __forceinline__ void gemm_tf32(uint32_t baseA, uint32_t baseB,
                                          int lane, int wm, int wn,
                                          float acc[2][8][4]) {
    const uint32_t g  = (uint32_t)(lane >> 2);   // 0..7
    const uint32_t t4 = (uint32_t)(lane & 3);    // 0..3
    #pragma unroll
    for (int k8 = 0; k8 < 8; k8++) {
        const uint32_t kw = (uint32_t)k8 * 8u + t4;
        uint32_t a[2][4];
        #pragma unroll
        for (int mt = 0; mt < 2; mt++) {
            uint32_t r0 = (uint32_t)(wm * 32 + mt * 16) + g;
            a[mt][0] = lds32(baseA + (r0 * TPW + kw) * 4u);
            a[mt][1] = lds32(baseA + ((r0 + 8) * TPW + kw) * 4u);
            a[mt][2] = lds32(baseA + (r0 * TPW + kw + 4) * 4u);
            a[mt][3] = lds32(baseA + ((r0 + 8) * TPW + kw + 4) * 4u);
        }
        #pragma unroll
        for (int nt = 0; nt < 8; nt++) {
            uint32_t nr = (uint32_t)(wn * 64 + nt * 8) + g;
            uint32_t b0 = lds32(baseB + (nr * TPW + kw) * 4u);
            uint32_t b1 = lds32(baseB + (nr * TPW + kw + 4) * 4u);
            mma_tf32(acc[0][nt], a[0], b0, b1);
            mma_tf32(acc[1][nt], a[1], b0, b1);
        }
    }
}

// ---------------------------------------------------------------------------
// Basis builders (R9-proven)
// ---------------------------------------------------------------------------
__global__ void build_basisA_tf32() {
    int t = blockIdx.x * blockDim.x + threadIdx.x;
    int kc = t >> 11;
    int j  = (t >> 4) & 127;
    int oc = t & 15;
    uint32_t w[4];
    #pragma unroll
    for (int u = 0; u < 4; u++) {
        int l = kc * 64 + oc * 4 + u;
        int m = j & 63;
        int phi = (m * l) & (LL - 1);
        float s, c;
        sincospif(2.0f * (float)phi / (float)LL, &s, &c);
        w[u] = tf32r((j < MODESN) ? c : -s);
    }
    *(uint4*)&g_A[(size_t)kc * TWORDS + j * TPW + oc * 4] =
        make_uint4(w[0], w[1], w[2], w[3]);
}

__global__ void build_basisF_tf32() {
    int t = blockIdx.x * blockDim.x + threadIdx.x;
    int tile = t >> 11;
    int lt = tile >> 1;
    int kc = tile & 1;
    int lr = (t >> 4) & 127;
    int oc = t & 15;
    int l = lt * 128 + lr;
    uint32_t w[4];
    #pragma unroll
    for (int u = 0; u < 4; u++) {
        int j = kc * 64 + oc * 4 + u;
        int m = j & 63;
        int phi = (m * l) & (LL - 1);
        float s, c;
        sincospif(2.0f * (float)phi / (float)LL, &s, &c);
        float v;
        if (j < MODESN) v = ((m == 0) ? 1.0f : 2.0f) * (1.0f / (float)LL) * c;
        else            v = (-2.0f / (float)LL) * s;
        w[u] = tf32r(v);
    }
    *(uint4*)&g_F[(size_t)tile * TWORDS + lr * TPW + oc * 4] =
        make_uint4(w[0], w[1], w[2], w[3]);
}

// ---------------------------------------------------------------------------
// Weight transpose: [d*D+e][m] -> [m][d*D+e]  (fp32, proven)
// ---------------------------------------------------------------------------
__global__ void transpose_w(const float* __restrict__ w, int which) {
    __shared__ float tile[32][33];
    float* __restrict__ wt = which ? g_WTi : g_WTr;
    int rb = blockIdx.x * 32;
    int cb = blockIdx.y * 32;
    int tx = threadIdx.x, ty = threadIdx.y;
    #pragma unroll
    for (int i = 0; i < 32; i += 8)
        tile[ty + i][tx] = w[(size_t)(rb + ty + i) * MODESN + cb + tx];
    __syncthreads();
    #pragma unroll
    for (int i = 0; i < 32; i += 8)
        wt[(size_t)(cb + ty + i) * (DD * DD) + rb + tx] = tile[tx][ty + i];
}

// ---------------------------------------------------------------------------
// Stage A (R9-PROVEN, unchanged): fused tf32 mma, K-split grid (dt4, b32, ks2)
// ---------------------------------------------------------------------------
#define QS_STRIDE 132
#define SMEM_A_BYTES (2 * TILE_BYTES + 64 * QS_STRIDE * 4)   // 103424
__global__ void __launch_bounds__(256, 2) stageA_tf32(const float* __restrict__ q) {
    extern __shared__ __align__(16) unsigned char smem[];
    uint32_t sb = smem_u32(smem);
    float* qs = (float*)(smem + 2 * TILE_BYTES);
    int tid = threadIdx.x;
    int lane = tid & 31, warp = tid >> 5;
    int wm = warp & 3, wn = warp >> 2;
    int dt = blockIdx.x, b = blockIdx.y, ks = blockIdx.z;

    float acc[2][8][4];
    #pragma unroll
    for (int mt = 0; mt < 2; mt++)
        #pragma unroll
        for (int nt = 0; nt < 8; nt++)
            #pragma unroll
            for (int i = 0; i < 4; i++) acc[mt][nt][i] = 0.0f;

    uint4* dA = (uint4*)smem;
    const int dl   = tid & 127;
    const int half = tid >> 7;

    for (int ic0 = 0; ic0 < 32; ic0++) {
        int ic = ks * 32 + ic0;
        const uint4* sA = (const uint4*)&g_A[(size_t)ic * TWORDS];
        #pragma unroll
        for (int i = 0; i < 9; i++) {
            int idx = tid + i * 256;
            if (idx < TILE_U4) dA[idx] = sA[idx];
        }
        const float* qsrc = q + ((size_t)b * LL + (size_t)ic * 64) * DD + dt * 128;
        #pragma unroll
        for (int i = 0; i < 8; i++) {
            int idx = tid + i * 256;
            int r  = idx >> 5;
            int c4 = idx & 31;
            float4 v = *(const float4*)(qsrc + (size_t)r * DD + c4 * 4);
            *(float4*)&qs[r * QS_STRIDE + c4 * 4] = v;
        }
        __syncthreads();
        #pragma unroll
        for (int g2 = 0; g2 < 8; g2++) {
            uint32_t w[4];
            #pragma unroll
            for (int u = 0; u < 4; u++) {
                int kk = half * 32 + g2 * 4 + u;
                w[u] = tf32r(qs[kk * QS_STRIDE + dl]);
            }
            *(uint4*)(smem + TILE_BYTES + ((uint32_t)dl * TPW + half * 32 + g2 * 4) * 4) =
                make_uint4(w[0], w[1], w[2], w[3]);
        }
        __syncthreads();
        gemm_tf32(sb, sb + TILE_BYTES, lane, wm, wn, acc);
        __syncthreads();
    }

    float* Xo = (ks == 0) ? g_X : g_X2;
    int tg = lane >> 2, tig = lane & 3;
    #pragma unroll
    for (int mt = 0; mt < 2; mt++) {
        int j0 = wm * 32 + mt * 16;
        #pragma unroll
        for (int nt = 0; nt < 8; nt++) {
            int dcol = dt * 128 + wn * 64 + nt * 8 + tig * 2;
            float* p0 = Xo + ((size_t)b * JJ + j0 + tg) * DD + dcol;
            float* p1 = Xo + ((size_t)b * JJ + j0 + tg + 8) * DD + dcol;
            *(float2*)p0 = make_float2(acc[mt][nt][0], acc[mt][nt][1]);
            *(float2*)p1 = make_float2(acc[mt][nt][2], acc[mt][nt][3]);
        }
    }
}

// ---------------------------------------------------------------------------
// Stage B (NEW, tf32 mma): per mode m, e-block 64:
//   Yr[b 32][e 64] = Xr.Wr - Xi.Wi ; Yi = Xr.Wi + Xi.Wr   (K = d = 512)
// grid (eb 8, m 64), 128 threads (4 warps): warps 0-1 -> Yr, 2-3 -> Yi.
// W tiles [d 64][e 64] staged via padded smem (stride 65) then transposed+cvt
// into B tiles [e][d(+4)]; X tiles loaded direct (sum partials + cvt).
// Subtraction: R-warps negate the Xi fragments (tf32 sign bit = bit 31).
// SMEM: S @0 (16640 B), Ar @16640, Ai @25344, Br @34048, Bi @51456. Tot 68864.
// ---------------------------------------------------------------------------
#define SBT_AR  16640
#define SBT_AI  25344
#define SBT_BR  34048
#define SBT_BI  51456
#define SMEM_B_BYTES 68864
__global__ void __launch_bounds__(128, 3) stageBt_tf32() {
    extern __shared__ __align__(16) unsigned char smem[];
    uint32_t sb = smem_u32(smem);
    float* Sf = (float*)smem;
    uint32_t* BwR = (uint32_t*)(smem + SBT_BR);
    uint32_t* BwI = (uint32_t*)(smem + SBT_BI);
    uint32_t* AwR = (uint32_t*)(smem + SBT_AR);
    uint32_t* AwI = (uint32_t*)(smem + SBT_AI);
    int tid = threadIdx.x;
    int lane = tid & 31, warp = tid >> 5;
    int outI = warp >> 1;          // 0 = Yr, 1 = Yi
    int nh   = warp & 1;           // n half: cols nh*32..+31
    int m  = blockIdx.y;
    int eb = blockIdx.x;

    const float* Wr = g_WTr + (size_t)m * DD * DD + eb * 64;
    const float* Wi = g_WTi + (size_t)m * DD * DD + eb * 64;

    float acc[2][4][4];
    #pragma unroll
    for (int mt = 0; mt < 2; mt++)
        #pragma unroll
        for (int nt = 0; nt < 4; nt++)
            #pragma unroll
            for (int i = 0; i < 4; i++) acc[mt][nt][i] = 0.0f;

    const int td = tid & 63, teh = tid >> 6;

    for (int kc8 = 0; kc8 < 8; kc8++) {
        int kd = kc8 * 64;
        // 1) Wr chunk [64 d][64 e] -> S (coalesced; S stride 65 conflict-free)
        #pragma unroll
        for (int i = 0; i < 32; i++) {
            int idx = tid + i * 128;
            int r = idx >> 6, c = idx & 63;
            Sf[r * 65 + c] = Wr[(size_t)(kd + r) * DD + c];
        }
        __syncthreads();
        // 2) transpose + cvt -> Br tile [e][d(+4)]
        #pragma unroll
        for (int i = 0; i < 32; i++) {
            int e = teh * 32 + i;
            BwR[e * TPW + td] = tf32r(Sf[td * 65 + e]);
        }
        __syncthreads();
        // 3) Wi chunk -> S
        #pragma unroll
        for (int i = 0; i < 32; i++) {
            int idx = tid + i * 128;
            int r = idx >> 6, c = idx & 63;
            Sf[r * 65 + c] = Wi[(size_t)(kd + r) * DD + c];
        }
        __syncthreads();
        // 4) transpose Wi -> Bi; X chunks -> A tiles (sum partials + cvt)
        #pragma unroll
        for (int i = 0; i < 32; i++) {
            int e = teh * 32 + i;
            BwI[e * TPW + td] = tf32r(Sf[td * 65 + e]);
        }
        #pragma unroll
        for (int i = 0; i < 16; i++) {
            int idx = tid + i * 128;
            int bb = idx >> 6, c = idx & 63;
            size_t xr = ((size_t)bb * JJ + m) * DD + kd + c;
            size_t xi = ((size_t)bb * JJ + MODESN + m) * DD + kd + c;
            AwR[bb * TPW + c] = tf32r(g_X[xr] + g_X2[xr]);
            AwI[bb * TPW + c] = tf32r(g_X[xi] + g_X2[xi]);
        }
        __syncthreads();
        // 5) mma over 8 k8 steps
        const uint32_t g  = (uint32_t)(lane >> 2);
        const uint32_t t4 = (uint32_t)(lane & 3);
        #pragma unroll
        for (int k8 = 0; k8 < 8; k8++) {
            uint32_t kw = (uint32_t)k8 * 8u + t4;
            uint32_t ar[2][4], ai[2][4];
            #pragma unroll
            for (int mt = 0; mt < 2; mt++) {
                uint32_t r0 = (uint32_t)(mt * 16) + g;
                ar[mt][0] = lds32(sb + SBT_AR + (r0 * TPW + kw) * 4u);
                ar[mt][1] = lds32(sb + SBT_AR + ((r0 + 8) * TPW + kw) * 4u);
                ar[mt][2] = lds32(sb + SBT_AR + (r0 * TPW + kw + 4) * 4u);
                ar[mt][3] = lds32(sb + SBT_AR + ((r0 + 8) * TPW + kw + 4) * 4u);
                ai[mt][0] = lds32(sb + SBT_AI + (r0 * TPW + kw) * 4u);
                ai[mt][1] = lds32(sb + SBT_AI + ((r0 + 8) * TPW + kw) * 4u);
                ai[mt][2] = lds32(sb + SBT_AI + (r0 * TPW + kw + 4) * 4u);
                ai[mt][3] = lds32(sb + SBT_AI + ((r0 + 8) * TPW + kw + 4) * 4u);
                if (outI == 0) {   // Yr needs -Xi.Wi: negate Xi fragments
                    #pragma unroll
                    for (int j = 0; j < 4; j++) ai[mt][j] ^= 0x80000000u;
                }
            }
            #pragma unroll
            for (int nt = 0; nt < 4; nt++) {
                uint32_t nr = (uint32_t)(nh * 32 + nt * 8) + g;
                uint32_t br0 = lds32(sb + SBT_BR + (nr * TPW + kw) * 4u);
                uint32_t br1 = lds32(sb + SBT_BR + (nr * TPW + kw + 4) * 4u);
                uint32_t bi0 = lds32(sb + SBT_BI + (nr * TPW + kw) * 4u);
                uint32_t bi1 = lds32(sb + SBT_BI + (nr * TPW + kw + 4) * 4u);
                if (outI == 0) {
                    mma_tf32(acc[0][nt], ar[0], br0, br1);
                    mma_tf32(acc[0][nt], ai[0], bi0, bi1);
                    mma_tf32(acc[1][nt], ar[1], br0, br1);
                    mma_tf32(acc[1][nt], ai[1], bi0, bi1);
                } else {
                    mma_tf32(acc[0][nt], ar[0], bi0, bi1);
                    mma_tf32(acc[0][nt], ai[0], br0, br1);
                    mma_tf32(acc[1][nt], ar[1], bi0, bi1);
                    mma_tf32(acc[1][nt], ai[1], br0, br1);
                }
            }
        }
        __syncthreads();
    }

    // Epilogue: tf32 Y^T tiles [b][et][kc=outI]: word (e_local row, m col)
    int tg = lane >> 2, tig = lane & 3;
    #pragma unroll
    for (int mt = 0; mt < 2; mt++) {
        #pragma unroll
        for (int nt = 0; nt < 4; nt++) {
            int e0c = eb * 64 + nh * 32 + nt * 8 + tig * 2;
            int b0 = mt * 16 + tg;
            #pragma unroll
            for (int o = 0; o < 2; o++) {
                int e = e0c + o;
                int et = e >> 7, el = e & 127;
                size_t w0 = (((size_t)b0 * 4 + et) * 2 + outI) * TWORDS
                          + (size_t)el * TPW + m;
                size_t w1 = (((size_t)(b0 + 8) * 4 + et) * 2 + outI) * TWORDS
                          + (size_t)el * TPW + m;
                g_yt[w0] = tf32r(acc[mt][nt][o]);
                g_yt[w1] = tf32r(acc[mt][nt][2 + o]);
            }
        }
    }
}

// ---------------------------------------------------------------------------
// Stage C (R9-PROVEN, unchanged): out[b][l 128][e 128] = F @ Y_b, K=128
// ---------------------------------------------------------------------------
#define SMEM_C_BYTES (2 * TILE_BYTES)   // 69632
__global__ void __launch_bounds__(256, 2) stageC_tf32(float* __restrict__ out) {
    extern __shared__ __align__(16) unsigned char smem[];
    uint32_t sb = smem_u32(smem);
    int tid = threadIdx.x;
    int lane = tid & 31, warp = tid >> 5;
    int wm = warp & 3, wn = warp >> 2;
    int et = blockIdx.x, lt = blockIdx.y, b = blockIdx.z;

    float acc[2][8][4];
    #pragma unroll
    for (int mt = 0; mt < 2; mt++)
        #pragma unroll
        for (int nt = 0; nt < 8; nt++)
            #pragma unroll
            for (int i = 0; i < 4; i++) acc[mt][nt][i] = 0.0f;

    uint4* dA = (uint4*)smem;
    uint4* dB = (uint4*)(smem + TILE_BYTES);

    #pragma unroll
    for (int kc = 0; kc < 2; kc++) {
        const uint4* sA = (const uint4*)&g_F[(size_t)(lt * 2 + kc) * TWORDS];
        const uint4* sB = (const uint4*)&g_yt[(((size_t)b * 4 + et) * 2 + kc) * TWORDS];
        #pragma unroll
        for (int i = 0; i < 9; i++) {
            int idx = tid + i * 256;
            if (idx < TILE_U4) {
                dA[idx] = sA[idx];
                dB[idx] = sB[idx];
            }
        }
        __syncthreads();
        gemm_tf32(sb, sb + TILE_BYTES, lane, wm, wn, acc);
        __syncthreads();
    }

    int tg = lane >> 2, tig = lane & 3;
    #pragma unroll
    for (int mt = 0; mt < 2; mt++) {
        int l0 = lt * 128 + wm * 32 + mt * 16;
        #pragma unroll
        for (int nt = 0; nt < 8; nt++) {
            int ecol = et * 128 + wn * 64 + nt * 8 + tig * 2;
            float* p0 = out + ((size_t)b * LL + l0 + tg) * DD + ecol;
            float* p1 = out + ((size_t)b * LL + l0 + tg + 8) * DD + ecol;
            *(float2*)p0 = make_float2(acc[mt][nt][0], acc[mt][nt][1]);
            *(float2*)p1 = make_float2(acc[mt][nt][2], acc[mt][nt][3]);
        }
    }
}

// ---------------------------------------------------------------------------
// launch
// ---------------------------------------------------------------------------
extern "C" void kernel_launch(void* const* d_in, const int* in_sizes, int n_in,
                              void* d_out, int out_size) {
    const float* q  = (const float*)d_in[0];
    const float* wr = (const float*)d_in[1];
    const float* wi = (const float*)d_in[2];
    float* out = (float*)d_out;

    // Idempotent, every invocation (no static guards — harness rule)
    cudaFuncSetAttribute(stageA_tf32, cudaFuncAttributeMaxDynamicSharedMemorySize, SMEM_A_BYTES);
    cudaFuncSetAttribute(stageBt_tf32, cudaFuncAttributeMaxDynamicSharedMemorySize, SMEM_B_BYTES);
    cudaFuncSetAttribute(stageC_tf32, cudaFuncAttributeMaxDynamicSharedMemorySize, SMEM_C_BYTES);

    build_basisA_tf32<<<512, 256>>>();
    build_basisF_tf32<<<512, 256>>>();

    dim3 tgrid((DD * DD) / 32, MODESN / 32);
    transpose_w<<<tgrid, dim3(32, 8)>>>(wr, 0);
    transpose_w<<<tgrid, dim3(32, 8)>>>(wi, 1);

    stageA_tf32<<<dim3(4, NB, 2), 256, SMEM_A_BYTES>>>(q);
    stageBt_tf32<<<dim3(8, MODESN), 128, SMEM_B_BYTES>>>();
    stageC_tf32<<<dim3(4, 32, NB), 256, SMEM_C_BYTES>>>(out);
}

// round 12
// speedup vs baseline: 2.5231x; 1.0308x over previous
#include <cuda_runtime.h>
#include <cuda_bf16.h>
#include <cstdint>

// Problem constants
#define LL     4096
#define DD     512
#define MODESN 64
#define JJ     128   // 2*MODES (Re rows then Im rows)
#define NB     32    // batch

// tf32 tile geometry: [row][word 64 data + 4 pad] fp32 words
#define TPW     68
#define TWORDS  (128 * TPW)        // 8704 words = 34816 bytes per 128-row tile
#define TILE_BYTES (TWORDS * 4)
#define TILE_U4 (TWORDS / 4)       // 2176 uint4 per 128-row tile
#define WTW     (64 * TPW)         // 4352 words per 64-row W tile
#define WT_U4   (WTW / 4)          // 1088 uint4

// ---------------------------------------------------------------------------
// Static device scratch (no allocation allowed)
// ---------------------------------------------------------------------------
// Stage A basis tiles: [kc 64] of [j 128][kk 64(+4)] tf32 words
__device__ __align__(16) uint32_t g_A[64 * TWORDS];
// Stage C basis tiles: [lt 32][kc 2] of [l 128][j 64(+4)]
__device__ __align__(16) uint32_t g_F[64 * TWORDS];
// Y^T tiles for stage C: [b 32][et 4][kc 2] of [e_local 128][m 64(+4)]
__device__ __align__(16) uint32_t g_yt[256 * TWORDS];
// W^T tf32 tiles: [ri 2][m 64][eb 8][kc8 8] of [e 64][d 64(+4)]  (142.6 MB)
__device__ __align__(16) uint32_t g_Wt[(size_t)2 * 64 * 64 * WTW];
// Stage A partial outputs fp32 [b][j][d] (K-split halves)
__device__ float g_X [NB * JJ * DD];
__device__ float g_X2[NB * JJ * DD];

// ---------------------------------------------------------------------------
// Helpers
// ---------------------------------------------------------------------------
__device__ __forceinline__ uint32_t smem_u32(const void* p) {
    uint32_t a;
    asm("{ .reg .u64 t; cvta.to.shared.u64 t, %1; cvt.u32.u64 %0, t; }"
        : "=r"(a) : "l"(p));
    return a;
}

__device__ __forceinline__ uint32_t lds32(uint32_t a) {
    uint32_t v;
    asm volatile("ld.shared.b32 %0, [%1];" : "=r"(v) : "r"(a));
    return v;
}

// fp32 -> tf32 (round to nearest)
__device__ __forceinline__ uint32_t tf32r(float v) {
    uint32_t r;
    asm("cvt.rna.tf32.f32 %0, %1;" : "=r"(r) : "f"(v));
    return r;
}

__device__ __forceinline__ void cp16(uint32_t saddr, const void* g) {
    asm volatile("cp.async.cg.shared.global [%0], [%1], 16;" :: "r"(saddr), "l"(g));
}
#define CP_COMMIT() asm volatile("cp.async.commit_group;" ::: "memory")
#define CP_WAIT0()  asm volatile("cp.async.wait_group 0;" ::: "memory")

__device__ __forceinline__ void mma_tf32(float* c, const uint32_t* a,
                                         uint32_t b0, uint32_t b1) {
    asm volatile(
        "mma.sync.aligned.m16n8k8.row.col.f32.tf32.tf32.f32 "
        "{%0,%1,%2,%3}, {%4,%5,%6,%7}, {%8,%9}, {%0,%1,%2,%3};"
        : "+f"(c[0]), "+f"(c[1]), "+f"(c[2]), "+f"(c[3])
        : "r"(a[0]), "r"(a[1]), "r"(a[2]), "r"(a[3]), "r"(b0), "r"(b1));
}

// ---------------------------------------------------------------------------
// tf32 chunk compute (R9-PROVEN): CTA tile 128(M) x 128(N), chunk K=64.
// ---------------------------------------------------------------------------
__device__ __forceinline__ void gemm_tf32(uint32_t baseA, uint32_t baseB,
                                          int lane, int wm, int wn,
                                          float acc[2][8][4]) {
    const uint32_t g  = (uint32_t)(lane >> 2);
    const uint32_t t4 = (uint32_t)(lane & 3);
    #pragma unroll
    for (int k8 = 0; k8 < 8; k8++) {
        const uint32_t kw = (uint32_t)k8 * 8u + t4;
        uint32_t a[2][4];
        #pragma unroll
        for (int mt = 0; mt < 2; mt++) {
            uint32_t r0 = (uint32_t)(wm * 32 + mt * 16) + g;
            a[mt][0] = lds32(baseA + (r0 * TPW + kw) * 4u);
            a[mt][1] = lds32(baseA + ((r0 + 8) * TPW + kw) * 4u);
            a[mt][2] = lds32(baseA + (r0 * TPW + kw + 4) * 4u);
            a[mt][3] = lds32(baseA + ((r0 + 8) * TPW + kw + 4) * 4u);
        }
        #pragma unroll
        for (int nt = 0; nt < 8; nt++) {
            uint32_t nr = (uint32_t)(wn * 64 + nt * 8) + g;
            uint32_t b0 = lds32(baseB + (nr * TPW + kw) * 4u);
            uint32_t b1 = lds32(baseB + (nr * TPW + kw + 4) * 4u);
            mma_tf32(acc[0][nt], a[0], b0, b1);
            mma_tf32(acc[1][nt], a[1], b0, b1);
        }
    }
}

// ---------------------------------------------------------------------------
// Basis builders (R9-proven)
// ---------------------------------------------------------------------------
__global__ void build_basisA_tf32() {
    int t = blockIdx.x * blockDim.x + threadIdx.x;
    int kc = t >> 11;
    int j  = (t >> 4) & 127;
    int oc = t & 15;
    uint32_t w[4];
    #pragma unroll
    for (int u = 0; u < 4; u++) {
        int l = kc * 64 + oc * 4 + u;
        int m = j & 63;
        int phi = (m * l) & (LL - 1);
        float s, c;
        sincospif(2.0f * (float)phi / (float)LL, &s, &c);
        w[u] = tf32r((j < MODESN) ? c : -s);
    }
    *(uint4*)&g_A[(size_t)kc * TWORDS + j * TPW + oc * 4] =
        make_uint4(w[0], w[1], w[2], w[3]);
}

__global__ void build_basisF_tf32() {
    int t = blockIdx.x * blockDim.x + threadIdx.x;
    int tile = t >> 11;
    int lt = tile >> 1;
    int kc = tile & 1;
    int lr = (t >> 4) & 127;
    int oc = t & 15;
    int l = lt * 128 + lr;
    uint32_t w[4];
    #pragma unroll
    for (int u = 0; u < 4; u++) {
        int j = kc * 64 + oc * 4 + u;
        int m = j & 63;
        int phi = (m * l) & (LL - 1);
        float s, c;
        sincospif(2.0f * (float)phi / (float)LL, &s, &c);
        float v;
        if (j < MODESN) v = ((m == 0) ? 1.0f : 2.0f) * (1.0f / (float)LL) * c;
        else            v = (-2.0f / (float)LL) * s;
        w[u] = tf32r(v);
    }
    *(uint4*)&g_F[(size_t)tile * TWORDS + lr * TPW + oc * 4] =
        make_uint4(w[0], w[1], w[2], w[3]);
}

// ---------------------------------------------------------------------------
// Weight transpose -> B-ready tf32 tiles.
// Input w[d][e][m] (flattened (d*D+e)*MODES+m). Output per mode m:
// tile(ri, m, eb=e>>6, kc8=d>>6)[e&63 row][d&63 word] = W[d][e].
// Block (e, kc8): stages [d 64][m 64] in smem (read coalesced along m),
// writes 256B-contiguous rows per mode (no write amplification).
// ---------------------------------------------------------------------------
__global__ void __launch_bounds__(128) transpose_w_tiles(const float* __restrict__ w,
                                                         int which) {
    __shared__ float Sf[64 * 65];
    int e   = blockIdx.x;       // 0..511
    int kc8 = blockIdx.y;       // 0..7
    int d0  = kc8 * 64;
    int tid = threadIdx.x;
    // load [d 64][m 64], coalesced 64-float rows
    #pragma unroll
    for (int i = 0; i < 32; i++) {
        int idx = tid + i * 128;
        int dd = idx >> 6, mm = idx & 63;
        Sf[dd * 65 + mm] = w[((size_t)(d0 + dd) * DD + e) * MODESN + mm];
    }
    __syncthreads();
    // write: thread (m = tid>>1, half = tid&1) -> 128B contiguous per thread
    int m = tid >> 1, half = tid & 1;
    int eb = e >> 6, el = e & 63;
    uint32_t* dst = g_Wt
        + ((size_t)((which * 64 + m) * 64) + eb * 8 + kc8) * WTW
        + (size_t)el * TPW + half * 32;
    #pragma unroll
    for (int u8 = 0; u8 < 8; u8++) {
        uint32_t wv[4];
        #pragma unroll
        for (int u = 0; u < 4; u++) {
            int dd = half * 32 + u8 * 4 + u;
            wv[u] = tf32r(Sf[dd * 65 + m]);
        }
        *(uint4*)(dst + u8 * 4) = make_uint4(wv[0], wv[1], wv[2], wv[3]);
    }
}

// ---------------------------------------------------------------------------
// Stage A (tf32 mma + cp.async q prefetch): K-split grid (dt4, b32, ks2)
// SMEM: A tile @0, B tile @TILE_BYTES, q staging fp32 @2*TILE_BYTES (64x132)
// ---------------------------------------------------------------------------
#define QS_STRIDE 132
#define SMEM_A_BYTES (2 * TILE_BYTES + 64 * QS_STRIDE * 4)   // 103424
__global__ void __launch_bounds__(256, 2) stageA_tf32(const float* __restrict__ q) {
    extern __shared__ __align__(16) unsigned char smem[];
    uint32_t sb = smem_u32(smem);
    uint32_t qsb = sb + 2 * TILE_BYTES;
    float* qs = (float*)(smem + 2 * TILE_BYTES);
    int tid = threadIdx.x;
    int lane = tid & 31, warp = tid >> 5;
    int wm = warp & 3, wn = warp >> 2;
    int dt = blockIdx.x, b = blockIdx.y, ks = blockIdx.z;

    float acc[2][8][4];
    #pragma unroll
    for (int mt = 0; mt < 2; mt++)
        #pragma unroll
        for (int nt = 0; nt < 8; nt++)
            #pragma unroll
            for (int i = 0; i < 4; i++) acc[mt][nt][i] = 0.0f;

    uint4* dA = (uint4*)smem;
    const int dl   = tid & 127;
    const int half = tid >> 7;

    auto issue_q = [&](int ic) {
        const float* qsrc = q + ((size_t)b * LL + (size_t)ic * 64) * DD + dt * 128;
        #pragma unroll
        for (int i = 0; i < 8; i++) {
            int idx = tid + i * 256;
            int r  = idx >> 5;
            int c4 = idx & 31;
            cp16(qsb + (uint32_t)(r * QS_STRIDE + c4 * 4) * 4u,
                 qsrc + (size_t)r * DD + c4 * 4);
        }
        CP_COMMIT();
    };

    issue_q(ks * 32);

    for (int ic0 = 0; ic0 < 32; ic0++) {
        int ic = ks * 32 + ic0;
        // basis tile global -> smem (L2-resident)
        const uint4* sA = (const uint4*)&g_A[(size_t)ic * TWORDS];
        #pragma unroll
        for (int i = 0; i < 9; i++) {
            int idx = tid + i * 256;
            if (idx < TILE_U4) dA[idx] = sA[idx];
        }
        CP_WAIT0();
        __syncthreads();
        // transpose q staging + tf32 cvt into B tile
        #pragma unroll
        for (int g2 = 0; g2 < 8; g2++) {
            uint32_t w[4];
            #pragma unroll
            for (int u = 0; u < 4; u++) {
                int kk = half * 32 + g2 * 4 + u;
                w[u] = tf32r(qs[kk * QS_STRIDE + dl]);
            }
            *(uint4*)(smem + TILE_BYTES + ((uint32_t)dl * TPW + half * 32 + g2 * 4) * 4) =
                make_uint4(w[0], w[1], w[2], w[3]);
        }
        __syncthreads();
        // prefetch next q chunk, overlapped with gemm
        if (ic0 < 31) issue_q(ic + 1);
        gemm_tf32(sb, sb + TILE_BYTES, lane, wm, wn, acc);
        __syncthreads();
    }

    float* Xo = (ks == 0) ? g_X : g_X2;
    int tg = lane >> 2, tig = lane & 3;
    #pragma unroll
    for (int mt = 0; mt < 2; mt++) {
        int j0 = wm * 32 + mt * 16;
        #pragma unroll
        for (int nt = 0; nt < 8; nt++) {
            int dcol = dt * 128 + wn * 64 + nt * 8 + tig * 2;
            float* p0 = Xo + ((size_t)b * JJ + j0 + tg) * DD + dcol;
            float* p1 = Xo + ((size_t)b * JJ + j0 + tg + 8) * DD + dcol;
            *(float2*)p0 = make_float2(acc[mt][nt][0], acc[mt][nt][1]);
            *(float2*)p1 = make_float2(acc[mt][nt][2], acc[mt][nt][3]);
        }
    }
}

// ---------------------------------------------------------------------------
// Stage B (tf32 mma, 2-phase): per mode m, e-block 64:
//   Yr[b 32][e 64] = Xr.Wr - Xi.Wi ; Yi = Xr.Wi + Xi.Wr   (K = d = 512)
// grid (eb 8, m 64), 128 threads: warps 0-1 -> Yr, 2-3 -> Yi.
// W tiles are pre-transposed tf32 (g_Wt) -> pure uint4 copies.
// SMEM: Ar @0 (8704), Ai @8704, Br @17408 (17408), Bi @34816. Total 52224.
// ---------------------------------------------------------------------------
#define SB2_AI  8704
#define SB2_BR  17408
#define SB2_BI  34816
#define SMEM_B_BYTES 52224
__global__ void __launch_bounds__(128, 4) stageBt_tf32() {
    extern __shared__ __align__(16) unsigned char smem[];
    uint32_t sb = smem_u32(smem);
    uint32_t* AwR = (uint32_t*)smem;
    uint32_t* AwI = (uint32_t*)(smem + SB2_AI);
    uint4* dBr = (uint4*)(smem + SB2_BR);
    uint4* dBi = (uint4*)(smem + SB2_BI);
    int tid = threadIdx.x;
    int lane = tid & 31, warp = tid >> 5;
    int outI = warp >> 1;          // 0 = Yr, 1 = Yi
    int nh   = warp & 1;           // n half: e cols nh*32..+31
    int m  = blockIdx.y;
    int eb = blockIdx.x;

    float acc[2][4][4];
    #pragma unroll
    for (int mt = 0; mt < 2; mt++)
        #pragma unroll
        for (int nt = 0; nt < 4; nt++)
            #pragma unroll
            for (int i = 0; i < 4; i++) acc[mt][nt][i] = 0.0f;

    for (int kc8 = 0; kc8 < 8; kc8++) {
        int kd = kc8 * 64;
        // 1) copy W tiles (pre-transposed tf32) + build X tiles
        const uint4* sBr = (const uint4*)&g_Wt[((size_t)m * 64 + eb * 8 + kc8) * WTW];
        const uint4* sBi = (const uint4*)&g_Wt[((size_t)(64 + m) * 64 + eb * 8 + kc8) * WTW];
        #pragma unroll
        for (int i = 0; i < 9; i++) {
            int idx = tid + i * 128;
            if (idx < WT_U4) {
                dBr[idx] = sBr[idx];
                dBi[idx] = sBi[idx];
            }
        }
        #pragma unroll
        for (int i = 0; i < 16; i++) {
            int idx = tid + i * 128;
            int bb = idx >> 6, c = idx & 63;
            size_t xr = ((size_t)bb * JJ + m) * DD + kd + c;
            size_t xi = ((size_t)bb * JJ + MODESN + m) * DD + kd + c;
            AwR[bb * TPW + c] = tf32r(g_X[xr] + g_X2[xr]);
            AwI[bb * TPW + c] = tf32r(g_X[xi] + g_X2[xi]);
        }
        __syncthreads();
        // 2) mma over 8 k8 steps
        const uint32_t g  = (uint32_t)(lane >> 2);
        const uint32_t t4 = (uint32_t)(lane & 3);
        #pragma unroll
        for (int k8 = 0; k8 < 8; k8++) {
            uint32_t kw = (uint32_t)k8 * 8u + t4;
            uint32_t ar[2][4], ai[2][4];
            #pragma unroll
            for (int mt = 0; mt < 2; mt++) {
                uint32_t r0 = (uint32_t)(mt * 16) + g;
                ar[mt][0] = lds32(sb + (r0 * TPW + kw) * 4u);
                ar[mt][1] = lds32(sb + ((r0 + 8) * TPW + kw) * 4u);
                ar[mt][2] = lds32(sb + (r0 * TPW + kw + 4) * 4u);
                ar[mt][3] = lds32(sb + ((r0 + 8) * TPW + kw + 4) * 4u);
                ai[mt][0] = lds32(sb + SB2_AI + (r0 * TPW + kw) * 4u);
                ai[mt][1] = lds32(sb + SB2_AI + ((r0 + 8) * TPW + kw) * 4u);
                ai[mt][2] = lds32(sb + SB2_AI + (r0 * TPW + kw + 4) * 4u);
                ai[mt][3] = lds32(sb + SB2_AI + ((r0 + 8) * TPW + kw + 4) * 4u);
                if (outI == 0) {   // Yr needs -Xi.Wi: negate Xi fragments
                    #pragma unroll
                    for (int j = 0; j < 4; j++) ai[mt][j] ^= 0x80000000u;
                }
            }
            #pragma unroll
            for (int nt = 0; nt < 4; nt++) {
                uint32_t nr = (uint32_t)(nh * 32 + nt * 8) + g;
                uint32_t br0 = lds32(sb + SB2_BR + (nr * TPW + kw) * 4u);
                uint32_t br1 = lds32(sb + SB2_BR + (nr * TPW + kw + 4) * 4u);
                uint32_t bi0 = lds32(sb + SB2_BI + (nr * TPW + kw) * 4u);
                uint32_t bi1 = lds32(sb + SB2_BI + (nr * TPW + kw + 4) * 4u);
                if (outI == 0) {
                    mma_tf32(acc[0][nt], ar[0], br0, br1);
                    mma_tf32(acc[0][nt], ai[0], bi0, bi1);
                    mma_tf32(acc[1][nt], ar[1], br0, br1);
                    mma_tf32(acc[1][nt], ai[1], bi0, bi1);
                } else {
                    mma_tf32(acc[0][nt], ar[0], bi0, bi1);
                    mma_tf32(acc[0][nt], ai[0], br0, br1);
                    mma_tf32(acc[1][nt], ar[1], bi0, bi1);
                    mma_tf32(acc[1][nt], ai[1], br0, br1);
                }
            }
        }
        __syncthreads();
    }

    // Epilogue: tf32 Y^T tiles [b][et][kc=outI]: word (e_local row, m col)
    int tg = lane >> 2, tig = lane & 3;
    #pragma unroll
    for (int mt = 0; mt < 2; mt++) {
        #pragma unroll
        for (int nt = 0; nt < 4; nt++) {
            int e0c = eb * 64 + nh * 32 + nt * 8 + tig * 2;
            int b0 = mt * 16 + tg;
            #pragma unroll
            for (int o = 0; o < 2; o++) {
                int e = e0c + o;
                int et = e >> 7, el = e & 127;
                size_t w0 = (((size_t)b0 * 4 + et) * 2 + outI) * TWORDS
                          + (size_t)el * TPW + m;
                size_t w1 = (((size_t)(b0 + 8) * 4 + et) * 2 + outI) * TWORDS
                          + (size_t)el * TPW + m;
                g_yt[w0] = tf32r(acc[mt][nt][o]);
                g_yt[w1] = tf32r(acc[mt][nt][2 + o]);
            }
        }
    }
}

// ---------------------------------------------------------------------------
// Stage C (R9-PROVEN, unchanged): out[b][l 128][e 128] = F @ Y_b, K=128
// ---------------------------------------------------------------------------
#define SMEM_C_BYTES (2 * TILE_BYTES)   // 69632
__global__ void __launch_bounds__(256, 2) stageC_tf32(float* __restrict__ out) {
    extern __shared__ __align__(16) unsigned char smem[];
    uint32_t sb = smem_u32(smem);
    int tid = threadIdx.x;
    int lane = tid & 31, warp = tid >> 5;
    int wm = warp & 3, wn = warp >> 2;
    int et = blockIdx.x, lt = blockIdx.y, b = blockIdx.z;

    float acc[2][8][4];
    #pragma unroll
    for (int mt = 0; mt < 2; mt++)
        #pragma unroll
        for (int nt = 0; nt < 8; nt++)
            #pragma unroll
            for (int i = 0; i < 4; i++) acc[mt][nt][i] = 0.0f;

    uint4* dA = (uint4*)smem;
    uint4* dB = (uint4*)(smem + TILE_BYTES);

    #pragma unroll
    for (int kc = 0; kc < 2; kc++) {
        const uint4* sA = (const uint4*)&g_F[(size_t)(lt * 2 + kc) * TWORDS];
        const uint4* sB = (const uint4*)&g_yt[(((size_t)b * 4 + et) * 2 + kc) * TWORDS];
        #pragma unroll
        for (int i = 0; i < 9; i++) {
            int idx = tid + i * 256;
            if (idx < TILE_U4) {
                dA[idx] = sA[idx];
                dB[idx] = sB[idx];
            }
        }
        __syncthreads();
        gemm_tf32(sb, sb + TILE_BYTES, lane, wm, wn, acc);
        __syncthreads();
    }

    int tg = lane >> 2, tig = lane & 3;
    #pragma unroll
    for (int mt = 0; mt < 2; mt++) {
        int l0 = lt * 128 + wm * 32 + mt * 16;
        #pragma unroll
        for (int nt = 0; nt < 8; nt++) {
            int ecol = et * 128 + wn * 64 + nt * 8 + tig * 2;
            float* p0 = out + ((size_t)b * LL + l0 + tg) * DD + ecol;
            float* p1 = out + ((size_t)b * LL + l0 + tg + 8) * DD + ecol;
            *(float2*)p0 = make_float2(acc[mt][nt][0], acc[mt][nt][1]);
            *(float2*)p1 = make_float2(acc[mt][nt][2], acc[mt][nt][3]);
        }
    }
}

// ---------------------------------------------------------------------------
// launch
// ---------------------------------------------------------------------------
extern "C" void kernel_launch(void* const* d_in, const int* in_sizes, int n_in,
                              void* d_out, int out_size) {
    const float* q  = (const float*)d_in[0];
    const float* wr = (const float*)d_in[1];
    const float* wi = (const float*)d_in[2];
    float* out = (float*)d_out;

    // Idempotent, every invocation (no static guards — harness rule)
    cudaFuncSetAttribute(stageA_tf32, cudaFuncAttributeMaxDynamicSharedMemorySize, SMEM_A_BYTES);
    cudaFuncSetAttribute(stageBt_tf32, cudaFuncAttributeMaxDynamicSharedMemorySize, SMEM_B_BYTES);
    cudaFuncSetAttribute(stageC_tf32, cudaFuncAttributeMaxDynamicSharedMemorySize, SMEM_C_BYTES);

    build_basisA_tf32<<<512, 256>>>();
    build_basisF_tf32<<<512, 256>>>();

    transpose_w_tiles<<<dim3(512, 8), 128>>>(wr, 0);
    transpose_w_tiles<<<dim3(512, 8), 128>>>(wi, 1);

    stageA_tf32<<<dim3(4, NB, 2), 256, SMEM_A_BYTES>>>(q);
    stageBt_tf32<<<dim3(8, MODESN), 128, SMEM_B_BYTES>>>();
    stageC_tf32<<<dim3(4, 32, NB), 256, SMEM_C_BYTES>>>(out);
}

// round 13
// speedup vs baseline: 2.7972x; 1.1086x over previous
#include <cuda_runtime.h>
#include <cuda_bf16.h>
#include <cstdint>

// Problem constants
#define LL     4096
#define DD     512
#define MODESN 64
#define JJ     128   // 2*MODES (Re rows then Im rows)
#define NB     32    // batch

// tf32 tile geometry: [row][word 64 data + 4 pad] fp32 words
#define TPW     68
#define TWORDS  (128 * TPW)        // 8704 words = 34816 bytes per 128-row tile
#define TILE_BYTES (TWORDS * 4)
#define TILE_U4 (TWORDS / 4)       // 2176 uint4 per 128-row tile
#define WTW     (64 * TPW)         // 4352 words per 64-row W tile
#define WT_U4   (WTW / 4)          // 1088 uint4

// ---------------------------------------------------------------------------
// Static device scratch (no allocation allowed)
// ---------------------------------------------------------------------------
// Stage A basis tiles: [kc 64] of [j 128][kk 64(+4)] tf32 words
__device__ __align__(16) uint32_t g_A[64 * TWORDS];
// Stage C basis tiles: [lt 32][kc 2] of [l 128][j 64(+4)]
__device__ __align__(16) uint32_t g_F[64 * TWORDS];
// Y^T tiles for stage C: [b 32][et 4][kc 2] of [e_local 128][m 64(+4)]
__device__ __align__(16) uint32_t g_yt[256 * TWORDS];
// W^T tf32 tiles: [ri 2][m 64][eb 8][kc8 8] of [e 64][d 64(+4)]  (142.6 MB)
__device__ __align__(16) uint32_t g_Wt[(size_t)2 * 64 * 64 * WTW];
// Stage A partial outputs fp32 [b][j][d] (K-split halves)
__device__ float g_X [NB * JJ * DD];
__device__ float g_X2[NB * JJ * DD];

// ---------------------------------------------------------------------------
// Helpers
// ---------------------------------------------------------------------------
__device__ __forceinline__ uint32_t smem_u32(const void* p) {
    uint32_t a;
    asm("{ .reg .u64 t; cvta.to.shared.u64 t, %1; cvt.u32.u64 %0, t; }"
        : "=r"(a) : "l"(p));
    return a;
}

__device__ __forceinline__ uint32_t lds32(uint32_t a) {
    uint32_t v;
    asm volatile("ld.shared.b32 %0, [%1];" : "=r"(v) : "r"(a));
    return v;
}

// fp32 -> tf32 (round to nearest)
__device__ __forceinline__ uint32_t tf32r(float v) {
    uint32_t r;
    asm("cvt.rna.tf32.f32 %0, %1;" : "=r"(r) : "f"(v));
    return r;
}

__device__ __forceinline__ void cp16(uint32_t saddr, const void* g) {
    asm volatile("cp.async.cg.shared.global [%0], [%1], 16;" :: "r"(saddr), "l"(g));
}
#define CP_COMMIT() asm volatile("cp.async.commit_group;" ::: "memory")
#define CP_WAIT0()  asm volatile("cp.async.wait_group 0;" ::: "memory")

__device__ __forceinline__ void mma_tf32(float* c, const uint32_t* a,
                                         uint32_t b0, uint32_t b1) {
    asm volatile(
        "mma.sync.aligned.m16n8k8.row.col.f32.tf32.tf32.f32 "
        "{%0,%1,%2,%3}, {%4,%5,%6,%7}, {%8,%9}, {%0,%1,%2,%3};"
        : "+f"(c[0]), "+f"(c[1]), "+f"(c[2]), "+f"(c[3])
        : "r"(a[0]), "r"(a[1]), "r"(a[2]), "r"(a[3]), "r"(b0), "r"(b1));
}

// ---------------------------------------------------------------------------
// tf32 chunk compute (R9-PROVEN): materialized A and B tiles, K=64.
// ---------------------------------------------------------------------------
__device__ __forceinline__ void gemm_tf32(uint32_t baseA, uint32_t baseB,
                                          int lane, int wm, int wn,
                                          float acc[2][8][4]) {
    const uint32_t g  = (uint32_t)(lane >> 2);
    const uint32_t t4 = (uint32_t)(lane & 3);
    #pragma unroll
    for (int k8 = 0; k8 < 8; k8++) {
        const uint32_t kw = (uint32_t)k8 * 8u + t4;
        uint32_t a[2][4];
        #pragma unroll
        for (int mt = 0; mt < 2; mt++) {
            uint32_t r0 = (uint32_t)(wm * 32 + mt * 16) + g;
            a[mt][0] = lds32(baseA + (r0 * TPW + kw) * 4u);
            a[mt][1] = lds32(baseA + ((r0 + 8) * TPW + kw) * 4u);
            a[mt][2] = lds32(baseA + (r0 * TPW + kw + 4) * 4u);
            a[mt][3] = lds32(baseA + ((r0 + 8) * TPW + kw + 4) * 4u);
        }
        #pragma unroll
        for (int nt = 0; nt < 8; nt++) {
            uint32_t nr = (uint32_t)(wn * 64 + nt * 8) + g;
            uint32_t b0 = lds32(baseB + (nr * TPW + kw) * 4u);
            uint32_t b1 = lds32(baseB + (nr * TPW + kw + 4) * 4u);
            mma_tf32(acc[0][nt], a[0], b0, b1);
            mma_tf32(acc[1][nt], a[1], b0, b1);
        }
    }
}

// ---------------------------------------------------------------------------
// Stage A gemm variant: B fragments straight from q staging (row stride 136
// words) with on-the-fly tf32 cvt. Bank: (8*t4 + g) mod 32 -> conflict-free.
// ---------------------------------------------------------------------------
#define QS2 136
__device__ __forceinline__ void gemm_tf32_qs(uint32_t baseA, uint32_t qsb,
                                             int lane, int wm, int wn,
                                             float acc[2][8][4]) {
    const uint32_t g  = (uint32_t)(lane >> 2);
    const uint32_t t4 = (uint32_t)(lane & 3);
    #pragma unroll
    for (int k8 = 0; k8 < 8; k8++) {
        const uint32_t kw = (uint32_t)k8 * 8u + t4;
        uint32_t a[2][4];
        #pragma unroll
        for (int mt = 0; mt < 2; mt++) {
            uint32_t r0 = (uint32_t)(wm * 32 + mt * 16) + g;
            a[mt][0] = lds32(baseA + (r0 * TPW + kw) * 4u);
            a[mt][1] = lds32(baseA + ((r0 + 8) * TPW + kw) * 4u);
            a[mt][2] = lds32(baseA + (r0 * TPW + kw + 4) * 4u);
            a[mt][3] = lds32(baseA + ((r0 + 8) * TPW + kw + 4) * 4u);
        }
        #pragma unroll
        for (int nt = 0; nt < 8; nt++) {
            uint32_t nr = (uint32_t)(wn * 64 + nt * 8) + g;
            float f0 = __uint_as_float(lds32(qsb + (kw * QS2 + nr) * 4u));
            float f1 = __uint_as_float(lds32(qsb + ((kw + 4) * QS2 + nr) * 4u));
            uint32_t b0 = tf32r(f0);
            uint32_t b1 = tf32r(f1);
            mma_tf32(acc[0][nt], a[0], b0, b1);
            mma_tf32(acc[1][nt], a[1], b0, b1);
        }
    }
}

// ---------------------------------------------------------------------------
// Basis builders (R9-proven)
// ---------------------------------------------------------------------------
__global__ void build_basisA_tf32() {
    int t = blockIdx.x * blockDim.x + threadIdx.x;
    int kc = t >> 11;
    int j  = (t >> 4) & 127;
    int oc = t & 15;
    uint32_t w[4];
    #pragma unroll
    for (int u = 0; u < 4; u++) {
        int l = kc * 64 + oc * 4 + u;
        int m = j & 63;
        int phi = (m * l) & (LL - 1);
        float s, c;
        sincospif(2.0f * (float)phi / (float)LL, &s, &c);
        w[u] = tf32r((j < MODESN) ? c : -s);
    }
    *(uint4*)&g_A[(size_t)kc * TWORDS + j * TPW + oc * 4] =
        make_uint4(w[0], w[1], w[2], w[3]);
}

__global__ void build_basisF_tf32() {
    int t = blockIdx.x * blockDim.x + threadIdx.x;
    int tile = t >> 11;
    int lt = tile >> 1;
    int kc = tile & 1;
    int lr = (t >> 4) & 127;
    int oc = t & 15;
    int l = lt * 128 + lr;
    uint32_t w[4];
    #pragma unroll
    for (int u = 0; u < 4; u++) {
        int j = kc * 64 + oc * 4 + u;
        int m = j & 63;
        int phi = (m * l) & (LL - 1);
        float s, c;
        sincospif(2.0f * (float)phi / (float)LL, &s, &c);
        float v;
        if (j < MODESN) v = ((m == 0) ? 1.0f : 2.0f) * (1.0f / (float)LL) * c;
        else            v = (-2.0f / (float)LL) * s;
        w[u] = tf32r(v);
    }
    *(uint4*)&g_F[(size_t)tile * TWORDS + lr * TPW + oc * 4] =
        make_uint4(w[0], w[1], w[2], w[3]);
}

// ---------------------------------------------------------------------------
// Weight transpose -> B-ready tf32 tiles (coalesced-write version).
// Block covers (4 e-values, kc8): stages [er 4][d 64][m 64] (reads coalesced
// along m); stores: lanes 0-15 write one mode-row's 256B contiguously,
// lanes 16-31 the next mode's row -> full-sector STG.128.
// ---------------------------------------------------------------------------
#define SMEM_TW_BYTES (4 * 64 * 65 * 4)   // 66560
__global__ void __launch_bounds__(256) transpose_w_tiles(const float* __restrict__ w,
                                                         int which) {
    extern __shared__ float Sf[];
    int e0  = blockIdx.x * 4;   // 0..508
    int kc8 = blockIdx.y;       // 0..7
    int d0  = kc8 * 64;
    int tid = threadIdx.x;
    // load [er 4][d 64][m 64], coalesced 64-float rows
    #pragma unroll
    for (int i = 0; i < 64; i++) {
        int idx = tid + i * 256;
        int m  = idx & 63;
        int dd = (idx >> 6) & 63;
        int er = idx >> 12;
        Sf[(er * 64 + dd) * 65 + m] = w[((size_t)(d0 + dd) * DD + e0 + er) * MODESN + m];
    }
    __syncthreads();
    int l16 = tid & 15, mslot = tid >> 4;
    #pragma unroll
    for (int mo = 0; mo < 4; mo++) {
        int m = mo * 16 + mslot;
        #pragma unroll
        for (int er = 0; er < 4; er++) {
            int e = e0 + er, eb = e >> 6, el = e & 63;
            uint32_t wv[4];
            #pragma unroll
            for (int u = 0; u < 4; u++) {
                int dd = l16 * 4 + u;
                wv[u] = tf32r(Sf[(er * 64 + dd) * 65 + m]);
            }
            uint32_t* dst = g_Wt
                + ((size_t)((which * 64 + m) * 64) + eb * 8 + kc8) * WTW
                + (size_t)el * TPW + l16 * 4;
            *(uint4*)dst = make_uint4(wv[0], wv[1], wv[2], wv[3]);
        }
    }
}

// ---------------------------------------------------------------------------
// Stage A (tf32 mma, direct-B): K-split grid (dt4, b32, ks2), 256 thr, 2/SM.
// SMEM: A tile @0, qs double buffer @TILE_BYTES (each 64 x 136 fp32 = 34816)
// Per chunk: sync; copy A tile; wait qs[p]; sync; prefetch qs[p^1]; gemm.
// ---------------------------------------------------------------------------
#define QS2_BYTES (64 * QS2 * 4)                     // 34816
#define SMEM_A_BYTES (TILE_BYTES + 2 * QS2_BYTES)    // 104448
__global__ void __launch_bounds__(256, 2) stageA_tf32(const float* __restrict__ q) {
    extern __shared__ __align__(16) unsigned char smem[];
    uint32_t sb = smem_u32(smem);
    int tid = threadIdx.x;
    int lane = tid & 31, warp = tid >> 5;
    int wm = warp & 3, wn = warp >> 2;
    int dt = blockIdx.x, b = blockIdx.y, ks = blockIdx.z;

    float acc[2][8][4];
    #pragma unroll
    for (int mt = 0; mt < 2; mt++)
        #pragma unroll
        for (int nt = 0; nt < 8; nt++)
            #pragma unroll
            for (int i = 0; i < 4; i++) acc[mt][nt][i] = 0.0f;

    uint4* dA = (uint4*)smem;

    auto issue_q = [&](int ic, int p) {
        const float* qsrc = q + ((size_t)b * LL + (size_t)ic * 64) * DD + dt * 128;
        uint32_t dstb = sb + TILE_BYTES + (uint32_t)p * QS2_BYTES;
        #pragma unroll
        for (int i = 0; i < 8; i++) {
            int idx = tid + i * 256;
            int r  = idx >> 5;
            int c4 = idx & 31;
            cp16(dstb + (uint32_t)(r * QS2 + c4 * 4) * 4u,
                 qsrc + (size_t)r * DD + c4 * 4);
        }
        CP_COMMIT();
    };

    issue_q(ks * 32, 0);

    for (int ic0 = 0; ic0 < 32; ic0++) {
        int ic = ks * 32 + ic0;
        int p = ic0 & 1;
        __syncthreads();   // prev gemm done: A tile + qs[p] buffer free to fill
        // copy basis tile ic (L2-resident)
        const uint4* sA = (const uint4*)&g_A[(size_t)ic * TWORDS];
        #pragma unroll
        for (int i = 0; i < 9; i++) {
            int idx = tid + i * 256;
            if (idx < TILE_U4) dA[idx] = sA[idx];
        }
        CP_WAIT0();        // qs[p] landed
        __syncthreads();   // A tile + qs[p] visible to all
        if (ic0 < 31) issue_q(ic + 1, p ^ 1);   // overlap with gemm
        gemm_tf32_qs(sb, sb + TILE_BYTES + (uint32_t)p * QS2_BYTES,
                     lane, wm, wn, acc);
    }

    float* Xo = (ks == 0) ? g_X : g_X2;
    int tg = lane >> 2, tig = lane & 3;
    #pragma unroll
    for (int mt = 0; mt < 2; mt++) {
        int j0 = wm * 32 + mt * 16;
        #pragma unroll
        for (int nt = 0; nt < 8; nt++) {
            int dcol = dt * 128 + wn * 64 + nt * 8 + tig * 2;
            float* p0 = Xo + ((size_t)b * JJ + j0 + tg) * DD + dcol;
            float* p1 = Xo + ((size_t)b * JJ + j0 + tg + 8) * DD + dcol;
            *(float2*)p0 = make_float2(acc[mt][nt][0], acc[mt][nt][1]);
            *(float2*)p1 = make_float2(acc[mt][nt][2], acc[mt][nt][3]);
        }
    }
}

// ---------------------------------------------------------------------------
// Stage B (R12-proven): per mode m, e-block 64, tf32 mma, 2-phase.
// SMEM: Ar @0, Ai @8704, Br @17408, Bi @34816. Total 52224.
// ---------------------------------------------------------------------------
#define SB2_AI  8704
#define SB2_BR  17408
#define SB2_BI  34816
#define SMEM_B_BYTES 52224
__global__ void __launch_bounds__(128, 4) stageBt_tf32() {
    extern __shared__ __align__(16) unsigned char smem[];
    uint32_t sb = smem_u32(smem);
    uint32_t* AwR = (uint32_t*)smem;
    uint32_t* AwI = (uint32_t*)(smem + SB2_AI);
    uint4* dBr = (uint4*)(smem + SB2_BR);
    uint4* dBi = (uint4*)(smem + SB2_BI);
    int tid = threadIdx.x;
    int lane = tid & 31, warp = tid >> 5;
    int outI = warp >> 1;
    int nh   = warp & 1;
    int m  = blockIdx.y;
    int eb = blockIdx.x;

    float acc[2][4][4];
    #pragma unroll
    for (int mt = 0; mt < 2; mt++)
        #pragma unroll
        for (int nt = 0; nt < 4; nt++)
            #pragma unroll
            for (int i = 0; i < 4; i++) acc[mt][nt][i] = 0.0f;

    for (int kc8 = 0; kc8 < 8; kc8++) {
        int kd = kc8 * 64;
        const uint4* sBr = (const uint4*)&g_Wt[((size_t)m * 64 + eb * 8 + kc8) * WTW];
        const uint4* sBi = (const uint4*)&g_Wt[((size_t)(64 + m) * 64 + eb * 8 + kc8) * WTW];
        #pragma unroll
        for (int i = 0; i < 9; i++) {
            int idx = tid + i * 128;
            if (idx < WT_U4) {
                dBr[idx] = sBr[idx];
                dBi[idx] = sBi[idx];
            }
        }
        #pragma unroll
        for (int i = 0; i < 16; i++) {
            int idx = tid + i * 128;
            int bb = idx >> 6, c = idx & 63;
            size_t xr = ((size_t)bb * JJ + m) * DD + kd + c;
            size_t xi = ((size_t)bb * JJ + MODESN + m) * DD + kd + c;
            AwR[bb * TPW + c] = tf32r(g_X[xr] + g_X2[xr]);
            AwI[bb * TPW + c] = tf32r(g_X[xi] + g_X2[xi]);
        }
        __syncthreads();
        const uint32_t g  = (uint32_t)(lane >> 2);
        const uint32_t t4 = (uint32_t)(lane & 3);
        #pragma unroll
        for (int k8 = 0; k8 < 8; k8++) {
            uint32_t kw = (uint32_t)k8 * 8u + t4;
            uint32_t ar[2][4], ai[2][4];
            #pragma unroll
            for (int mt = 0; mt < 2; mt++) {
                uint32_t r0 = (uint32_t)(mt * 16) + g;
                ar[mt][0] = lds32(sb + (r0 * TPW + kw) * 4u);
                ar[mt][1] = lds32(sb + ((r0 + 8) * TPW + kw) * 4u);
                ar[mt][2] = lds32(sb + (r0 * TPW + kw + 4) * 4u);
                ar[mt][3] = lds32(sb + ((r0 + 8) * TPW + kw + 4) * 4u);
                ai[mt][0] = lds32(sb + SB2_AI + (r0 * TPW + kw) * 4u);
                ai[mt][1] = lds32(sb + SB2_AI + ((r0 + 8) * TPW + kw) * 4u);
                ai[mt][2] = lds32(sb + SB2_AI + (r0 * TPW + kw + 4) * 4u);
                ai[mt][3] = lds32(sb + SB2_AI + ((r0 + 8) * TPW + kw + 4) * 4u);
                if (outI == 0) {
                    #pragma unroll
                    for (int j = 0; j < 4; j++) ai[mt][j] ^= 0x80000000u;
                }
            }
            #pragma unroll
            for (int nt = 0; nt < 4; nt++) {
                uint32_t nr = (uint32_t)(nh * 32 + nt * 8) + g;
                uint32_t br0 = lds32(sb + SB2_BR + (nr * TPW + kw) * 4u);
                uint32_t br1 = lds32(sb + SB2_BR + (nr * TPW + kw + 4) * 4u);
                uint32_t bi0 = lds32(sb + SB2_BI + (nr * TPW + kw) * 4u);
                uint32_t bi1 = lds32(sb + SB2_BI + (nr * TPW + kw + 4) * 4u);
                if (outI == 0) {
                    mma_tf32(acc[0][nt], ar[0], br0, br1);
                    mma_tf32(acc[0][nt], ai[0], bi0, bi1);
                    mma_tf32(acc[1][nt], ar[1], br0, br1);
                    mma_tf32(acc[1][nt], ai[1], bi0, bi1);
                } else {
                    mma_tf32(acc[0][nt], ar[0], bi0, bi1);
                    mma_tf32(acc[0][nt], ai[0], br0, br1);
                    mma_tf32(acc[1][nt], ar[1], bi0, bi1);
                    mma_tf32(acc[1][nt], ai[1], br0, br1);
                }
            }
        }
        __syncthreads();
    }

    int tg = lane >> 2, tig = lane & 3;
    #pragma unroll
    for (int mt = 0; mt < 2; mt++) {
        #pragma unroll
        for (int nt = 0; nt < 4; nt++) {
            int e0c = eb * 64 + nh * 32 + nt * 8 + tig * 2;
            int b0 = mt * 16 + tg;
            #pragma unroll
            for (int o = 0; o < 2; o++) {
                int e = e0c + o;
                int et = e >> 7, el = e & 127;
                size_t w0 = (((size_t)b0 * 4 + et) * 2 + outI) * TWORDS
                          + (size_t)el * TPW + m;
                size_t w1 = (((size_t)(b0 + 8) * 4 + et) * 2 + outI) * TWORDS
                          + (size_t)el * TPW + m;
                g_yt[w0] = tf32r(acc[mt][nt][o]);
                g_yt[w1] = tf32r(acc[mt][nt][2 + o]);
            }
        }
    }
}

// ---------------------------------------------------------------------------
// Stage C (R9-PROVEN, unchanged): out[b][l 128][e 128] = F @ Y_b, K=128
// ---------------------------------------------------------------------------
#define SMEM_C_BYTES (2 * TILE_BYTES)   // 69632
__global__ void __launch_bounds__(256, 2) stageC_tf32(float* __restrict__ out) {
    extern __shared__ __align__(16) unsigned char smem[];
    uint32_t sb = smem_u32(smem);
    int tid = threadIdx.x;
    int lane = tid & 31, warp = tid >> 5;
    int wm = warp & 3, wn = warp >> 2;
    int et = blockIdx.x, lt = blockIdx.y, b = blockIdx.z;

    float acc[2][8][4];
    #pragma unroll
    for (int mt = 0; mt < 2; mt++)
        #pragma unroll
        for (int nt = 0; nt < 8; nt++)
            #pragma unroll
            for (int i = 0; i < 4; i++) acc[mt][nt][i] = 0.0f;

    uint4* dA = (uint4*)smem;
    uint4* dB = (uint4*)(smem + TILE_BYTES);

    #pragma unroll
    for (int kc = 0; kc < 2; kc++) {
        const uint4* sA = (const uint4*)&g_F[(size_t)(lt * 2 + kc) * TWORDS];
        const uint4* sB = (const uint4*)&g_yt[(((size_t)b * 4 + et) * 2 + kc) * TWORDS];
        #pragma unroll
        for (int i = 0; i < 9; i++) {
            int idx = tid + i * 256;
            if (idx < TILE_U4) {
                dA[idx] = sA[idx];
                dB[idx] = sB[idx];
            }
        }
        __syncthreads();
        gemm_tf32(sb, sb + TILE_BYTES, lane, wm, wn, acc);
        __syncthreads();
    }

    int tg = lane >> 2, tig = lane & 3;
    #pragma unroll
    for (int mt = 0; mt < 2; mt++) {
        int l0 = lt * 128 + wm * 32 + mt * 16;
        #pragma unroll
        for (int nt = 0; nt < 8; nt++) {
            int ecol = et * 128 + wn * 64 + nt * 8 + tig * 2;
            float* p0 = out + ((size_t)b * LL + l0 + tg) * DD + ecol;
            float* p1 = out + ((size_t)b * LL + l0 + tg + 8) * DD + ecol;
            *(float2*)p0 = make_float2(acc[mt][nt][0], acc[mt][nt][1]);
            *(float2*)p1 = make_float2(acc[mt][nt][2], acc[mt][nt][3]);
        }
    }
}

// ---------------------------------------------------------------------------
// launch
// ---------------------------------------------------------------------------
extern "C" void kernel_launch(void* const* d_in, const int* in_sizes, int n_in,
                              void* d_out, int out_size) {
    const float* q  = (const float*)d_in[0];
    const float* wr = (const float*)d_in[1];
    const float* wi = (const float*)d_in[2];
    float* out = (float*)d_out;

    // Idempotent, every invocation (no static guards — harness rule)
    cudaFuncSetAttribute(stageA_tf32, cudaFuncAttributeMaxDynamicSharedMemorySize, SMEM_A_BYTES);
    cudaFuncSetAttribute(stageBt_tf32, cudaFuncAttributeMaxDynamicSharedMemorySize, SMEM_B_BYTES);
    cudaFuncSetAttribute(stageC_tf32, cudaFuncAttributeMaxDynamicSharedMemorySize, SMEM_C_BYTES);
    cudaFuncSetAttribute(transpose_w_tiles, cudaFuncAttributeMaxDynamicSharedMemorySize, SMEM_TW_BYTES);

    build_basisA_tf32<<<512, 256>>>();
    build_basisF_tf32<<<512, 256>>>();

    transpose_w_tiles<<<dim3(128, 8), 256, SMEM_TW_BYTES>>>(wr, 0);
    transpose_w_tiles<<<dim3(128, 8), 256, SMEM_TW_BYTES>>>(wi, 1);

    stageA_tf32<<<dim3(4, NB, 2), 256, SMEM_A_BYTES>>>(q);
    stageBt_tf32<<<dim3(8, MODESN), 128, SMEM_B_BYTES>>>();
    stageC_tf32<<<dim3(4, 32, NB), 256, SMEM_C_BYTES>>>(out);
}

// round 14
// speedup vs baseline: 3.3999x; 1.2155x over previous
#include <cuda_runtime.h>
#include <cuda_bf16.h>
#include <cstdint>

// Problem constants
#define LL     4096
#define DD     512
#define MODESN 64
#define JJ     128   // 2*MODES (Re rows then Im rows)
#define NB     32    // batch

// tf32 tile geometry: [row][word 64 data + 4 pad] fp32 words
#define TPW     68
#define TWORDS  (128 * TPW)        // 8704 words / 34816 B per 128-row tile
#define TILE_BYTES (TWORDS * 4)
#define TILE_U4 (TWORDS / 4)       // 2176
#define HTW     (64 * TPW)         // 4352 words per 64-row tile
#define HT_BYTES (HTW * 4)         // 17408
#define HT_U4   (HTW / 4)          // 1088
#define WTDW    (64 * 64)          // dense W tile words (256B rows)

// ---------------------------------------------------------------------------
// Static device scratch (no allocation allowed)
// ---------------------------------------------------------------------------
// Stage A parity basis: [icp 32][par 2] of [j 64][k 64(+4)]
__device__ __align__(16) uint32_t g_A[64 * HTW];
// Stage C parity basis: [lt 16][par 2] of [l 128][k 64(+4)]
__device__ __align__(16) uint32_t g_F[32 * TWORDS];
// Y^T tiles: [b 32][et 4][p 2] of [e 128][word 64(+4)]
// word layout: outI*32 + m/2  (p = m&1)
__device__ __align__(16) uint32_t g_yt[256 * TWORDS];
// W^T tf32 tiles DENSE: [ri 2][m 64][eb 8][kc8 8] of [e 64][d 64] (128 MB)
__device__ __align__(16) uint32_t g_Wt[(size_t)2 * 64 * 64 * WTDW];
// Stage A partial outputs fp32 [b][j][d] (K-split halves)
__device__ float g_X [NB * JJ * DD];
__device__ float g_X2[NB * JJ * DD];

// ---------------------------------------------------------------------------
// Helpers
// ---------------------------------------------------------------------------
__device__ __forceinline__ uint32_t smem_u32(const void* p) {
    uint32_t a;
    asm("{ .reg .u64 t; cvta.to.shared.u64 t, %1; cvt.u32.u64 %0, t; }"
        : "=r"(a) : "l"(p));
    return a;
}

__device__ __forceinline__ uint32_t lds32(uint32_t a) {
    uint32_t v;
    asm volatile("ld.shared.b32 %0, [%1];" : "=r"(v) : "r"(a));
    return v;
}

__device__ __forceinline__ uint32_t tf32r(float v) {
    uint32_t r;
    asm("cvt.rna.tf32.f32 %0, %1;" : "=r"(r) : "f"(v));
    return r;
}

__device__ __forceinline__ void cp16(uint32_t saddr, const void* g) {
    asm volatile("cp.async.cg.shared.global [%0], [%1], 16;" :: "r"(saddr), "l"(g));
}
#define CP_COMMIT() asm volatile("cp.async.commit_group;" ::: "memory")
#define CP_WAIT0()  asm volatile("cp.async.wait_group 0;" ::: "memory")

__device__ __forceinline__ void mma_tf32(float* c, const uint32_t* a,
                                         uint32_t b0, uint32_t b1) {
    asm volatile(
        "mma.sync.aligned.m16n8k8.row.col.f32.tf32.tf32.f32 "
        "{%0,%1,%2,%3}, {%4,%5,%6,%7}, {%8,%9}, {%0,%1,%2,%3};"
        : "+f"(c[0]), "+f"(c[1]), "+f"(c[2]), "+f"(c[3])
        : "r"(a[0]), "r"(a[1]), "r"(a[2]), "r"(a[3]), "r"(b0), "r"(b1));
}

// ---------------------------------------------------------------------------
// Stage A gemm: M=64 (one m16 tile per warp), B read from q staging
// (row stride 136 words) with on-the-fly tf32 cvt; conflict-free (R13-proven).
// ---------------------------------------------------------------------------
#define QS2 136
__device__ __forceinline__ void gemm_qs64(uint32_t baseA, uint32_t qsb,
                                          int lane, int wm, int wn,
                                          float acc[8][4]) {
    const uint32_t g  = (uint32_t)(lane >> 2);
    const uint32_t t4 = (uint32_t)(lane & 3);
    #pragma unroll
    for (int k8 = 0; k8 < 8; k8++) {
        const uint32_t kw = (uint32_t)k8 * 8u + t4;
        uint32_t a[4];
        uint32_t r0 = (uint32_t)(wm * 16) + g;
        a[0] = lds32(baseA + (r0 * TPW + kw) * 4u);
        a[1] = lds32(baseA + ((r0 + 8) * TPW + kw) * 4u);
        a[2] = lds32(baseA + (r0 * TPW + kw + 4) * 4u);
        a[3] = lds32(baseA + ((r0 + 8) * TPW + kw + 4) * 4u);
        #pragma unroll
        for (int nt = 0; nt < 8; nt++) {
            uint32_t nr = (uint32_t)(wn * 64 + nt * 8) + g;
            float f0 = __uint_as_float(lds32(qsb + (kw * QS2 + nr) * 4u));
            float f1 = __uint_as_float(lds32(qsb + ((kw + 4) * QS2 + nr) * 4u));
            mma_tf32(acc[nt], a, tf32r(f0), tf32r(f1));
        }
    }
}

// ---------------------------------------------------------------------------
// Stage C gemm: M=128 (mt 2), N=32 per warp-half (nt 4), materialized tiles.
// ---------------------------------------------------------------------------
__device__ __forceinline__ void gemm_c(uint32_t baseA, uint32_t baseB,
                                       int lane, int wm, int wn,
                                       float acc[2][4][4]) {
    const uint32_t g  = (uint32_t)(lane >> 2);
    const uint32_t t4 = (uint32_t)(lane & 3);
    #pragma unroll
    for (int k8 = 0; k8 < 8; k8++) {
        const uint32_t kw = (uint32_t)k8 * 8u + t4;
        uint32_t a[2][4];
        #pragma unroll
        for (int mt = 0; mt < 2; mt++) {
            uint32_t r0 = (uint32_t)(wm * 32 + mt * 16) + g;
            a[mt][0] = lds32(baseA + (r0 * TPW + kw) * 4u);
            a[mt][1] = lds32(baseA + ((r0 + 8) * TPW + kw) * 4u);
            a[mt][2] = lds32(baseA + (r0 * TPW + kw + 4) * 4u);
            a[mt][3] = lds32(baseA + ((r0 + 8) * TPW + kw + 4) * 4u);
        }
        #pragma unroll
        for (int nt = 0; nt < 4; nt++) {
            uint32_t nr = (uint32_t)(wn * 32 + nt * 8) + g;
            uint32_t b0 = lds32(baseB + (nr * TPW + kw) * 4u);
            uint32_t b1 = lds32(baseB + (nr * TPW + kw + 4) * 4u);
            mma_tf32(acc[0][nt], a[0], b0, b1);
            mma_tf32(acc[1][nt], a[1], b0, b1);
        }
    }
}

// ---------------------------------------------------------------------------
// Basis builders (parity-split tiles)
// ---------------------------------------------------------------------------
__global__ void build_basisA_pair() {
    int t = blockIdx.x * blockDim.x + threadIdx.x;   // 65536 tasks
    int oc  = t & 15;
    int j   = (t >> 4) & 63;
    int par = (t >> 10) & 1;
    int icp = t >> 11;          // 0..31
    uint32_t w[4];
    #pragma unroll
    for (int u = 0; u < 4; u++) {
        int kk = oc * 4 + u;
        int l = icp * 64 + kk;
        int m = ((j < 32) ? 2 * j : 2 * (j - 32)) + par;
        int phi = (m * l) & (LL - 1);
        float s, c;
        sincospif(2.0f * (float)phi / (float)LL, &s, &c);
        w[u] = tf32r((j < 32) ? c : -s);
    }
    *(uint4*)&g_A[(size_t)(icp * 2 + par) * HTW + j * TPW + oc * 4] =
        make_uint4(w[0], w[1], w[2], w[3]);
}

__global__ void build_basisF_pair() {
    int t = blockIdx.x * blockDim.x + threadIdx.x;   // 65536 tasks
    int oc  = t & 15;
    int lr  = (t >> 4) & 127;
    int par = (t >> 11) & 1;
    int lt  = t >> 12;          // 0..15
    int l = lt * 128 + lr;
    uint32_t w[4];
    #pragma unroll
    for (int u = 0; u < 4; u++) {
        int k = oc * 4 + u;
        int m = ((k < 32) ? 2 * k : 2 * (k - 32)) + par;
        int phi = (m * l) & (LL - 1);
        float s, c;
        sincospif(2.0f * (float)phi / (float)LL, &s, &c);
        float v;
        if (k < 32) v = ((m == 0) ? 1.0f : 2.0f) * (1.0f / (float)LL) * c;
        else        v = (-2.0f / (float)LL) * s;
        w[u] = tf32r(v);
    }
    *(uint4*)&g_F[(size_t)(lt * 2 + par) * TWORDS + lr * TPW + oc * 4] =
        make_uint4(w[0], w[1], w[2], w[3]);
}

// ---------------------------------------------------------------------------
// Weight transpose -> DENSE B-ready tf32 tiles (256B-aligned rows)
// ---------------------------------------------------------------------------
#define SMEM_TW_BYTES (4 * 64 * 65 * 4)   // 66560
__global__ void __launch_bounds__(256) transpose_w_tiles(const float* __restrict__ w,
                                                         int which) {
    extern __shared__ float Sf[];
    int e0  = blockIdx.x * 4;
    int kc8 = blockIdx.y;
    int d0  = kc8 * 64;
    int tid = threadIdx.x;
    #pragma unroll
    for (int i = 0; i < 64; i++) {
        int idx = tid + i * 256;
        int m  = idx & 63;
        int dd = (idx >> 6) & 63;
        int er = idx >> 12;
        Sf[(er * 64 + dd) * 65 + m] = w[((size_t)(d0 + dd) * DD + e0 + er) * MODESN + m];
    }
    __syncthreads();
    int l16 = tid & 15, mslot = tid >> 4;
    #pragma unroll
    for (int mo = 0; mo < 4; mo++) {
        int m = mo * 16 + mslot;
        #pragma unroll
        for (int er = 0; er < 4; er++) {
            int e = e0 + er, eb = e >> 6, el = e & 63;
            uint32_t wv[4];
            #pragma unroll
            for (int u = 0; u < 4; u++) {
                int dd = l16 * 4 + u;
                wv[u] = tf32r(Sf[(er * 64 + dd) * 65 + m]);
            }
            uint32_t* dst = g_Wt
                + ((size_t)((which * 64 + m) * 64) + eb * 8 + kc8) * WTDW
                + (size_t)el * 64 + l16 * 4;
            *(uint4*)dst = make_uint4(wv[0], wv[1], wv[2], wv[3]);
        }
    }
}

// ---------------------------------------------------------------------------
// Stage A (radix-2 split): per chunk-pair icp: load q rows l and l+2048,
// combine in-place to sum/diff, two M=64 gemms (even/odd basis).
// X row = 2*je + par. grid (dt 4, b 32, ks 2), 256 thr, 2 CTAs/SM.
// SMEM: AE @0, AO @HT_BYTES, qsL @34816, qsH @34816+QS2_BYTES.
// ---------------------------------------------------------------------------
#define QS2_BYTES (64 * QS2 * 4)                       // 34816
#define SMEM_A_BYTES (2 * HT_BYTES + 2 * QS2_BYTES)    // 104448
__global__ void __launch_bounds__(256, 2) stageA_tf32(const float* __restrict__ q) {
    extern __shared__ __align__(16) unsigned char smem[];
    uint32_t sb = smem_u32(smem);
    int tid = threadIdx.x;
    int lane = tid & 31, warp = tid >> 5;
    int wm = warp & 3, wn = warp >> 2;
    int dt = blockIdx.x, b = blockIdx.y, ks = blockIdx.z;

    float acc_e[8][4], acc_o[8][4];
    #pragma unroll
    for (int nt = 0; nt < 8; nt++)
        #pragma unroll
        for (int i = 0; i < 4; i++) { acc_e[nt][i] = 0.0f; acc_o[nt][i] = 0.0f; }

    uint4* dA = (uint4*)smem;
    float* qL = (float*)(smem + 2 * HT_BYTES);
    float* qH = (float*)(smem + 2 * HT_BYTES + QS2_BYTES);
    const uint32_t qLb = sb + 2 * HT_BYTES;
    const uint32_t qHb = qLb + QS2_BYTES;

    for (int icp0 = 0; icp0 < 16; icp0++) {
        int icp = ks * 16 + icp0;
        __syncthreads();   // prev gemm done: buffers free
        // issue q loads (rows l and l+2048)
        const float* qlo = q + ((size_t)b * LL + (size_t)icp * 64) * DD + dt * 128;
        const float* qhi = qlo + (size_t)2048 * DD;
        #pragma unroll
        for (int i = 0; i < 8; i++) {
            int idx = tid + i * 256;
            int r  = idx >> 5;
            int c4 = idx & 31;
            uint32_t so = (uint32_t)(r * QS2 + c4 * 4) * 4u;
            cp16(qLb + so, qlo + (size_t)r * DD + c4 * 4);
            cp16(qHb + so, qhi + (size_t)r * DD + c4 * 4);
        }
        CP_COMMIT();
        // copy basis pair (AE then AO, contiguous 2176 u4, L2-resident)
        const uint4* sA = (const uint4*)&g_A[(size_t)icp * 2 * HTW];
        #pragma unroll
        for (int i = 0; i < 9; i++) {
            int idx = tid + i * 256;
            if (idx < 2 * HT_U4) dA[idx] = sA[idx];
        }
        CP_WAIT0();
        __syncthreads();
        // in-place combine: qL <- lo+hi, qH <- lo-hi
        #pragma unroll
        for (int i = 0; i < 32; i++) {
            int idx = tid + i * 256;
            int r = idx >> 7, c = idx & 127;
            int off = r * QS2 + c;
            float lo = qL[off], hi = qH[off];
            qL[off] = lo + hi;
            qH[off] = lo - hi;
        }
        __syncthreads();
        gemm_qs64(sb,            qLb, lane, wm, wn, acc_e);
        gemm_qs64(sb + HT_BYTES, qHb, lane, wm, wn, acc_o);
    }

    float* Xo = (ks == 0) ? g_X : g_X2;
    int tg = lane >> 2, tig = lane & 3;
    int je = wm * 16 + tg;
    #pragma unroll
    for (int nt = 0; nt < 8; nt++) {
        int dcol = dt * 128 + wn * 64 + nt * 8 + tig * 2;
        int re0 = 2 * je, re1 = 2 * (je + 8);
        *(float2*)&Xo[((size_t)b * JJ + re0) * DD + dcol] =
            make_float2(acc_e[nt][0], acc_e[nt][1]);
        *(float2*)&Xo[((size_t)b * JJ + re1) * DD + dcol] =
            make_float2(acc_e[nt][2], acc_e[nt][3]);
        *(float2*)&Xo[((size_t)b * JJ + re0 + 1) * DD + dcol] =
            make_float2(acc_o[nt][0], acc_o[nt][1]);
        *(float2*)&Xo[((size_t)b * JJ + re1 + 1) * DD + dcol] =
            make_float2(acc_o[nt][2], acc_o[nt][3]);
    }
}

// ---------------------------------------------------------------------------
// Stage B (tf32 mma, 2-phase, dense W tiles re-padded during copy).
// Epilogue writes parity-grouped Y^T: tile p = m&1, word = outI*32 + m/2.
// SMEM: Ar @0, Ai @8704, Br @17408, Bi @34816. Total 52224.
// ---------------------------------------------------------------------------
#define SB2_AI  8704
#define SB2_BR  17408
#define SB2_BI  34816
#define SMEM_B_BYTES 52224
__global__ void __launch_bounds__(128, 4) stageBt_tf32() {
    extern __shared__ __align__(16) unsigned char smem[];
    uint32_t sb = smem_u32(smem);
    uint32_t* AwR = (uint32_t*)smem;
    uint32_t* AwI = (uint32_t*)(smem + SB2_AI);
    uint4* dBr = (uint4*)(smem + SB2_BR);
    uint4* dBi = (uint4*)(smem + SB2_BI);
    int tid = threadIdx.x;
    int lane = tid & 31, warp = tid >> 5;
    int outI = warp >> 1;
    int nh   = warp & 1;
    int m  = blockIdx.y;
    int eb = blockIdx.x;

    float acc[2][4][4];
    #pragma unroll
    for (int mt = 0; mt < 2; mt++)
        #pragma unroll
        for (int nt = 0; nt < 4; nt++)
            #pragma unroll
            for (int i = 0; i < 4; i++) acc[mt][nt][i] = 0.0f;

    for (int kc8 = 0; kc8 < 8; kc8++) {
        int kd = kc8 * 64;
        const uint4* sBr = (const uint4*)&g_Wt[((size_t)m * 64 + eb * 8 + kc8) * WTDW];
        const uint4* sBi = (const uint4*)&g_Wt[((size_t)(64 + m) * 64 + eb * 8 + kc8) * WTDW];
        #pragma unroll
        for (int i = 0; i < 8; i++) {
            int idx = tid + i * 128;
            if (idx < 1024) {
                int row = idx >> 4, c4 = idx & 15;
                dBr[row * 17 + c4] = sBr[idx];
                dBi[row * 17 + c4] = sBi[idx];
            }
        }
        #pragma unroll
        for (int i = 0; i < 16; i++) {
            int idx = tid + i * 128;
            int bb = idx >> 6, c = idx & 63;
            size_t xr = ((size_t)bb * JJ + m) * DD + kd + c;
            size_t xi = ((size_t)bb * JJ + MODESN + m) * DD + kd + c;
            AwR[bb * TPW + c] = tf32r(g_X[xr] + g_X2[xr]);
            AwI[bb * TPW + c] = tf32r(g_X[xi] + g_X2[xi]);
        }
        __syncthreads();
        const uint32_t g  = (uint32_t)(lane >> 2);
        const uint32_t t4 = (uint32_t)(lane & 3);
        #pragma unroll
        for (int k8 = 0; k8 < 8; k8++) {
            uint32_t kw = (uint32_t)k8 * 8u + t4;
            uint32_t ar[2][4], ai[2][4];
            #pragma unroll
            for (int mt = 0; mt < 2; mt++) {
                uint32_t r0 = (uint32_t)(mt * 16) + g;
                ar[mt][0] = lds32(sb + (r0 * TPW + kw) * 4u);
                ar[mt][1] = lds32(sb + ((r0 + 8) * TPW + kw) * 4u);
                ar[mt][2] = lds32(sb + (r0 * TPW + kw + 4) * 4u);
                ar[mt][3] = lds32(sb + ((r0 + 8) * TPW + kw + 4) * 4u);
                ai[mt][0] = lds32(sb + SB2_AI + (r0 * TPW + kw) * 4u);
                ai[mt][1] = lds32(sb + SB2_AI + ((r0 + 8) * TPW + kw) * 4u);
                ai[mt][2] = lds32(sb + SB2_AI + (r0 * TPW + kw + 4) * 4u);
                ai[mt][3] = lds32(sb + SB2_AI + ((r0 + 8) * TPW + kw + 4) * 4u);
                if (outI == 0) {
                    #pragma unroll
                    for (int j = 0; j < 4; j++) ai[mt][j] ^= 0x80000000u;
                }
            }
            #pragma unroll
            for (int nt = 0; nt < 4; nt++) {
                uint32_t nr = (uint32_t)(nh * 32 + nt * 8) + g;
                uint32_t br0 = lds32(sb + SB2_BR + (nr * TPW + kw) * 4u);
                uint32_t br1 = lds32(sb + SB2_BR + (nr * TPW + kw + 4) * 4u);
                uint32_t bi0 = lds32(sb + SB2_BI + (nr * TPW + kw) * 4u);
                uint32_t bi1 = lds32(sb + SB2_BI + (nr * TPW + kw + 4) * 4u);
                if (outI == 0) {
                    mma_tf32(acc[0][nt], ar[0], br0, br1);
                    mma_tf32(acc[0][nt], ai[0], bi0, bi1);
                    mma_tf32(acc[1][nt], ar[1], br0, br1);
                    mma_tf32(acc[1][nt], ai[1], bi0, bi1);
                } else {
                    mma_tf32(acc[0][nt], ar[0], bi0, bi1);
                    mma_tf32(acc[0][nt], ai[0], br0, br1);
                    mma_tf32(acc[1][nt], ar[1], bi0, bi1);
                    mma_tf32(acc[1][nt], ai[1], br0, br1);
                }
            }
        }
        __syncthreads();
    }

    int tg = lane >> 2, tig = lane & 3;
    int p = m & 1;
    int word = outI * 32 + (m >> 1);
    #pragma unroll
    for (int mt = 0; mt < 2; mt++) {
        #pragma unroll
        for (int nt = 0; nt < 4; nt++) {
            int e0c = eb * 64 + nh * 32 + nt * 8 + tig * 2;
            int b0 = mt * 16 + tg;
            #pragma unroll
            for (int o = 0; o < 2; o++) {
                int e = e0c + o;
                int et = e >> 7, el = e & 127;
                size_t w0 = (((size_t)b0 * 4 + et) * 2 + p) * TWORDS
                          + (size_t)el * TPW + word;
                size_t w1 = (((size_t)(b0 + 8) * 4 + et) * 2 + p) * TWORDS
                          + (size_t)el * TPW + word;
                g_yt[w0] = tf32r(acc[mt][nt][o]);
                g_yt[w1] = tf32r(acc[mt][nt][2 + o]);
            }
        }
    }
}

// ---------------------------------------------------------------------------
// Stage C (radix-2 split): E = F_even.Y_even, O = F_odd.Y_odd over l<2048;
// out[l] = E+O, out[l+2048] = E-O. grid (et 8, lt 16, b 32), 2 CTAs/SM.
// SMEM: F tile @0 (34816), Y half-tile @34816 (17408). Total 52224.
// ---------------------------------------------------------------------------
#define SMEM_C_BYTES (TILE_BYTES + HT_BYTES)   // 52224
__global__ void __launch_bounds__(256, 2) stageC_tf32(float* __restrict__ out) {
    extern __shared__ __align__(16) unsigned char smem[];
    uint32_t sb = smem_u32(smem);
    int tid = threadIdx.x;
    int lane = tid & 31, warp = tid >> 5;
    int wm = warp & 3, wn = warp >> 2;
    int et = blockIdx.x, lt = blockIdx.y, b = blockIdx.z;

    float accE[2][4][4], accO[2][4][4];
    #pragma unroll
    for (int mt = 0; mt < 2; mt++)
        #pragma unroll
        for (int nt = 0; nt < 4; nt++)
            #pragma unroll
            for (int i = 0; i < 4; i++) { accE[mt][nt][i] = 0.0f; accO[mt][nt][i] = 0.0f; }

    uint4* dF = (uint4*)smem;
    uint4* dY = (uint4*)(smem + TILE_BYTES);

    #pragma unroll
    for (int p = 0; p < 2; p++) {
        const uint4* sF = (const uint4*)&g_F[(size_t)(lt * 2 + p) * TWORDS];
        const uint4* sY = (const uint4*)&g_yt[(((size_t)b * 4 + (et >> 1)) * 2 + p) * TWORDS
                                              + (size_t)(et & 1) * 64 * TPW];
        #pragma unroll
        for (int i = 0; i < 9; i++) {
            int idx = tid + i * 256;
            if (idx < TILE_U4) dF[idx] = sF[idx];
        }
        #pragma unroll
        for (int i = 0; i < 5; i++) {
            int idx = tid + i * 256;
            if (idx < HT_U4) dY[idx] = sY[idx];
        }
        __syncthreads();
        gemm_c(sb, sb + TILE_BYTES, lane, wm, wn, p ? accO : accE);
        __syncthreads();
    }

    int tg = lane >> 2, tig = lane & 3;
    #pragma unroll
    for (int mt = 0; mt < 2; mt++) {
        int r = lt * 128 + wm * 32 + mt * 16 + tg;
        #pragma unroll
        for (int nt = 0; nt < 4; nt++) {
            int col = et * 64 + wn * 32 + nt * 8 + tig * 2;
            float e0 = accE[mt][nt][0], e1 = accE[mt][nt][1];
            float e2 = accE[mt][nt][2], e3 = accE[mt][nt][3];
            float o0 = accO[mt][nt][0], o1 = accO[mt][nt][1];
            float o2 = accO[mt][nt][2], o3 = accO[mt][nt][3];
            *(float2*)&out[((size_t)b * LL + r) * DD + col]          = make_float2(e0 + o0, e1 + o1);
            *(float2*)&out[((size_t)b * LL + r + 8) * DD + col]      = make_float2(e2 + o2, e3 + o3);
            *(float2*)&out[((size_t)b * LL + r + 2048) * DD + col]   = make_float2(e0 - o0, e1 - o1);
            *(float2*)&out[((size_t)b * LL + r + 2056) * DD + col]   = make_float2(e2 - o2, e3 - o3);
        }
    }
}

// ---------------------------------------------------------------------------
// launch
// ---------------------------------------------------------------------------
extern "C" void kernel_launch(void* const* d_in, const int* in_sizes, int n_in,
                              void* d_out, int out_size) {
    const float* q  = (const float*)d_in[0];
    const float* wr = (const float*)d_in[1];
    const float* wi = (const float*)d_in[2];
    float* out = (float*)d_out;

    // Idempotent, every invocation (no static guards — harness rule)
    cudaFuncSetAttribute(stageA_tf32, cudaFuncAttributeMaxDynamicSharedMemorySize, SMEM_A_BYTES);
    cudaFuncSetAttribute(stageBt_tf32, cudaFuncAttributeMaxDynamicSharedMemorySize, SMEM_B_BYTES);
    cudaFuncSetAttribute(stageC_tf32, cudaFuncAttributeMaxDynamicSharedMemorySize, SMEM_C_BYTES);
    cudaFuncSetAttribute(transpose_w_tiles, cudaFuncAttributeMaxDynamicSharedMemorySize, SMEM_TW_BYTES);

    build_basisA_pair<<<256, 256>>>();
    build_basisF_pair<<<256, 256>>>();

    transpose_w_tiles<<<dim3(128, 8), 256, SMEM_TW_BYTES>>>(wr, 0);
    transpose_w_tiles<<<dim3(128, 8), 256, SMEM_TW_BYTES>>>(wi, 1);

    stageA_tf32<<<dim3(4, NB, 2), 256, SMEM_A_BYTES>>>(q);
    stageBt_tf32<<<dim3(8, MODESN), 128, SMEM_B_BYTES>>>();
    stageC_tf32<<<dim3(8, 16, NB), 256, SMEM_C_BYTES>>>(out);
}

// round 15
// speedup vs baseline: 3.6406x; 1.0708x over previous
#include <cuda_runtime.h>
#include <cuda_bf16.h>
#include <cstdint>

// Problem constants
#define LL     4096
#define DD     512
#define MODESN 64
#define JJ     128   // 2*MODES (Re rows then Im rows)
#define NB     32    // batch

// tf32 tile geometry: [row][word 64 data + 4 pad] fp32 words
#define TPW     68
#define TWORDS  (128 * TPW)        // 8704 words / 34816 B per 128-row tile
#define TILE_BYTES (TWORDS * 4)
#define TILE_U4 (TWORDS / 4)       // 2176
#define HTW     (64 * TPW)         // 4352 words per 64-row tile
#define HT_BYTES (HTW * 4)         // 17408
#define HT_U4   (HTW / 4)          // 1088
#define WTDW    (64 * 64)          // dense W tile words (256B rows)

// ---------------------------------------------------------------------------
// Static device scratch (no allocation allowed)
// ---------------------------------------------------------------------------
// Stage A parity basis: [icp 32][par 2] of [j 64][k 64(+4)]
__device__ __align__(16) uint32_t g_A[64 * HTW];
// Stage C parity basis: [lt 16][par 2] of [l 128][k 64(+4)]
__device__ __align__(16) uint32_t g_F[32 * TWORDS];
// Y^T tiles: [b 32][et 4][p 2] of [e 128][word 64(+4)]
// word layout: outI*32 + m/2  (p = m&1)
__device__ __align__(16) uint32_t g_yt[256 * TWORDS];
// W^T tf32 tiles DENSE: [ri 2][m 64][eb 8][kc8 8] of [e 64][d 64] (128 MB)
__device__ __align__(16) uint32_t g_Wt[(size_t)2 * 64 * 64 * WTDW];
// Stage A partial outputs fp32 [b][j][d] (K-split halves)
__device__ float g_X [NB * JJ * DD];
__device__ float g_X2[NB * JJ * DD];

// ---------------------------------------------------------------------------
// Helpers
// ---------------------------------------------------------------------------
__device__ __forceinline__ uint32_t smem_u32(const void* p) {
    uint32_t a;
    asm("{ .reg .u64 t; cvta.to.shared.u64 t, %1; cvt.u32.u64 %0, t; }"
        : "=r"(a) : "l"(p));
    return a;
}

__device__ __forceinline__ uint32_t lds32(uint32_t a) {
    uint32_t v;
    asm volatile("ld.shared.b32 %0, [%1];" : "=r"(v) : "r"(a));
    return v;
}

__device__ __forceinline__ uint32_t tf32r(float v) {
    uint32_t r;
    asm("cvt.rna.tf32.f32 %0, %1;" : "=r"(r) : "f"(v));
    return r;
}

__device__ __forceinline__ void cp16(uint32_t saddr, const void* g) {
    asm volatile("cp.async.cg.shared.global [%0], [%1], 16;" :: "r"(saddr), "l"(g));
}
#define CP_COMMIT() asm volatile("cp.async.commit_group;" ::: "memory")
#define CP_WAIT0()  asm volatile("cp.async.wait_group 0;" ::: "memory")
#define CP_WAIT1()  asm volatile("cp.async.wait_group 1;" ::: "memory")

__device__ __forceinline__ void mma_tf32(float* c, const uint32_t* a,
                                         uint32_t b0, uint32_t b1) {
    asm volatile(
        "mma.sync.aligned.m16n8k8.row.col.f32.tf32.tf32.f32 "
        "{%0,%1,%2,%3}, {%4,%5,%6,%7}, {%8,%9}, {%0,%1,%2,%3};"
        : "+f"(c[0]), "+f"(c[1]), "+f"(c[2]), "+f"(c[3])
        : "r"(a[0]), "r"(a[1]), "r"(a[2]), "r"(a[3]), "r"(b0), "r"(b1));
}

// ---------------------------------------------------------------------------
// Stage A fused butterfly gemm: even/odd basis tiles + raw q-lo/q-hi staging.
// B fragments: s = lo+hi feeds even acc, d = lo-hi feeds odd acc (registers,
// same fp32 add + cvt points as the former smem combine -> bit-identical).
// Staging row stride 136 words keeps fragment loads conflict-free (R13-proven).
// ---------------------------------------------------------------------------
#define QS2 136
__device__ __forceinline__ void gemm_qs_pair(uint32_t baseAE, uint32_t baseAO,
                                             uint32_t qLb, uint32_t qHb,
                                             int lane, int wm, int wn,
                                             float acc_e[8][4], float acc_o[8][4]) {
    const uint32_t g  = (uint32_t)(lane >> 2);
    const uint32_t t4 = (uint32_t)(lane & 3);
    #pragma unroll
    for (int k8 = 0; k8 < 8; k8++) {
        const uint32_t kw = (uint32_t)k8 * 8u + t4;
        uint32_t aE[4], aO[4];
        uint32_t r0 = (uint32_t)(wm * 16) + g;
        aE[0] = lds32(baseAE + (r0 * TPW + kw) * 4u);
        aE[1] = lds32(baseAE + ((r0 + 8) * TPW + kw) * 4u);
        aE[2] = lds32(baseAE + (r0 * TPW + kw + 4) * 4u);
        aE[3] = lds32(baseAE + ((r0 + 8) * TPW + kw + 4) * 4u);
        aO[0] = lds32(baseAO + (r0 * TPW + kw) * 4u);
        aO[1] = lds32(baseAO + ((r0 + 8) * TPW + kw) * 4u);
        aO[2] = lds32(baseAO + (r0 * TPW + kw + 4) * 4u);
        aO[3] = lds32(baseAO + ((r0 + 8) * TPW + kw + 4) * 4u);
        #pragma unroll
        for (int nt = 0; nt < 8; nt++) {
            uint32_t nr = (uint32_t)(wn * 64 + nt * 8) + g;
            float lo0 = __uint_as_float(lds32(qLb + (kw * QS2 + nr) * 4u));
            float lo1 = __uint_as_float(lds32(qLb + ((kw + 4) * QS2 + nr) * 4u));
            float hi0 = __uint_as_float(lds32(qHb + (kw * QS2 + nr) * 4u));
            float hi1 = __uint_as_float(lds32(qHb + ((kw + 4) * QS2 + nr) * 4u));
            mma_tf32(acc_e[nt], aE, tf32r(lo0 + hi0), tf32r(lo1 + hi1));
            mma_tf32(acc_o[nt], aO, tf32r(lo0 - hi0), tf32r(lo1 - hi1));
        }
    }
}

// ---------------------------------------------------------------------------
// Stage C gemm (R14-proven): M=128 (mt 2), N=32 per warp-half (nt 4).
// ---------------------------------------------------------------------------
__device__ __forceinline__ void gemm_c(uint32_t baseA, uint32_t baseB,
                                       int lane, int wm, int wn,
                                       float acc[2][4][4]) {
    const uint32_t g  = (uint32_t)(lane >> 2);
    const uint32_t t4 = (uint32_t)(lane & 3);
    #pragma unroll
    for (int k8 = 0; k8 < 8; k8++) {
        const uint32_t kw = (uint32_t)k8 * 8u + t4;
        uint32_t a[2][4];
        #pragma unroll
        for (int mt = 0; mt < 2; mt++) {
            uint32_t r0 = (uint32_t)(wm * 32 + mt * 16) + g;
            a[mt][0] = lds32(baseA + (r0 * TPW + kw) * 4u);
            a[mt][1] = lds32(baseA + ((r0 + 8) * TPW + kw) * 4u);
            a[mt][2] = lds32(baseA + (r0 * TPW + kw + 4) * 4u);
            a[mt][3] = lds32(baseA + ((r0 + 8) * TPW + kw + 4) * 4u);
        }
        #pragma unroll
        for (int nt = 0; nt < 4; nt++) {
            uint32_t nr = (uint32_t)(wn * 32 + nt * 8) + g;
            uint32_t b0 = lds32(baseB + (nr * TPW + kw) * 4u);
            uint32_t b1 = lds32(baseB + (nr * TPW + kw + 4) * 4u);
            mma_tf32(acc[0][nt], a[0], b0, b1);
            mma_tf32(acc[1][nt], a[1], b0, b1);
        }
    }
}

// ---------------------------------------------------------------------------
// Basis builders (R14-proven, parity-split tiles)
// ---------------------------------------------------------------------------
__global__ void build_basisA_pair() {
    int t = blockIdx.x * blockDim.x + threadIdx.x;   // 65536 tasks
    int oc  = t & 15;
    int j   = (t >> 4) & 63;
    int par = (t >> 10) & 1;
    int icp = t >> 11;          // 0..31
    uint32_t w[4];
    #pragma unroll
    for (int u = 0; u < 4; u++) {
        int kk = oc * 4 + u;
        int l = icp * 64 + kk;
        int m = ((j < 32) ? 2 * j : 2 * (j - 32)) + par;
        int phi = (m * l) & (LL - 1);
        float s, c;
        sincospif(2.0f * (float)phi / (float)LL, &s, &c);
        w[u] = tf32r((j < 32) ? c : -s);
    }
    *(uint4*)&g_A[(size_t)(icp * 2 + par) * HTW + j * TPW + oc * 4] =
        make_uint4(w[0], w[1], w[2], w[3]);
}

__global__ void build_basisF_pair() {
    int t = blockIdx.x * blockDim.x + threadIdx.x;   // 65536 tasks
    int oc  = t & 15;
    int lr  = (t >> 4) & 127;
    int par = (t >> 11) & 1;
    int lt  = t >> 12;          // 0..15
    int l = lt * 128 + lr;
    uint32_t w[4];
    #pragma unroll
    for (int u = 0; u < 4; u++) {
        int k = oc * 4 + u;
        int m = ((k < 32) ? 2 * k : 2 * (k - 32)) + par;
        int phi = (m * l) & (LL - 1);
        float s, c;
        sincospif(2.0f * (float)phi / (float)LL, &s, &c);
        float v;
        if (k < 32) v = ((m == 0) ? 1.0f : 2.0f) * (1.0f / (float)LL) * c;
        else        v = (-2.0f / (float)LL) * s;
        w[u] = tf32r(v);
    }
    *(uint4*)&g_F[(size_t)(lt * 2 + par) * TWORDS + lr * TPW + oc * 4] =
        make_uint4(w[0], w[1], w[2], w[3]);
}

// ---------------------------------------------------------------------------
// Weight transpose -> DENSE B-ready tf32 tiles (R14-proven)
// ---------------------------------------------------------------------------
#define SMEM_TW_BYTES (4 * 64 * 65 * 4)   // 66560
__global__ void __launch_bounds__(256) transpose_w_tiles(const float* __restrict__ w,
                                                         int which) {
    extern __shared__ float Sf[];
    int e0  = blockIdx.x * 4;
    int kc8 = blockIdx.y;
    int d0  = kc8 * 64;
    int tid = threadIdx.x;
    #pragma unroll
    for (int i = 0; i < 64; i++) {
        int idx = tid + i * 256;
        int m  = idx & 63;
        int dd = (idx >> 6) & 63;
        int er = idx >> 12;
        Sf[(er * 64 + dd) * 65 + m] = w[((size_t)(d0 + dd) * DD + e0 + er) * MODESN + m];
    }
    __syncthreads();
    int l16 = tid & 15, mslot = tid >> 4;
    #pragma unroll
    for (int mo = 0; mo < 4; mo++) {
        int m = mo * 16 + mslot;
        #pragma unroll
        for (int er = 0; er < 4; er++) {
            int e = e0 + er, eb = e >> 6, el = e & 63;
            uint32_t wv[4];
            #pragma unroll
            for (int u = 0; u < 4; u++) {
                int dd = l16 * 4 + u;
                wv[u] = tf32r(Sf[(er * 64 + dd) * 65 + m]);
            }
            uint32_t* dst = g_Wt
                + ((size_t)((which * 64 + m) * 64) + eb * 8 + kc8) * WTDW
                + (size_t)el * 64 + l16 * 4;
            *(uint4*)dst = make_uint4(wv[0], wv[1], wv[2], wv[3]);
        }
    }
}

// ---------------------------------------------------------------------------
// Stage A (radix-2 fused): per chunk-pair icp, load q rows l and l+2048 raw;
// butterfly happens in gemm_qs_pair's register path. X row = 2*je + par.
// grid (dt 4, b 32, ks 2), 256 thr, 2 CTAs/SM.
// SMEM: AE @0, AO @HT_BYTES, qL @34816, qH @34816+QS2_BYTES.
// ---------------------------------------------------------------------------
#define QS2_BYTES (64 * QS2 * 4)                       // 34816
#define SMEM_A_BYTES (2 * HT_BYTES + 2 * QS2_BYTES)    // 104448
__global__ void __launch_bounds__(256, 2) stageA_tf32(const float* __restrict__ q) {
    extern __shared__ __align__(16) unsigned char smem[];
    uint32_t sb = smem_u32(smem);
    int tid = threadIdx.x;
    int lane = tid & 31, warp = tid >> 5;
    int wm = warp & 3, wn = warp >> 2;
    int dt = blockIdx.x, b = blockIdx.y, ks = blockIdx.z;

    float acc_e[8][4], acc_o[8][4];
    #pragma unroll
    for (int nt = 0; nt < 8; nt++)
        #pragma unroll
        for (int i = 0; i < 4; i++) { acc_e[nt][i] = 0.0f; acc_o[nt][i] = 0.0f; }

    uint4* dA = (uint4*)smem;
    const uint32_t qLb = sb + 2 * HT_BYTES;
    const uint32_t qHb = qLb + QS2_BYTES;

    for (int icp0 = 0; icp0 < 16; icp0++) {
        int icp = ks * 16 + icp0;
        __syncthreads();   // prev gemm done: buffers free
        // issue q loads (rows l and l+2048)
        const float* qlo = q + ((size_t)b * LL + (size_t)icp * 64) * DD + dt * 128;
        const float* qhi = qlo + (size_t)2048 * DD;
        #pragma unroll
        for (int i = 0; i < 8; i++) {
            int idx = tid + i * 256;
            int r  = idx >> 5;
            int c4 = idx & 31;
            uint32_t so = (uint32_t)(r * QS2 + c4 * 4) * 4u;
            cp16(qLb + so, qlo + (size_t)r * DD + c4 * 4);
            cp16(qHb + so, qhi + (size_t)r * DD + c4 * 4);
        }
        CP_COMMIT();
        // copy basis pair (AE then AO, contiguous 2176 u4, L2-resident)
        const uint4* sA = (const uint4*)&g_A[(size_t)icp * 2 * HTW];
        #pragma unroll
        for (int i = 0; i < 9; i++) {
            int idx = tid + i * 256;
            if (idx < 2 * HT_U4) dA[idx] = sA[idx];
        }
        CP_WAIT0();
        __syncthreads();
        gemm_qs_pair(sb, sb + HT_BYTES, qLb, qHb, lane, wm, wn, acc_e, acc_o);
    }

    float* Xo = (ks == 0) ? g_X : g_X2;
    int tg = lane >> 2, tig = lane & 3;
    int je = wm * 16 + tg;
    #pragma unroll
    for (int nt = 0; nt < 8; nt++) {
        int dcol = dt * 128 + wn * 64 + nt * 8 + tig * 2;
        int re0 = 2 * je, re1 = 2 * (je + 8);
        *(float2*)&Xo[((size_t)b * JJ + re0) * DD + dcol] =
            make_float2(acc_e[nt][0], acc_e[nt][1]);
        *(float2*)&Xo[((size_t)b * JJ + re1) * DD + dcol] =
            make_float2(acc_e[nt][2], acc_e[nt][3]);
        *(float2*)&Xo[((size_t)b * JJ + re0 + 1) * DD + dcol] =
            make_float2(acc_o[nt][0], acc_o[nt][1]);
        *(float2*)&Xo[((size_t)b * JJ + re1 + 1) * DD + dcol] =
            make_float2(acc_o[nt][2], acc_o[nt][3]);
    }
}

// ---------------------------------------------------------------------------
// Stage B (R14-proven): tf32 mma, 2-phase, dense W tiles re-padded on copy.
// Epilogue writes parity-grouped Y^T: tile p = m&1, word = outI*32 + m/2.
// SMEM: Ar @0, Ai @8704, Br @17408, Bi @34816. Total 52224.
// ---------------------------------------------------------------------------
#define SB2_AI  8704
#define SB2_BR  17408
#define SB2_BI  34816
#define SMEM_B_BYTES 52224
__global__ void __launch_bounds__(128, 4) stageBt_tf32() {
    extern __shared__ __align__(16) unsigned char smem[];
    uint32_t sb = smem_u32(smem);
    uint32_t* AwR = (uint32_t*)smem;
    uint32_t* AwI = (uint32_t*)(smem + SB2_AI);
    uint4* dBr = (uint4*)(smem + SB2_BR);
    uint4* dBi = (uint4*)(smem + SB2_BI);
    int tid = threadIdx.x;
    int lane = tid & 31, warp = tid >> 5;
    int outI = warp >> 1;
    int nh   = warp & 1;
    int m  = blockIdx.y;
    int eb = blockIdx.x;

    float acc[2][4][4];
    #pragma unroll
    for (int mt = 0; mt < 2; mt++)
        #pragma unroll
        for (int nt = 0; nt < 4; nt++)
            #pragma unroll
            for (int i = 0; i < 4; i++) acc[mt][nt][i] = 0.0f;

    for (int kc8 = 0; kc8 < 8; kc8++) {
        int kd = kc8 * 64;
        const uint4* sBr = (const uint4*)&g_Wt[((size_t)m * 64 + eb * 8 + kc8) * WTDW];
        const uint4* sBi = (const uint4*)&g_Wt[((size_t)(64 + m) * 64 + eb * 8 + kc8) * WTDW];
        #pragma unroll
        for (int i = 0; i < 8; i++) {
            int idx = tid + i * 128;
            if (idx < 1024) {
                int row = idx >> 4, c4 = idx & 15;
                dBr[row * 17 + c4] = sBr[idx];
                dBi[row * 17 + c4] = sBi[idx];
            }
        }
        #pragma unroll
        for (int i = 0; i < 16; i++) {
            int idx = tid + i * 128;
            int bb = idx >> 6, c = idx & 63;
            size_t xr = ((size_t)bb * JJ + m) * DD + kd + c;
            size_t xi = ((size_t)bb * JJ + MODESN + m) * DD + kd + c;
            AwR[bb * TPW + c] = tf32r(g_X[xr] + g_X2[xr]);
            AwI[bb * TPW + c] = tf32r(g_X[xi] + g_X2[xi]);
        }
        __syncthreads();
        const uint32_t g  = (uint32_t)(lane >> 2);
        const uint32_t t4 = (uint32_t)(lane & 3);
        #pragma unroll
        for (int k8 = 0; k8 < 8; k8++) {
            uint32_t kw = (uint32_t)k8 * 8u + t4;
            uint32_t ar[2][4], ai[2][4];
            #pragma unroll
            for (int mt = 0; mt < 2; mt++) {
                uint32_t r0 = (uint32_t)(mt * 16) + g;
                ar[mt][0] = lds32(sb + (r0 * TPW + kw) * 4u);
                ar[mt][1] = lds32(sb + ((r0 + 8) * TPW + kw) * 4u);
                ar[mt][2] = lds32(sb + (r0 * TPW + kw + 4) * 4u);
                ar[mt][3] = lds32(sb + ((r0 + 8) * TPW + kw + 4) * 4u);
                ai[mt][0] = lds32(sb + SB2_AI + (r0 * TPW + kw) * 4u);
                ai[mt][1] = lds32(sb + SB2_AI + ((r0 + 8) * TPW + kw) * 4u);
                ai[mt][2] = lds32(sb + SB2_AI + (r0 * TPW + kw + 4) * 4u);
                ai[mt][3] = lds32(sb + SB2_AI + ((r0 + 8) * TPW + kw + 4) * 4u);
                if (outI == 0) {
                    #pragma unroll
                    for (int j = 0; j < 4; j++) ai[mt][j] ^= 0x80000000u;
                }
            }
            #pragma unroll
            for (int nt = 0; nt < 4; nt++) {
                uint32_t nr = (uint32_t)(nh * 32 + nt * 8) + g;
                uint32_t br0 = lds32(sb + SB2_BR + (nr * TPW + kw) * 4u);
                uint32_t br1 = lds32(sb + SB2_BR + (nr * TPW + kw + 4) * 4u);
                uint32_t bi0 = lds32(sb + SB2_BI + (nr * TPW + kw) * 4u);
                uint32_t bi1 = lds32(sb + SB2_BI + (nr * TPW + kw + 4) * 4u);
                if (outI == 0) {
                    mma_tf32(acc[0][nt], ar[0], br0, br1);
                    mma_tf32(acc[0][nt], ai[0], bi0, bi1);
                    mma_tf32(acc[1][nt], ar[1], br0, br1);
                    mma_tf32(acc[1][nt], ai[1], bi0, bi1);
                } else {
                    mma_tf32(acc[0][nt], ar[0], bi0, bi1);
                    mma_tf32(acc[0][nt], ai[0], br0, br1);
                    mma_tf32(acc[1][nt], ar[1], bi0, bi1);
                    mma_tf32(acc[1][nt], ai[1], br0, br1);
                }
            }
        }
        __syncthreads();
    }

    int tg = lane >> 2, tig = lane & 3;
    int p = m & 1;
    int word = outI * 32 + (m >> 1);
    #pragma unroll
    for (int mt = 0; mt < 2; mt++) {
        #pragma unroll
        for (int nt = 0; nt < 4; nt++) {
            int e0c = eb * 64 + nh * 32 + nt * 8 + tig * 2;
            int b0 = mt * 16 + tg;
            #pragma unroll
            for (int o = 0; o < 2; o++) {
                int e = e0c + o;
                int et = e >> 7, el = e & 127;
                size_t w0 = (((size_t)b0 * 4 + et) * 2 + p) * TWORDS
                          + (size_t)el * TPW + word;
                size_t w1 = (((size_t)(b0 + 8) * 4 + et) * 2 + p) * TWORDS
                          + (size_t)el * TPW + word;
                g_yt[w0] = tf32r(acc[mt][nt][o]);
                g_yt[w1] = tf32r(acc[mt][nt][2 + o]);
            }
        }
    }
}

// ---------------------------------------------------------------------------
// Stage C (radix-2, double-buffered): issue both parity tile sets via
// cp.async up front; gemm p=0 overlaps the p=1 loads. out[l] = E+O,
// out[l+2048] = E-O. grid (et 8, lt 16, b 32), 2 CTAs/SM.
// SMEM: buf[p] = F tile (34816) + Y half (17408); total 104448.
// ---------------------------------------------------------------------------
#define SMEM_C_HALF (TILE_BYTES + HT_BYTES)   // 52224
#define SMEM_C_BYTES (2 * SMEM_C_HALF)        // 104448
__global__ void __launch_bounds__(256, 2) stageC_tf32(float* __restrict__ out) {
    extern __shared__ __align__(16) unsigned char smem[];
    uint32_t sb = smem_u32(smem);
    int tid = threadIdx.x;
    int lane = tid & 31, warp = tid >> 5;
    int wm = warp & 3, wn = warp >> 2;
    int et = blockIdx.x, lt = blockIdx.y, b = blockIdx.z;

    float accE[2][4][4], accO[2][4][4];
    #pragma unroll
    for (int mt = 0; mt < 2; mt++)
        #pragma unroll
        for (int nt = 0; nt < 4; nt++)
            #pragma unroll
            for (int i = 0; i < 4; i++) { accE[mt][nt][i] = 0.0f; accO[mt][nt][i] = 0.0f; }

    auto issue = [&](int p) {
        const uint4* sF = (const uint4*)&g_F[(size_t)(lt * 2 + p) * TWORDS];
        const uint4* sY = (const uint4*)&g_yt[(((size_t)b * 4 + (et >> 1)) * 2 + p) * TWORDS
                                              + (size_t)(et & 1) * 64 * TPW];
        uint32_t fb = sb + (uint32_t)p * SMEM_C_HALF;
        uint32_t yb = fb + TILE_BYTES;
        #pragma unroll
        for (int i = 0; i < 9; i++) {
            int idx = tid + i * 256;
            if (idx < TILE_U4) cp16(fb + (uint32_t)idx * 16u, sF + idx);
        }
        #pragma unroll
        for (int i = 0; i < 5; i++) {
            int idx = tid + i * 256;
            if (idx < HT_U4) cp16(yb + (uint32_t)idx * 16u, sY + idx);
        }
        CP_COMMIT();
    };

    issue(0);
    issue(1);
    CP_WAIT1();
    __syncthreads();
    gemm_c(sb, sb + TILE_BYTES, lane, wm, wn, accE);
    CP_WAIT0();
    __syncthreads();
    gemm_c(sb + SMEM_C_HALF, sb + SMEM_C_HALF + TILE_BYTES, lane, wm, wn, accO);

    int tg = lane >> 2, tig = lane & 3;
    #pragma unroll
    for (int mt = 0; mt < 2; mt++) {
        int r = lt * 128 + wm * 32 + mt * 16 + tg;
        #pragma unroll
        for (int nt = 0; nt < 4; nt++) {
            int col = et * 64 + wn * 32 + nt * 8 + tig * 2;
            float e0 = accE[mt][nt][0], e1 = accE[mt][nt][1];
            float e2 = accE[mt][nt][2], e3 = accE[mt][nt][3];
            float o0 = accO[mt][nt][0], o1 = accO[mt][nt][1];
            float o2 = accO[mt][nt][2], o3 = accO[mt][nt][3];
            *(float2*)&out[((size_t)b * LL + r) * DD + col]          = make_float2(e0 + o0, e1 + o1);
            *(float2*)&out[((size_t)b * LL + r + 8) * DD + col]      = make_float2(e2 + o2, e3 + o3);
            *(float2*)&out[((size_t)b * LL + r + 2048) * DD + col]   = make_float2(e0 - o0, e1 - o1);
            *(float2*)&out[((size_t)b * LL + r + 2056) * DD + col]   = make_float2(e2 - o2, e3 - o3);
        }
    }
}

// ---------------------------------------------------------------------------
// launch
// ---------------------------------------------------------------------------
extern "C" void kernel_launch(void* const* d_in, const int* in_sizes, int n_in,
                              void* d_out, int out_size) {
    const float* q  = (const float*)d_in[0];
    const float* wr = (const float*)d_in[1];
    const float* wi = (const float*)d_in[2];
    float* out = (float*)d_out;

    // Idempotent, every invocation (no static guards — harness rule)
    cudaFuncSetAttribute(stageA_tf32, cudaFuncAttributeMaxDynamicSharedMemorySize, SMEM_A_BYTES);
    cudaFuncSetAttribute(stageBt_tf32, cudaFuncAttributeMaxDynamicSharedMemorySize, SMEM_B_BYTES);
    cudaFuncSetAttribute(stageC_tf32, cudaFuncAttributeMaxDynamicSharedMemorySize, SMEM_C_BYTES);
    cudaFuncSetAttribute(transpose_w_tiles, cudaFuncAttributeMaxDynamicSharedMemorySize, SMEM_TW_BYTES);

    build_basisA_pair<<<256, 256>>>();
    build_basisF_pair<<<256, 256>>>();

    transpose_w_tiles<<<dim3(128, 8), 256, SMEM_TW_BYTES>>>(wr, 0);
    transpose_w_tiles<<<dim3(128, 8), 256, SMEM_TW_BYTES>>>(wi, 1);

    stageA_tf32<<<dim3(4, NB, 2), 256, SMEM_A_BYTES>>>(q);
    stageBt_tf32<<<dim3(8, MODESN), 128, SMEM_B_BYTES>>>();
    stageC_tf32<<<dim3(8, 16, NB), 256, SMEM_C_BYTES>>>(out);
}

// round 17
// speedup vs baseline: 3.7479x; 1.0295x over previous
#include <cuda_runtime.h>
#include <cuda_bf16.h>
#include <cstdint>

// Problem constants
#define LL     4096
#define DD     512
#define MODESN 64
#define JJ     128   // 2*MODES (Re rows then Im rows)
#define NB     32    // batch

// tf32 tile geometry: [row][word 64 data + 4 pad] fp32 words
#define TPW     68
#define TWORDS  (128 * TPW)        // 8704 words / 34816 B per 128-row tile
#define TILE_BYTES (TWORDS * 4)
#define TILE_U4 (TWORDS / 4)       // 2176
#define HTW     (64 * TPW)         // 4352 words per 64-row tile
#define HT_BYTES (HTW * 4)         // 17408
#define HT_U4   (HTW / 4)          // 1088
#define WTDW    (64 * 64)          // dense W tile words (256B rows)

// ---------------------------------------------------------------------------
// Static device scratch (no allocation allowed)
// ---------------------------------------------------------------------------
// Stage A parity basis: [icp 32][par 2] of [j 64][k 64(+4)]
__device__ __align__(16) uint32_t g_A[64 * HTW];
// Stage C parity basis: [lt 16][par 2] of [l 128][k 64(+4)]
__device__ __align__(16) uint32_t g_F[32 * TWORDS];
// Y^T tiles: [b 32][et 4][p 2] of [e 128][word 64(+4)]; word = outI*32 + m/2
__device__ __align__(16) uint32_t g_yt[256 * TWORDS];
// W^T tf32 tiles DENSE: [ri 2][m 64][eb 8][kc8 8] of [e 64][d 64] (128 MB)
__device__ __align__(16) uint32_t g_Wt[(size_t)2 * 64 * 64 * WTDW];
// Stage A partial outputs fp32 [b][j][d] (K-split halves) + presum
__device__ float g_X [NB * JJ * DD];
__device__ float g_X2[NB * JJ * DD];
__device__ __align__(16) float g_Xs[NB * JJ * DD];

// ---------------------------------------------------------------------------
// Helpers
// ---------------------------------------------------------------------------
__device__ __forceinline__ uint32_t smem_u32(const void* p) {
    uint32_t a;
    asm("{ .reg .u64 t; cvta.to.shared.u64 t, %1; cvt.u32.u64 %0, t; }"
        : "=r"(a) : "l"(p));
    return a;
}

__device__ __forceinline__ uint32_t lds32(uint32_t a) {
    uint32_t v;
    asm volatile("ld.shared.b32 %0, [%1];" : "=r"(v) : "r"(a));
    return v;
}

__device__ __forceinline__ uint32_t tf32r(float v) {
    uint32_t r;
    asm("cvt.rna.tf32.f32 %0, %1;" : "=r"(r) : "f"(v));
    return r;
}

__device__ __forceinline__ void cp16(uint32_t saddr, const void* g) {
    asm volatile("cp.async.cg.shared.global [%0], [%1], 16;" :: "r"(saddr), "l"(g));
}
#define CP_COMMIT() asm volatile("cp.async.commit_group;" ::: "memory")
#define CP_WAIT0()  asm volatile("cp.async.wait_group 0;" ::: "memory")
#define CP_WAIT1()  asm volatile("cp.async.wait_group 1;" ::: "memory")

__device__ __forceinline__ void mma_tf32(float* c, const uint32_t* a,
                                         uint32_t b0, uint32_t b1) {
    asm volatile(
        "mma.sync.aligned.m16n8k8.row.col.f32.tf32.tf32.f32 "
        "{%0,%1,%2,%3}, {%4,%5,%6,%7}, {%8,%9}, {%0,%1,%2,%3};"
        : "+f"(c[0]), "+f"(c[1]), "+f"(c[2]), "+f"(c[3])
        : "r"(a[0]), "r"(a[1]), "r"(a[2]), "r"(a[3]), "r"(b0), "r"(b1));
}

// ---------------------------------------------------------------------------
// Stage A fused butterfly gemm (R15-PROVEN)
// ---------------------------------------------------------------------------
#define QS2 136
__device__ __forceinline__ void gemm_qs_pair(uint32_t baseAE, uint32_t baseAO,
                                             uint32_t qLb, uint32_t qHb,
                                             int lane, int wm, int wn,
                                             float acc_e[8][4], float acc_o[8][4]) {
    const uint32_t g  = (uint32_t)(lane >> 2);
    const uint32_t t4 = (uint32_t)(lane & 3);
    #pragma unroll
    for (int k8 = 0; k8 < 8; k8++) {
        const uint32_t kw = (uint32_t)k8 * 8u + t4;
        uint32_t aE[4], aO[4];
        uint32_t r0 = (uint32_t)(wm * 16) + g;
        aE[0] = lds32(baseAE + (r0 * TPW + kw) * 4u);
        aE[1] = lds32(baseAE + ((r0 + 8) * TPW + kw) * 4u);
        aE[2] = lds32(baseAE + (r0 * TPW + kw + 4) * 4u);
        aE[3] = lds32(baseAE + ((r0 + 8) * TPW + kw + 4) * 4u);
        aO[0] = lds32(baseAO + (r0 * TPW + kw) * 4u);
        aO[1] = lds32(baseAO + ((r0 + 8) * TPW + kw) * 4u);
        aO[2] = lds32(baseAO + (r0 * TPW + kw + 4) * 4u);
        aO[3] = lds32(baseAO + ((r0 + 8) * TPW + kw + 4) * 4u);
        #pragma unroll
        for (int nt = 0; nt < 8; nt++) {
            uint32_t nr = (uint32_t)(wn * 64 + nt * 8) + g;
            float lo0 = __uint_as_float(lds32(qLb + (kw * QS2 + nr) * 4u));
            float lo1 = __uint_as_float(lds32(qLb + ((kw + 4) * QS2 + nr) * 4u));
            float hi0 = __uint_as_float(lds32(qHb + (kw * QS2 + nr) * 4u));
            float hi1 = __uint_as_float(lds32(qHb + ((kw + 4) * QS2 + nr) * 4u));
            mma_tf32(acc_e[nt], aE, tf32r(lo0 + hi0), tf32r(lo1 + hi1));
            mma_tf32(acc_o[nt], aO, tf32r(lo0 - hi0), tf32r(lo1 - hi1));
        }
    }
}

// ---------------------------------------------------------------------------
// Stage C gemm (R14-proven)
// ---------------------------------------------------------------------------
__device__ __forceinline__ void gemm_c(uint32_t baseA, uint32_t baseB,
                                       int lane, int wm, int wn,
                                       float acc[2][4][4]) {
    const uint32_t g  = (uint32_t)(lane >> 2);
    const uint32_t t4 = (uint32_t)(lane & 3);
    #pragma unroll
    for (int k8 = 0; k8 < 8; k8++) {
        const uint32_t kw = (uint32_t)k8 * 8u + t4;
        uint32_t a[2][4];
        #pragma unroll
        for (int mt = 0; mt < 2; mt++) {
            uint32_t r0 = (uint32_t)(wm * 32 + mt * 16) + g;
            a[mt][0] = lds32(baseA + (r0 * TPW + kw) * 4u);
            a[mt][1] = lds32(baseA + ((r0 + 8) * TPW + kw) * 4u);
            a[mt][2] = lds32(baseA + (r0 * TPW + kw + 4) * 4u);
            a[mt][3] = lds32(baseA + ((r0 + 8) * TPW + kw + 4) * 4u);
        }
        #pragma unroll
        for (int nt = 0; nt < 4; nt++) {
            uint32_t nr = (uint32_t)(wn * 32 + nt * 8) + g;
            uint32_t b0 = lds32(baseB + (nr * TPW + kw) * 4u);
            uint32_t b1 = lds32(baseB + (nr * TPW + kw + 4) * 4u);
            mma_tf32(acc[0][nt], a[0], b0, b1);
            mma_tf32(acc[1][nt], a[1], b0, b1);
        }
    }
}

// ---------------------------------------------------------------------------
// Basis builders (R14-proven)
// ---------------------------------------------------------------------------
__global__ void build_basisA_pair() {
    int t = blockIdx.x * blockDim.x + threadIdx.x;
    int oc  = t & 15;
    int j   = (t >> 4) & 63;
    int par = (t >> 10) & 1;
    int icp = t >> 11;
    uint32_t w[4];
    #pragma unroll
    for (int u = 0; u < 4; u++) {
        int kk = oc * 4 + u;
        int l = icp * 64 + kk;
        int m = ((j < 32) ? 2 * j : 2 * (j - 32)) + par;
        int phi = (m * l) & (LL - 1);
        float s, c;
        sincospif(2.0f * (float)phi / (float)LL, &s, &c);
        w[u] = tf32r((j < 32) ? c : -s);
    }
    *(uint4*)&g_A[(size_t)(icp * 2 + par) * HTW + j * TPW + oc * 4] =
        make_uint4(w[0], w[1], w[2], w[3]);
}

__global__ void build_basisF_pair() {
    int t = blockIdx.x * blockDim.x + threadIdx.x;
    int oc  = t & 15;
    int lr  = (t >> 4) & 127;
    int par = (t >> 11) & 1;
    int lt  = t >> 12;
    int l = lt * 128 + lr;
    uint32_t w[4];
    #pragma unroll
    for (int u = 0; u < 4; u++) {
        int k = oc * 4 + u;
        int m = ((k < 32) ? 2 * k : 2 * (k - 32)) + par;
        int phi = (m * l) & (LL - 1);
        float s, c;
        sincospif(2.0f * (float)phi / (float)LL, &s, &c);
        float v;
        if (k < 32) v = ((m == 0) ? 1.0f : 2.0f) * (1.0f / (float)LL) * c;
        else        v = (-2.0f / (float)LL) * s;
        w[u] = tf32r(v);
    }
    *(uint4*)&g_F[(size_t)(lt * 2 + par) * TWORDS + lr * TPW + oc * 4] =
        make_uint4(w[0], w[1], w[2], w[3]);
}

// ---------------------------------------------------------------------------
// Weight transpose -> DENSE tiles; wr and wi merged via blockIdx.z
// ---------------------------------------------------------------------------
#define SMEM_TW_BYTES (4 * 64 * 65 * 4)   // 66560
__global__ void __launch_bounds__(256) transpose_w_tiles(const float* __restrict__ w0,
                                                         const float* __restrict__ w1) {
    extern __shared__ float Sf[];
    int which = blockIdx.z;
    const float* __restrict__ w = which ? w1 : w0;
    int e0  = blockIdx.x * 4;
    int kc8 = blockIdx.y;
    int d0  = kc8 * 64;
    int tid = threadIdx.x;
    #pragma unroll
    for (int i = 0; i < 64; i++) {
        int idx = tid + i * 256;
        int m  = idx & 63;
        int dd = (idx >> 6) & 63;
        int er = idx >> 12;
        Sf[(er * 64 + dd) * 65 + m] = w[((size_t)(d0 + dd) * DD + e0 + er) * MODESN + m];
    }
    __syncthreads();
    int l16 = tid & 15, mslot = tid >> 4;
    #pragma unroll
    for (int mo = 0; mo < 4; mo++) {
        int m = mo * 16 + mslot;
        #pragma unroll
        for (int er = 0; er < 4; er++) {
            int e = e0 + er, eb = e >> 6, el = e & 63;
            uint32_t wv[4];
            #pragma unroll
            for (int u = 0; u < 4; u++) {
                int dd = l16 * 4 + u;
                wv[u] = tf32r(Sf[(er * 64 + dd) * 65 + m]);
            }
            uint32_t* dst = g_Wt
                + ((size_t)((which * 64 + m) * 64) + eb * 8 + kc8) * WTDW
                + (size_t)el * 64 + l16 * 4;
            *(uint4*)dst = make_uint4(wv[0], wv[1], wv[2], wv[3]);
        }
    }
}

// ---------------------------------------------------------------------------
// X presum: g_Xs = g_X + g_X2 (fp32, same add as before — bit-identical)
// ---------------------------------------------------------------------------
__global__ void presum_X() {
    size_t i = ((size_t)blockIdx.x * 256 + threadIdx.x) * 4;
    float4 a = *(const float4*)&g_X[i];
    float4 b = *(const float4*)&g_X2[i];
    *(float4*)&g_Xs[i] = make_float4(a.x + b.x, a.y + b.y, a.z + b.z, a.w + b.w);
}

// ---------------------------------------------------------------------------
// Stage A (R15-PROVEN, unchanged)
// ---------------------------------------------------------------------------
#define QS2_BYTES (64 * QS2 * 4)                       // 34816
#define SMEM_A_BYTES (2 * HT_BYTES + 2 * QS2_BYTES)    // 104448
__global__ void __launch_bounds__(256, 2) stageA_tf32(const float* __restrict__ q) {
    extern __shared__ __align__(16) unsigned char smem[];
    uint32_t sb = smem_u32(smem);
    int tid = threadIdx.x;
    int lane = tid & 31, warp = tid >> 5;
    int wm = warp & 3, wn = warp >> 2;
    int dt = blockIdx.x, b = blockIdx.y, ks = blockIdx.z;

    float acc_e[8][4], acc_o[8][4];
    #pragma unroll
    for (int nt = 0; nt < 8; nt++)
        #pragma unroll
        for (int i = 0; i < 4; i++) { acc_e[nt][i] = 0.0f; acc_o[nt][i] = 0.0f; }

    uint4* dA = (uint4*)smem;
    const uint32_t qLb = sb + 2 * HT_BYTES;
    const uint32_t qHb = qLb + QS2_BYTES;

    for (int icp0 = 0; icp0 < 16; icp0++) {
        int icp = ks * 16 + icp0;
        __syncthreads();
        const float* qlo = q + ((size_t)b * LL + (size_t)icp * 64) * DD + dt * 128;
        const float* qhi = qlo + (size_t)2048 * DD;
        #pragma unroll
        for (int i = 0; i < 8; i++) {
            int idx = tid + i * 256;
            int r  = idx >> 5;
            int c4 = idx & 31;
            uint32_t so = (uint32_t)(r * QS2 + c4 * 4) * 4u;
            cp16(qLb + so, qlo + (size_t)r * DD + c4 * 4);
            cp16(qHb + so, qhi + (size_t)r * DD + c4 * 4);
        }
        CP_COMMIT();
        const uint4* sA = (const uint4*)&g_A[(size_t)icp * 2 * HTW];
        #pragma unroll
        for (int i = 0; i < 9; i++) {
            int idx = tid + i * 256;
            if (idx < 2 * HT_U4) dA[idx] = sA[idx];
        }
        CP_WAIT0();
        __syncthreads();
        gemm_qs_pair(sb, sb + HT_BYTES, qLb, qHb, lane, wm, wn, acc_e, acc_o);
    }

    float* Xo = (ks == 0) ? g_X : g_X2;
    int tg = lane >> 2, tig = lane & 3;
    int je = wm * 16 + tg;
    #pragma unroll
    for (int nt = 0; nt < 8; nt++) {
        int dcol = dt * 128 + wn * 64 + nt * 8 + tig * 2;
        int re0 = 2 * je, re1 = 2 * (je + 8);
        *(float2*)&Xo[((size_t)b * JJ + re0) * DD + dcol] =
            make_float2(acc_e[nt][0], acc_e[nt][1]);
        *(float2*)&Xo[((size_t)b * JJ + re1) * DD + dcol] =
            make_float2(acc_e[nt][2], acc_e[nt][3]);
        *(float2*)&Xo[((size_t)b * JJ + re0 + 1) * DD + dcol] =
            make_float2(acc_o[nt][0], acc_o[nt][1]);
        *(float2*)&Xo[((size_t)b * JJ + re1 + 1) * DD + dcol] =
            make_float2(acc_o[nt][2], acc_o[nt][3]);
    }
}

// ---------------------------------------------------------------------------
// Stage B (cp.async double-buffered): per mode m, e-block 64.
// W tiles (tf32) and X tiles (raw fp32, cvt in fragment path) stream via
// cp.async with PADDED destinations ((row*17+c4) u4 -> stride-68 rows).
// Stage layout: Ar @0 (8704), Ai @8704, Br @17408, Bi @34816; stage 52224.
// ---------------------------------------------------------------------------
#define SBS_AI   8704
#define SBS_BR   17408
#define SBS_BI   34816
#define SB_STAGE 52224
#define SMEM_B_BYTES (2 * SB_STAGE)   // 104448
__global__ void __launch_bounds__(128, 2) stageBt_tf32() {
    extern __shared__ __align__(16) unsigned char smem[];
    uint32_t sb = smem_u32(smem);
    int tid = threadIdx.x;
    int lane = tid & 31, warp = tid >> 5;
    int outI = warp >> 1;
    int nh   = warp & 1;
    int m  = blockIdx.y;
    int eb = blockIdx.x;

    float acc[2][4][4];
    #pragma unroll
    for (int mt = 0; mt < 2; mt++)
        #pragma unroll
        for (int nt = 0; nt < 4; nt++)
            #pragma unroll
            for (int i = 0; i < 4; i++) acc[mt][nt][i] = 0.0f;

    auto issue = [&](int kc8, int s) {
        uint32_t base = sb + (uint32_t)s * SB_STAGE;
        const uint4* sBr = (const uint4*)&g_Wt[((size_t)m * 64 + eb * 8 + kc8) * WTDW];
        const uint4* sBi = (const uint4*)&g_Wt[((size_t)(64 + m) * 64 + eb * 8 + kc8) * WTDW];
        int kd = kc8 * 64;
        #pragma unroll
        for (int i = 0; i < 8; i++) {            // W tiles: 1024 u4 each
            int idx = tid + i * 128;
            int row = idx >> 4, c4 = idx & 15;
            uint32_t doff = (uint32_t)(row * 17 + c4) * 16u;
            cp16(base + SBS_BR + doff, sBr + idx);
            cp16(base + SBS_BI + doff, sBi + idx);
        }
        #pragma unroll
        for (int i = 0; i < 4; i++) {            // X tiles: 512 u4 each
            int idx = tid + i * 128;
            int bb = idx >> 4, c4 = idx & 15;
            uint32_t doff = (uint32_t)(bb * 17 + c4) * 16u;
            const float* xr = &g_Xs[((size_t)bb * JJ + m) * DD + kd + c4 * 4];
            const float* xi = &g_Xs[((size_t)bb * JJ + MODESN + m) * DD + kd + c4 * 4];
            cp16(base + doff, xr);
            cp16(base + SBS_AI + doff, xi);
        }
        CP_COMMIT();
    };

    issue(0, 0);

    for (int kc8 = 0; kc8 < 8; kc8++) {
        int p = kc8 & 1;
        if (kc8 < 7) { issue(kc8 + 1, p ^ 1); CP_WAIT1(); }
        else         { CP_WAIT0(); }
        __syncthreads();   // stage p visible to all
        uint32_t base = sb + (uint32_t)p * SB_STAGE;
        const uint32_t g  = (uint32_t)(lane >> 2);
        const uint32_t t4 = (uint32_t)(lane & 3);
        #pragma unroll
        for (int k8 = 0; k8 < 8; k8++) {
            uint32_t kw = (uint32_t)k8 * 8u + t4;
            uint32_t ar[2][4], ai[2][4];
            #pragma unroll
            for (int mt = 0; mt < 2; mt++) {
                uint32_t r0 = (uint32_t)(mt * 16) + g;
                ar[mt][0] = tf32r(__uint_as_float(lds32(base + (r0 * TPW + kw) * 4u)));
                ar[mt][1] = tf32r(__uint_as_float(lds32(base + ((r0 + 8) * TPW + kw) * 4u)));
                ar[mt][2] = tf32r(__uint_as_float(lds32(base + (r0 * TPW + kw + 4) * 4u)));
                ar[mt][3] = tf32r(__uint_as_float(lds32(base + ((r0 + 8) * TPW + kw + 4) * 4u)));
                ai[mt][0] = tf32r(__uint_as_float(lds32(base + SBS_AI + (r0 * TPW + kw) * 4u)));
                ai[mt][1] = tf32r(__uint_as_float(lds32(base + SBS_AI + ((r0 + 8) * TPW + kw) * 4u)));
                ai[mt][2] = tf32r(__uint_as_float(lds32(base + SBS_AI + (r0 * TPW + kw + 4) * 4u)));
                ai[mt][3] = tf32r(__uint_as_float(lds32(base + SBS_AI + ((r0 + 8) * TPW + kw + 4) * 4u)));
                if (outI == 0) {   // Yr needs -Xi.Wi (sign XOR commutes with tf32r)
                    #pragma unroll
                    for (int j = 0; j < 4; j++) ai[mt][j] ^= 0x80000000u;
                }
            }
            #pragma unroll
            for (int nt = 0; nt < 4; nt++) {
                uint32_t nr = (uint32_t)(nh * 32 + nt * 8) + g;
                uint32_t br0 = lds32(base + SBS_BR + (nr * TPW + kw) * 4u);
                uint32_t br1 = lds32(base + SBS_BR + (nr * TPW + kw + 4) * 4u);
                uint32_t bi0 = lds32(base + SBS_BI + (nr * TPW + kw) * 4u);
                uint32_t bi1 = lds32(base + SBS_BI + (nr * TPW + kw + 4) * 4u);
                if (outI == 0) {
                    mma_tf32(acc[0][nt], ar[0], br0, br1);
                    mma_tf32(acc[0][nt], ai[0], bi0, bi1);
                    mma_tf32(acc[1][nt], ar[1], br0, br1);
                    mma_tf32(acc[1][nt], ai[1], bi0, bi1);
                } else {
                    mma_tf32(acc[0][nt], ar[0], bi0, bi1);
                    mma_tf32(acc[0][nt], ai[0], br0, br1);
                    mma_tf32(acc[1][nt], ar[1], bi0, bi1);
                    mma_tf32(acc[1][nt], ai[1], br0, br1);
                }
            }
        }
        __syncthreads();   // done reading stage p (refilled next iteration)
    }

    int tg = lane >> 2, tig = lane & 3;
    int p = m & 1;
    int word = outI * 32 + (m >> 1);
    #pragma unroll
    for (int mt = 0; mt < 2; mt++) {
        #pragma unroll
        for (int nt = 0; nt < 4; nt++) {
            int e0c = eb * 64 + nh * 32 + nt * 8 + tig * 2;
            int b0 = mt * 16 + tg;
            #pragma unroll
            for (int o = 0; o < 2; o++) {
                int e = e0c + o;
                int et = e >> 7, el = e & 127;
                size_t w0 = (((size_t)b0 * 4 + et) * 2 + p) * TWORDS
                          + (size_t)el * TPW + word;
                size_t w1 = (((size_t)(b0 + 8) * 4 + et) * 2 + p) * TWORDS
                          + (size_t)el * TPW + word;
                g_yt[w0] = tf32r(acc[mt][nt][o]);
                g_yt[w1] = tf32r(acc[mt][nt][2 + o]);
            }
        }
    }
}

// ---------------------------------------------------------------------------
// Stage C (R15-PROVEN, unchanged): radix-2 double-buffered cp.async
// ---------------------------------------------------------------------------
#define SMEM_C_HALF (TILE_BYTES + HT_BYTES)   // 52224
#define SMEM_C_BYTES (2 * SMEM_C_HALF)        // 104448
__global__ void __launch_bounds__(256, 2) stageC_tf32(float* __restrict__ out) {
    extern __shared__ __align__(16) unsigned char smem[];
    uint32_t sb = smem_u32(smem);
    int tid = threadIdx.x;
    int lane = tid & 31, warp = tid >> 5;
    int wm = warp & 3, wn = warp >> 2;
    int et = blockIdx.x, lt = blockIdx.y, b = blockIdx.z;

    float accE[2][4][4], accO[2][4][4];
    #pragma unroll
    for (int mt = 0; mt < 2; mt++)
        #pragma unroll
        for (int nt = 0; nt < 4; nt++)
            #pragma unroll
            for (int i = 0; i < 4; i++) { accE[mt][nt][i] = 0.0f; accO[mt][nt][i] = 0.0f; }

    auto issue = [&](int p) {
        const uint4* sF = (const uint4*)&g_F[(size_t)(lt * 2 + p) * TWORDS];
        const uint4* sY = (const uint4*)&g_yt[(((size_t)b * 4 + (et >> 1)) * 2 + p) * TWORDS
                                              + (size_t)(et & 1) * 64 * TPW];
        uint32_t fb = sb + (uint32_t)p * SMEM_C_HALF;
        uint32_t yb = fb + TILE_BYTES;
        #pragma unroll
        for (int i = 0; i < 9; i++) {
            int idx = tid + i * 256;
            if (idx < TILE_U4) cp16(fb + (uint32_t)idx * 16u, sF + idx);
        }
        #pragma unroll
        for (int i = 0; i < 5; i++) {
            int idx = tid + i * 256;
            if (idx < HT_U4) cp16(yb + (uint32_t)idx * 16u, sY + idx);
        }
        CP_COMMIT();
    };

    issue(0);
    issue(1);
    CP_WAIT1();
    __syncthreads();
    gemm_c(sb, sb + TILE_BYTES, lane, wm, wn, accE);
    CP_WAIT0();
    __syncthreads();
    gemm_c(sb + SMEM_C_HALF, sb + SMEM_C_HALF + TILE_BYTES, lane, wm, wn, accO);

    int tg = lane >> 2, tig = lane & 3;
    #pragma unroll
    for (int mt = 0; mt < 2; mt++) {
        int r = lt * 128 + wm * 32 + mt * 16 + tg;
        #pragma unroll
        for (int nt = 0; nt < 4; nt++) {
            int col = et * 64 + wn * 32 + nt * 8 + tig * 2;
            float e0 = accE[mt][nt][0], e1 = accE[mt][nt][1];
            float e2 = accE[mt][nt][2], e3 = accE[mt][nt][3];
            float o0 = accO[mt][nt][0], o1 = accO[mt][nt][1];
            float o2 = accO[mt][nt][2], o3 = accO[mt][nt][3];
            *(float2*)&out[((size_t)b * LL + r) * DD + col]          = make_float2(e0 + o0, e1 + o1);
            *(float2*)&out[((size_t)b * LL + r + 8) * DD + col]      = make_float2(e2 + o2, e3 + o3);
            *(float2*)&out[((size_t)b * LL + r + 2048) * DD + col]   = make_float2(e0 - o0, e1 - o1);
            *(float2*)&out[((size_t)b * LL + r + 2056) * DD + col]   = make_float2(e2 - o2, e3 - o3);
        }
    }
}

// ---------------------------------------------------------------------------
// launch
// ---------------------------------------------------------------------------
extern "C" void kernel_launch(void* const* d_in, const int* in_sizes, int n_in,
                              void* d_out, int out_size) {
    const float* q  = (const float*)d_in[0];
    const float* wr = (const float*)d_in[1];
    const float* wi = (const float*)d_in[2];
    float* out = (float*)d_out;

    // Idempotent, every invocation (no static guards — harness rule)
    cudaFuncSetAttribute(stageA_tf32, cudaFuncAttributeMaxDynamicSharedMemorySize, SMEM_A_BYTES);
    cudaFuncSetAttribute(stageBt_tf32, cudaFuncAttributeMaxDynamicSharedMemorySize, SMEM_B_BYTES);
    cudaFuncSetAttribute(stageC_tf32, cudaFuncAttributeMaxDynamicSharedMemorySize, SMEM_C_BYTES);
    cudaFuncSetAttribute(transpose_w_tiles, cudaFuncAttributeMaxDynamicSharedMemorySize, SMEM_TW_BYTES);

    build_basisA_pair<<<256, 256>>>();
    build_basisF_pair<<<256, 256>>>();

    transpose_w_tiles<<<dim3(128, 8, 2), 256, SMEM_TW_BYTES>>>(wr, wi);

    stageA_tf32<<<dim3(4, NB, 2), 256, SMEM_A_BYTES>>>(q);
    presum_X<<<2048, 256>>>();
    stageBt_tf32<<<dim3(8, MODESN), 128, SMEM_B_BYTES>>>();
    stageC_tf32<<<dim3(8, 16, NB), 256, SMEM_C_BYTES>>>(out);
}